// round 1
// baseline (speedup 1.0000x reference)
#include <cuda_runtime.h>
#include <math.h>

// Problem constants (fixed shapes from reference)
#define NLAYER 6
#define NHEAD  16
#define DMODEL 1024
#define DHEAD  64
#define DFF    4096
#define BATCH  4
#define SEQ    1024
#define MROWS  (BATCH*SEQ)
#define NEG_INF_F (-100000000.0f)

// ---------------------------------------------------------------------------
// Scratch (static device globals; no allocation anywhere)
// ---------------------------------------------------------------------------
__device__ float g_x[MROWS*DMODEL];   // running activation
__device__ float g_q[MROWS*DMODEL];
__device__ float g_k[MROWS*DMODEL];
__device__ float g_v[MROWS*DMODEL];
__device__ float g_o[MROWS*DMODEL];   // attention output (pre-Wo)
__device__ float g_y[MROWS*DMODEL];   // projection / ffn output
__device__ float g_h[MROWS*DFF];      // ffn hidden

// ---------------------------------------------------------------------------
// Positional encoding: x += [sin(s*inv_t) | cos(s*inv_t)], computed in fp64
// for accuracy. One thread per (s,d); writes all 4 batch copies.
// ---------------------------------------------------------------------------
__global__ void posenc_kernel(const float* __restrict__ x, float* __restrict__ out)
{
    int idx = blockIdx.x * blockDim.x + threadIdx.x;
    if (idx >= SEQ * DMODEL) return;
    int d = idx & (DMODEL - 1);
    int s = idx >> 10;
    int t = (d < DMODEL/2) ? d : d - DMODEL/2;
    const double log_inc = log(10000.0) / (double)(DMODEL/2 - 1);
    double arg = (double)s * exp(-(double)t * log_inc);
    float sig = (float)((d < DMODEL/2) ? sin(arg) : cos(arg));
#pragma unroll
    for (int b = 0; b < BATCH; ++b) {
        size_t off = (size_t)b * SEQ * DMODEL + idx;
        out[off] = x[off] + sig;
    }
}

// ---------------------------------------------------------------------------
// SGEMM: C[M,N] = act( (A[M,K] @ W[K,N] + bias[N]) * alpha )
// 128x128 tile, BK=8, 256 threads, 8x8 per thread.
// All dims are multiples of 128 here (M=4096, N in {1024,4096}, K in {1024,4096}).
// ---------------------------------------------------------------------------
__global__ __launch_bounds__(256) void sgemm_kernel(
    const float* __restrict__ A, const float* __restrict__ W,
    const float* __restrict__ bias, float* __restrict__ C,
    int Mdim, int Ndim, int Kdim, float alpha, int relu)
{
    __shared__ float As[8][128];   // As[k][m]  (transposed A tile)
    __shared__ float Bs[8][128];   // Bs[k][n]

    const int tid = threadIdx.x;
    const int m0 = blockIdx.y * 128;
    const int n0 = blockIdx.x * 128;

    const int arow = tid >> 1;            // 0..127
    const int acol = (tid & 1) << 2;      // 0 or 4
    const int brow = tid >> 5;            // 0..7
    const int bcol = (tid & 31) << 2;     // 0..124

    const int ty = tid >> 4;              // 0..15 -> rows ty*8
    const int tx = tid & 15;              // 0..15 -> cols tx*8

    float acc[8][8];
#pragma unroll
    for (int i = 0; i < 8; ++i)
#pragma unroll
        for (int j = 0; j < 8; ++j) acc[i][j] = 0.0f;

    const float* Ap = A + (size_t)(m0 + arow) * Kdim + acol;
    const float* Bp = W + (size_t)brow * Ndim + n0 + bcol;

    for (int k0 = 0; k0 < Kdim; k0 += 8) {
        float4 av = *(const float4*)(Ap + k0);
        float4 bv = *(const float4*)(Bp + (size_t)k0 * Ndim);
        As[acol + 0][arow] = av.x;
        As[acol + 1][arow] = av.y;
        As[acol + 2][arow] = av.z;
        As[acol + 3][arow] = av.w;
        *(float4*)&Bs[brow][bcol] = bv;
        __syncthreads();

#pragma unroll
        for (int k = 0; k < 8; ++k) {
            float4 a0 = *(const float4*)&As[k][ty * 8];
            float4 a1 = *(const float4*)&As[k][ty * 8 + 4];
            float4 b0 = *(const float4*)&Bs[k][tx * 8];
            float4 b1 = *(const float4*)&Bs[k][tx * 8 + 4];
            float a[8] = {a0.x, a0.y, a0.z, a0.w, a1.x, a1.y, a1.z, a1.w};
            float b[8] = {b0.x, b0.y, b0.z, b0.w, b1.x, b1.y, b1.z, b1.w};
#pragma unroll
            for (int i = 0; i < 8; ++i)
#pragma unroll
                for (int j = 0; j < 8; ++j)
                    acc[i][j] = fmaf(a[i], b[j], acc[i][j]);
        }
        __syncthreads();
    }

    // Epilogue: bias add, scale, optional relu, float4 stores.
#pragma unroll
    for (int i = 0; i < 8; ++i) {
        const size_t crow = (size_t)(m0 + ty * 8 + i) * Ndim;
#pragma unroll
        for (int j4 = 0; j4 < 8; j4 += 4) {
            int ncol = n0 + tx * 8 + j4;
            float4 bv = *(const float4*)(bias + ncol);
            float4 c;
            c.x = (acc[i][j4 + 0] + bv.x) * alpha;
            c.y = (acc[i][j4 + 1] + bv.y) * alpha;
            c.z = (acc[i][j4 + 2] + bv.z) * alpha;
            c.w = (acc[i][j4 + 3] + bv.w) * alpha;
            if (relu) {
                c.x = fmaxf(c.x, 0.0f); c.y = fmaxf(c.y, 0.0f);
                c.z = fmaxf(c.z, 0.0f); c.w = fmaxf(c.w, 0.0f);
            }
            *(float4*)(C + crow + ncol) = c;
        }
    }
}

// ---------------------------------------------------------------------------
// Flash attention (fp32, streaming softmax).
// grid (S/64, H, B), 256 threads (16x16), each thread owns a 4x4 fragment.
// Q already scaled by DH^-0.5 (folded into the Q projection's alpha).
// Layout of Q/K/V: [B, S, H*DH] contiguous (same as reshape of [B,S,D]).
// smem = Qs(16KB) + KPs(16KB, K^T then reused for P) + Vs(16KB) = 48KB exactly.
// ---------------------------------------------------------------------------
__global__ __launch_bounds__(256) void attn_kernel(
    const float* __restrict__ Q, const float* __restrict__ K,
    const float* __restrict__ V, const float* __restrict__ mask,
    float* __restrict__ O)
{
    __shared__ float Qs[64][64];    // [q][d]
    __shared__ float KPs[64][64];   // [d][k] for K^T; reused as P [q][k]
    __shared__ float Vs[64][64];    // [k][d]

    const int tid = threadIdx.x;
    const int ty = tid >> 4;        // 0..15 -> q rows ty*4
    const int tx = tid & 15;        // 0..15 -> k cols / d cols tx*4
    const int b = blockIdx.z;
    const int h = blockIdx.y;
    const int q0 = blockIdx.x * 64;

    // Load Q tile (coalesced float4)
    for (int i = tid; i < 64 * 16; i += 256) {
        int r = i >> 4, c = (i & 15) << 2;
        float4 v = *(const float4*)(Q + (size_t)(b * SEQ + q0 + r) * DMODEL + h * DHEAD + c);
        *(float4*)&Qs[r][c] = v;
    }

    float m_i[4], l_i[4], acc[4][4];
#pragma unroll
    for (int i = 0; i < 4; ++i) {
        m_i[i] = -INFINITY; l_i[i] = 0.0f;
#pragma unroll
        for (int j = 0; j < 4; ++j) acc[i][j] = 0.0f;
    }

    for (int kt = 0; kt < SEQ; kt += 64) {
        // Load K (transposed into KPs[d][k]) and V tiles
        for (int i = tid; i < 64 * 16; i += 256) {
            int r = i >> 4, c = (i & 15) << 2;
            size_t base = (size_t)(b * SEQ + kt + r) * DMODEL + h * DHEAD + c;
            float4 kv = *(const float4*)(K + base);
            float4 vv = *(const float4*)(V + base);
            KPs[c + 0][r] = kv.x;
            KPs[c + 1][r] = kv.y;
            KPs[c + 2][r] = kv.z;
            KPs[c + 3][r] = kv.w;
            *(float4*)&Vs[r][c] = vv;
        }
        __syncthreads();

        // S = Q @ K^T  (4x4 fragment per thread)
        float sv[4][4];
#pragma unroll
        for (int i = 0; i < 4; ++i)
#pragma unroll
            for (int j = 0; j < 4; ++j) sv[i][j] = 0.0f;

#pragma unroll 16
        for (int d = 0; d < 64; ++d) {
            float qr[4], kc[4];
#pragma unroll
            for (int i = 0; i < 4; ++i) qr[i] = Qs[ty * 4 + i][d];
#pragma unroll
            for (int j = 0; j < 4; ++j) kc[j] = KPs[d][tx * 4 + j];
#pragma unroll
            for (int i = 0; i < 4; ++i)
#pragma unroll
                for (int j = 0; j < 4; ++j)
                    sv[i][j] = fmaf(qr[i], kc[j], sv[i][j]);
        }

        // Additive mask: (1 - mask[b,k]) * NEG_INF
#pragma unroll
        for (int j = 0; j < 4; ++j) {
            float madd = (1.0f - mask[b * SEQ + kt + tx * 4 + j]) * NEG_INF_F;
#pragma unroll
            for (int i = 0; i < 4; ++i) sv[i][j] += madd;
        }

        // Streaming softmax per q row (row reduction over 16 tx lanes via shfl)
        float pv[4][4];
#pragma unroll
        for (int i = 0; i < 4; ++i) {
            float mx = fmaxf(fmaxf(sv[i][0], sv[i][1]), fmaxf(sv[i][2], sv[i][3]));
#pragma unroll
            for (int o = 8; o > 0; o >>= 1)
                mx = fmaxf(mx, __shfl_xor_sync(0xffffffffu, mx, o));
            float mnew = fmaxf(m_i[i], mx);
            float rs = 0.0f;
#pragma unroll
            for (int j = 0; j < 4; ++j) {
                pv[i][j] = __expf(sv[i][j] - mnew);
                rs += pv[i][j];
            }
#pragma unroll
            for (int o = 8; o > 0; o >>= 1)
                rs += __shfl_xor_sync(0xffffffffu, rs, o);
            float sc = __expf(m_i[i] - mnew);   // 0 on first iteration (m=-inf)
            l_i[i] = l_i[i] * sc + rs;
            m_i[i] = mnew;
#pragma unroll
            for (int j = 0; j < 4; ++j) acc[i][j] *= sc;
        }

        __syncthreads();   // everyone done reading KPs as K^T
#pragma unroll
        for (int i = 0; i < 4; ++i)
#pragma unroll
            for (int j = 0; j < 4; ++j)
                KPs[ty * 4 + i][tx * 4 + j] = pv[i][j];   // reuse as P
        __syncthreads();

        // acc += P @ V
#pragma unroll 16
        for (int k = 0; k < 64; ++k) {
            float pr[4], vc[4];
#pragma unroll
            for (int i = 0; i < 4; ++i) pr[i] = KPs[ty * 4 + i][k];
#pragma unroll
            for (int j = 0; j < 4; ++j) vc[j] = Vs[k][tx * 4 + j];
#pragma unroll
            for (int i = 0; i < 4; ++i)
#pragma unroll
                for (int j = 0; j < 4; ++j)
                    acc[i][j] = fmaf(pr[i], vc[j], acc[i][j]);
        }
        __syncthreads();   // before next tile overwrites KPs/Vs
    }

    // O = acc / l
#pragma unroll
    for (int i = 0; i < 4; ++i) {
        float inv = 1.0f / l_i[i];
        float4 o4;
        o4.x = acc[i][0] * inv; o4.y = acc[i][1] * inv;
        o4.z = acc[i][2] * inv; o4.w = acc[i][3] * inv;
        *(float4*)(O + (size_t)(b * SEQ + q0 + ty * 4 + i) * DMODEL + h * DHEAD + tx * 4) = o4;
    }
}

// ---------------------------------------------------------------------------
// Fused residual + LayerNorm: out[row] = LN(x[row] + y[row]) * g + b
// One block (256 threads) per row of 1024 elements; in-place safe (out == x).
// ---------------------------------------------------------------------------
__global__ __launch_bounds__(256) void add_ln_kernel(
    const float* __restrict__ x, const float* __restrict__ y,
    const float* __restrict__ g, const float* __restrict__ beta,
    float* __restrict__ out)
{
    __shared__ float red[8];
    __shared__ float sbroadcast;

    const int row = blockIdx.x;
    const int tid = threadIdx.x;
    const int lane = tid & 31, wid = tid >> 5;
    const size_t base = (size_t)row * DMODEL + tid * 4;

    float4 xv = *(const float4*)(x + base);
    float4 yv = *(const float4*)(y + base);
    float4 v;
    v.x = xv.x + yv.x; v.y = xv.y + yv.y; v.z = xv.z + yv.z; v.w = xv.w + yv.w;

    // mean
    float s = v.x + v.y + v.z + v.w;
#pragma unroll
    for (int o = 16; o > 0; o >>= 1) s += __shfl_xor_sync(0xffffffffu, s, o);
    if (lane == 0) red[wid] = s;
    __syncthreads();
    if (tid == 0) {
        float t = 0.0f;
#pragma unroll
        for (int w = 0; w < 8; ++w) t += red[w];
        sbroadcast = t * (1.0f / DMODEL);
    }
    __syncthreads();
    const float mean = sbroadcast;

    // biased variance
    float dx0 = v.x - mean, dx1 = v.y - mean, dx2 = v.z - mean, dx3 = v.w - mean;
    float s2 = dx0 * dx0 + dx1 * dx1 + dx2 * dx2 + dx3 * dx3;
#pragma unroll
    for (int o = 16; o > 0; o >>= 1) s2 += __shfl_xor_sync(0xffffffffu, s2, o);
    __syncthreads();           // red[] reuse barrier
    if (lane == 0) red[wid] = s2;
    __syncthreads();
    if (tid == 0) {
        float t = 0.0f;
#pragma unroll
        for (int w = 0; w < 8; ++w) t += red[w];
        sbroadcast = t * (1.0f / DMODEL);
    }
    __syncthreads();
    const float rstd = rsqrtf(sbroadcast + 1e-5f);

    float4 gv = *(const float4*)(g + tid * 4);
    float4 bv = *(const float4*)(beta + tid * 4);
    float4 o4;
    o4.x = dx0 * rstd * gv.x + bv.x;
    o4.y = dx1 * rstd * gv.y + bv.y;
    o4.z = dx2 * rstd * gv.z + bv.z;
    o4.w = dx3 * rstd * gv.w + bv.w;
    *(float4*)(out + base) = o4;
}

// ---------------------------------------------------------------------------
// Launch
// ---------------------------------------------------------------------------
extern "C" void kernel_launch(void* const* d_in, const int* in_sizes, int n_in,
                              void* d_out, int out_size)
{
    (void)in_sizes; (void)n_in; (void)out_size;

    const float* x    = (const float*)d_in[0];
    const float* mask = (const float*)d_in[1];
    const float* Wq   = (const float*)d_in[2];
    const float* bq   = (const float*)d_in[3];
    const float* Wk   = (const float*)d_in[4];
    const float* bk   = (const float*)d_in[5];
    const float* Wv   = (const float*)d_in[6];
    const float* bv   = (const float*)d_in[7];
    const float* Wo   = (const float*)d_in[8];
    const float* bo   = (const float*)d_in[9];
    const float* W1   = (const float*)d_in[10];
    const float* b1   = (const float*)d_in[11];
    const float* W2   = (const float*)d_in[12];
    const float* b2   = (const float*)d_in[13];
    const float* lng  = (const float*)d_in[14];
    const float* lnb  = (const float*)d_in[15];
    float* out = (float*)d_out;

    float *gx, *gq, *gk, *gv, *go, *gy, *gh;
    cudaGetSymbolAddress((void**)&gx, g_x);
    cudaGetSymbolAddress((void**)&gq, g_q);
    cudaGetSymbolAddress((void**)&gk, g_k);
    cudaGetSymbolAddress((void**)&gv, g_v);
    cudaGetSymbolAddress((void**)&go, g_o);
    cudaGetSymbolAddress((void**)&gy, g_y);
    cudaGetSymbolAddress((void**)&gh, g_h);

    posenc_kernel<<<(SEQ * DMODEL + 255) / 256, 256>>>(x, gx);

    const float qscale = 0.125f;  // DH^-0.5
    dim3 gProj(DMODEL / 128, MROWS / 128);   // (8, 32)
    dim3 gFF1(DFF / 128, MROWS / 128);       // (32, 32)
    dim3 gAttn(SEQ / 64, NHEAD, BATCH);      // (16, 16, 4)

    for (int l = 0; l < NLAYER; ++l) {
        const float* wq = Wq + (size_t)l * DMODEL * DMODEL;
        const float* wk = Wk + (size_t)l * DMODEL * DMODEL;
        const float* wv = Wv + (size_t)l * DMODEL * DMODEL;
        const float* wo = Wo + (size_t)l * DMODEL * DMODEL;

        sgemm_kernel<<<gProj, 256>>>(gx, wq, bq + (size_t)l * DMODEL, gq,
                                     MROWS, DMODEL, DMODEL, qscale, 0);
        sgemm_kernel<<<gProj, 256>>>(gx, wk, bk + (size_t)l * DMODEL, gk,
                                     MROWS, DMODEL, DMODEL, 1.0f, 0);
        sgemm_kernel<<<gProj, 256>>>(gx, wv, bv + (size_t)l * DMODEL, gv,
                                     MROWS, DMODEL, DMODEL, 1.0f, 0);

        attn_kernel<<<gAttn, 256>>>(gq, gk, gv, mask, go);

        sgemm_kernel<<<gProj, 256>>>(go, wo, bo + (size_t)l * DMODEL, gy,
                                     MROWS, DMODEL, DMODEL, 1.0f, 0);
        add_ln_kernel<<<MROWS, 256>>>(gx, gy,
                                      lng + (size_t)(2 * l) * DMODEL,
                                      lnb + (size_t)(2 * l) * DMODEL, gx);

        sgemm_kernel<<<gFF1, 256>>>(gx, W1 + (size_t)l * DMODEL * DFF,
                                    b1 + (size_t)l * DFF, gh,
                                    MROWS, DFF, DMODEL, 1.0f, 1);
        sgemm_kernel<<<gProj, 256>>>(gh, W2 + (size_t)l * DFF * DMODEL,
                                     b2 + (size_t)l * DMODEL, gy,
                                     MROWS, DMODEL, DFF, 1.0f, 0);
        add_ln_kernel<<<MROWS, 256>>>(gx, gy,
                                      lng + (size_t)(2 * l + 1) * DMODEL,
                                      lnb + (size_t)(2 * l + 1) * DMODEL, gx);
    }

    cudaMemcpyAsync(out, gx, (size_t)MROWS * DMODEL * sizeof(float),
                    cudaMemcpyDeviceToDevice);
}

// round 3
// speedup vs baseline: 2.0889x; 2.0889x over previous
#include <cuda_runtime.h>
#include <cuda_bf16.h>
#include <math.h>
#include <stdint.h>

// Problem constants
#define NLAYER 6
#define NHEAD  16
#define DMODEL 1024
#define DHEAD  64
#define DFF    4096
#define BATCH  4
#define SEQ    1024
#define MROWS  (BATCH*SEQ)
#define NEG_INF_F (-100000000.0f)

// ---------------------------------------------------------------------------
// Scratch (static device globals; no allocation anywhere)
// ---------------------------------------------------------------------------
__device__ float g_x[MROWS*DMODEL];
__device__ float g_q[MROWS*DMODEL];
__device__ float g_k[MROWS*DMODEL];
__device__ float g_v[MROWS*DMODEL];
__device__ float g_o[MROWS*DMODEL];
__device__ float g_y[MROWS*DMODEL];
__device__ float g_h[MROWS*DFF];
__device__ __nv_bfloat16 g_ahi[MROWS*DFF];
__device__ __nv_bfloat16 g_alo[MROWS*DFF];
__device__ __nv_bfloat16 g_whi[DMODEL*DFF];
__device__ __nv_bfloat16 g_wlo[DMODEL*DFF];

// ---------------------------------------------------------------------------
// PTX helpers (non-arch-specific only: cp.async sm_80, ldmatrix sm_75, mma sm_80)
// ---------------------------------------------------------------------------
__device__ __forceinline__ uint32_t smem_u32(const void* p) {
    uint32_t a;
    asm("{ .reg .u64 t; cvta.to.shared.u64 t, %1; cvt.u32.u64 %0, t; }" : "=r"(a) : "l"(p));
    return a;
}
__device__ __forceinline__ void cp_async16(uint32_t dst, const void* src) {
    asm volatile("cp.async.cg.shared.global [%0], [%1], 16;" :: "r"(dst), "l"(src) : "memory");
}
#define CP_COMMIT() asm volatile("cp.async.commit_group;" ::: "memory")

__device__ __forceinline__ void ldsm_x4(uint32_t& r0, uint32_t& r1, uint32_t& r2,
                                        uint32_t& r3, uint32_t addr) {
    asm volatile("ldmatrix.sync.aligned.m8n8.x4.shared.b16 {%0,%1,%2,%3}, [%4];"
                 : "=r"(r0), "=r"(r1), "=r"(r2), "=r"(r3) : "r"(addr));
}
__device__ __forceinline__ void mma_bf16(float* c, const uint32_t* a, const uint32_t* b) {
    asm volatile(
        "mma.sync.aligned.m16n8k16.row.col.f32.bf16.bf16.f32 "
        "{%0,%1,%2,%3}, {%4,%5,%6,%7}, {%8,%9}, {%0,%1,%2,%3};"
        : "+f"(c[0]), "+f"(c[1]), "+f"(c[2]), "+f"(c[3])
        : "r"(a[0]), "r"(a[1]), "r"(a[2]), "r"(a[3]), "r"(b[0]), "r"(b[1]));
}

// Swizzled smem offset for a 128-row x 32-bf16 (64B/row) tile.
// Two rows share one 128B line; 16B chunk index xor'd with line index (3 bits).
// Verified: any ldmatrix phase (8 consecutive rows, fixed chunk) hits 8 distinct
// bank quads; cp.async writes of consecutive (row,chunk) are also conflict-free.
__device__ __forceinline__ uint32_t swz(int row, int c) {
    return (uint32_t)(((row >> 1) << 7) |
                      ((((((row & 1) << 2) | c)) ^ ((row >> 1) & 7)) << 4));
}

#define TILEB 8192          // one 128x32 bf16 tile
#define BUFB  (4*TILEB)     // Ahi, Alo, Bhi, Blo
#define GSMEM (2*BUFB)      // double buffered = 65536

// ---------------------------------------------------------------------------
// Positional encoding (fp64 for accuracy)
// ---------------------------------------------------------------------------
__global__ void posenc_kernel(const float* __restrict__ x, float* __restrict__ out)
{
    int idx = blockIdx.x * blockDim.x + threadIdx.x;
    if (idx >= SEQ * DMODEL) return;
    int d = idx & (DMODEL - 1);
    int s = idx >> 10;
    int t = (d < DMODEL/2) ? d : d - DMODEL/2;
    const double log_inc = log(10000.0) / (double)(DMODEL/2 - 1);
    double arg = (double)s * exp(-(double)t * log_inc);
    float sig = (float)((d < DMODEL/2) ? sin(arg) : cos(arg));
#pragma unroll
    for (int b = 0; b < BATCH; ++b) {
        size_t off = (size_t)b * SEQ * DMODEL + idx;
        out[off] = x[off] + sig;
    }
}

// ---------------------------------------------------------------------------
// fp32 -> bf16 (hi, lo) elementwise split
// ---------------------------------------------------------------------------
__global__ __launch_bounds__(256) void split_act_kernel(
    const float* __restrict__ in, __nv_bfloat16* __restrict__ hi,
    __nv_bfloat16* __restrict__ lo, int n4)
{
    int i = blockIdx.x * blockDim.x + threadIdx.x;
    if (i >= n4) return;
    float4 v = ((const float4*)in)[i];
    __nv_bfloat16 h0 = __float2bfloat16(v.x);
    __nv_bfloat16 h1 = __float2bfloat16(v.y);
    __nv_bfloat16 h2 = __float2bfloat16(v.z);
    __nv_bfloat16 h3 = __float2bfloat16(v.w);
    __nv_bfloat162 H0 = {h0, h1}, H1 = {h2, h3};
    __nv_bfloat162 L0 = {__float2bfloat16(v.x - __bfloat162float(h0)),
                         __float2bfloat16(v.y - __bfloat162float(h1))};
    __nv_bfloat162 L1 = {__float2bfloat16(v.z - __bfloat162float(h2)),
                         __float2bfloat16(v.w - __bfloat162float(h3))};
    ((__nv_bfloat162*)hi)[2*i]   = H0;
    ((__nv_bfloat162*)hi)[2*i+1] = H1;
    ((__nv_bfloat162*)lo)[2*i]   = L0;
    ((__nv_bfloat162*)lo)[2*i+1] = L1;
}

// ---------------------------------------------------------------------------
// W [K,N] fp32 -> transposed bf16 split: hiT, loT [N,K]
// ---------------------------------------------------------------------------
__global__ __launch_bounds__(256) void split_wT_kernel(
    const float* __restrict__ W, __nv_bfloat16* __restrict__ hiT,
    __nv_bfloat16* __restrict__ loT, int K, int N)
{
    __shared__ float t[32][33];
    int nx = blockIdx.x * 32;
    int ky = blockIdx.y * 32;
    int tx = threadIdx.x, ty = threadIdx.y;   // (32, 8)
#pragma unroll
    for (int i = 0; i < 4; ++i)
        t[ty + 8*i][tx] = W[(size_t)(ky + ty + 8*i) * N + nx + tx];
    __syncthreads();
#pragma unroll
    for (int i = 0; i < 4; ++i) {
        float v = t[tx][ty + 8*i];
        __nv_bfloat16 h = __float2bfloat16(v);
        size_t o = (size_t)(nx + ty + 8*i) * K + ky + tx;
        hiT[o] = h;
        loT[o] = __float2bfloat16(v - __bfloat162float(h));
    }
}

// ---------------------------------------------------------------------------
// HMMA bf16-split GEMM: C[M,N] = act((Ahi+Alo)[M,K] @ (Bhi+Blo)^T[N,K] + bias)*alpha
// 128x128 CTA tile, BK=32, 8 warps (32x64 each), double-buffered cp.async.
// 3-pass compensation: C = Ahi*Bhi + Ahi*Blo + Alo*Bhi (fp32 accumulate).
// ---------------------------------------------------------------------------
__global__ __launch_bounds__(256, 1) void mma_gemm_kernel(
    const __nv_bfloat16* __restrict__ Ahi, const __nv_bfloat16* __restrict__ Alo,
    const __nv_bfloat16* __restrict__ Bhi, const __nv_bfloat16* __restrict__ Blo,
    const float* __restrict__ bias, float* __restrict__ C,
    int M, int N, int K, float alpha, int relu)
{
    extern __shared__ char smem[];
    const uint32_t sb = smem_u32(smem);
    const int tid = threadIdx.x;
    const int wid = tid >> 5, lane = tid & 31;
    const int m0 = blockIdx.y * 128, n0 = blockIdx.x * 128;
    const int wm = (wid & 3) * 32;      // warp row base in tile
    const int wn = (wid >> 2) * 64;     // warp col base in tile

    float acc[2][8][4];
#pragma unroll
    for (int mi = 0; mi < 2; ++mi)
#pragma unroll
        for (int ni = 0; ni < 8; ++ni)
#pragma unroll
            for (int r = 0; r < 4; ++r) acc[mi][ni][r] = 0.0f;

    const int nch = K >> 5;

    // chunk loader: 4 tiles x 512 16B transfers = 8 per thread
#define LOAD_CHUNK(k0, buf)                                                     \
    {                                                                           \
        _Pragma("unroll")                                                       \
        for (int i = 0; i < 8; ++i) {                                           \
            int t = tid + i * 256;                                              \
            int tile = t >> 9;                                                  \
            int w = t & 511;                                                    \
            int row = w >> 2;                                                   \
            int c = w & 3;                                                      \
            const __nv_bfloat16* src =                                          \
                (tile == 0) ? Ahi : (tile == 1) ? Alo : (tile == 2) ? Bhi : Blo;\
            int gr = ((tile < 2) ? m0 : n0) + row;                              \
            uint32_t dst = (buf) + tile * TILEB + swz(row, c);                  \
            cp_async16(dst, src + (size_t)gr * K + (k0) + c * 8);               \
        }                                                                       \
        CP_COMMIT();                                                            \
    }

    LOAD_CHUNK(0, sb);

    // per-thread ldmatrix address components
    const int a_r = wm + (lane & 15);            // + mi*16
    const int a_h = lane >> 4;                   // k-chunk half for A
    const int b_r = wn + ((lane >> 4) << 3) + (lane & 7);   // + nt*16
    const int b_h = (lane >> 3) & 1;             // k-chunk half for B

    for (int ch = 0; ch < nch; ++ch) {
        const uint32_t buf = sb + (ch & 1) * BUFB;
        if (ch + 1 < nch) {
            LOAD_CHUNK((ch + 1) << 5, sb + ((ch + 1) & 1) * BUFB);
            asm volatile("cp.async.wait_group 1;" ::: "memory");
        } else {
            asm volatile("cp.async.wait_group 0;" ::: "memory");
        }
        __syncthreads();

        const uint32_t Ah = buf;
        const uint32_t Al = buf + TILEB;
        const uint32_t Bh = buf + 2 * TILEB;
        const uint32_t Bl = buf + 3 * TILEB;

#pragma unroll
        for (int kk = 0; kk < 2; ++kk) {
            uint32_t ahi_f[2][4], alo_f[2][4];
#pragma unroll
            for (int mi = 0; mi < 2; ++mi) {
                int r = a_r + mi * 16;
                uint32_t off = swz(r, kk * 2 + a_h);
                ldsm_x4(ahi_f[mi][0], ahi_f[mi][1], ahi_f[mi][2], ahi_f[mi][3], Ah + off);
                ldsm_x4(alo_f[mi][0], alo_f[mi][1], alo_f[mi][2], alo_f[mi][3], Al + off);
            }
            uint32_t bhi_f[8][2], blo_f[8][2];
#pragma unroll
            for (int nt = 0; nt < 4; ++nt) {
                int r = b_r + nt * 16;
                uint32_t off = swz(r, kk * 2 + b_h);
                uint32_t q0, q1, q2, q3;
                ldsm_x4(q0, q1, q2, q3, Bh + off);
                bhi_f[nt*2][0] = q0; bhi_f[nt*2][1] = q1;
                bhi_f[nt*2+1][0] = q2; bhi_f[nt*2+1][1] = q3;
                ldsm_x4(q0, q1, q2, q3, Bl + off);
                blo_f[nt*2][0] = q0; blo_f[nt*2][1] = q1;
                blo_f[nt*2+1][0] = q2; blo_f[nt*2+1][1] = q3;
            }
#pragma unroll
            for (int mi = 0; mi < 2; ++mi)
#pragma unroll
                for (int ni = 0; ni < 8; ++ni) {
                    mma_bf16(acc[mi][ni], ahi_f[mi], bhi_f[ni]);
                    mma_bf16(acc[mi][ni], ahi_f[mi], blo_f[ni]);
                    mma_bf16(acc[mi][ni], alo_f[mi], bhi_f[ni]);
                }
        }
        __syncthreads();
    }

    // Epilogue: c0,c1 -> row grp; c2,c3 -> row grp+8
    const int grp = lane >> 2, qid = lane & 3;
#pragma unroll
    for (int mi = 0; mi < 2; ++mi) {
        const int row0 = m0 + wm + mi * 16 + grp;
#pragma unroll
        for (int ni = 0; ni < 8; ++ni) {
            const int col = n0 + wn + ni * 8 + qid * 2;
            float2 b2 = *(const float2*)(bias + col);
            float2 u, v;
            u.x = (acc[mi][ni][0] + b2.x) * alpha;
            u.y = (acc[mi][ni][1] + b2.y) * alpha;
            v.x = (acc[mi][ni][2] + b2.x) * alpha;
            v.y = (acc[mi][ni][3] + b2.y) * alpha;
            if (relu) {
                u.x = fmaxf(u.x, 0.f); u.y = fmaxf(u.y, 0.f);
                v.x = fmaxf(v.x, 0.f); v.y = fmaxf(v.y, 0.f);
            }
            *(float2*)(C + (size_t)row0 * N + col) = u;
            *(float2*)(C + (size_t)(row0 + 8) * N + col) = v;
        }
    }
#undef LOAD_CHUNK
}

// ---------------------------------------------------------------------------
// Flash attention (fp32, streaming softmax) — unchanged
// ---------------------------------------------------------------------------
__global__ __launch_bounds__(256) void attn_kernel(
    const float* __restrict__ Q, const float* __restrict__ K,
    const float* __restrict__ V, const float* __restrict__ mask,
    float* __restrict__ O)
{
    __shared__ float Qs[64][64];
    __shared__ float KPs[64][64];
    __shared__ float Vs[64][64];

    const int tid = threadIdx.x;
    const int ty = tid >> 4;
    const int tx = tid & 15;
    const int b = blockIdx.z;
    const int h = blockIdx.y;
    const int q0 = blockIdx.x * 64;

    for (int i = tid; i < 64 * 16; i += 256) {
        int r = i >> 4, c = (i & 15) << 2;
        float4 v = *(const float4*)(Q + (size_t)(b * SEQ + q0 + r) * DMODEL + h * DHEAD + c);
        *(float4*)&Qs[r][c] = v;
    }

    float m_i[4], l_i[4], acc[4][4];
#pragma unroll
    for (int i = 0; i < 4; ++i) {
        m_i[i] = -INFINITY; l_i[i] = 0.0f;
#pragma unroll
        for (int j = 0; j < 4; ++j) acc[i][j] = 0.0f;
    }

    for (int kt = 0; kt < SEQ; kt += 64) {
        for (int i = tid; i < 64 * 16; i += 256) {
            int r = i >> 4, c = (i & 15) << 2;
            size_t base = (size_t)(b * SEQ + kt + r) * DMODEL + h * DHEAD + c;
            float4 kv = *(const float4*)(K + base);
            float4 vv = *(const float4*)(V + base);
            KPs[c + 0][r] = kv.x;
            KPs[c + 1][r] = kv.y;
            KPs[c + 2][r] = kv.z;
            KPs[c + 3][r] = kv.w;
            *(float4*)&Vs[r][c] = vv;
        }
        __syncthreads();

        float sv[4][4];
#pragma unroll
        for (int i = 0; i < 4; ++i)
#pragma unroll
            for (int j = 0; j < 4; ++j) sv[i][j] = 0.0f;

#pragma unroll 16
        for (int d = 0; d < 64; ++d) {
            float qr[4], kc[4];
#pragma unroll
            for (int i = 0; i < 4; ++i) qr[i] = Qs[ty * 4 + i][d];
#pragma unroll
            for (int j = 0; j < 4; ++j) kc[j] = KPs[d][tx * 4 + j];
#pragma unroll
            for (int i = 0; i < 4; ++i)
#pragma unroll
                for (int j = 0; j < 4; ++j)
                    sv[i][j] = fmaf(qr[i], kc[j], sv[i][j]);
        }

#pragma unroll
        for (int j = 0; j < 4; ++j) {
            float madd = (1.0f - mask[b * SEQ + kt + tx * 4 + j]) * NEG_INF_F;
#pragma unroll
            for (int i = 0; i < 4; ++i) sv[i][j] += madd;
        }

        float pv[4][4];
#pragma unroll
        for (int i = 0; i < 4; ++i) {
            float mx = fmaxf(fmaxf(sv[i][0], sv[i][1]), fmaxf(sv[i][2], sv[i][3]));
#pragma unroll
            for (int o = 8; o > 0; o >>= 1)
                mx = fmaxf(mx, __shfl_xor_sync(0xffffffffu, mx, o));
            float mnew = fmaxf(m_i[i], mx);
            float rs = 0.0f;
#pragma unroll
            for (int j = 0; j < 4; ++j) {
                pv[i][j] = __expf(sv[i][j] - mnew);
                rs += pv[i][j];
            }
#pragma unroll
            for (int o = 8; o > 0; o >>= 1)
                rs += __shfl_xor_sync(0xffffffffu, rs, o);
            float sc = __expf(m_i[i] - mnew);
            l_i[i] = l_i[i] * sc + rs;
            m_i[i] = mnew;
#pragma unroll
            for (int j = 0; j < 4; ++j) acc[i][j] *= sc;
        }

        __syncthreads();
#pragma unroll
        for (int i = 0; i < 4; ++i)
#pragma unroll
            for (int j = 0; j < 4; ++j)
                KPs[ty * 4 + i][tx * 4 + j] = pv[i][j];
        __syncthreads();

#pragma unroll 16
        for (int k = 0; k < 64; ++k) {
            float pr[4], vc[4];
#pragma unroll
            for (int i = 0; i < 4; ++i) pr[i] = KPs[ty * 4 + i][k];
#pragma unroll
            for (int j = 0; j < 4; ++j) vc[j] = Vs[k][tx * 4 + j];
#pragma unroll
            for (int i = 0; i < 4; ++i)
#pragma unroll
                for (int j = 0; j < 4; ++j)
                    acc[i][j] = fmaf(pr[i], vc[j], acc[i][j]);
        }
        __syncthreads();
    }

#pragma unroll
    for (int i = 0; i < 4; ++i) {
        float inv = 1.0f / l_i[i];
        float4 o4;
        o4.x = acc[i][0] * inv; o4.y = acc[i][1] * inv;
        o4.z = acc[i][2] * inv; o4.w = acc[i][3] * inv;
        *(float4*)(O + (size_t)(b * SEQ + q0 + ty * 4 + i) * DMODEL + h * DHEAD + tx * 4) = o4;
    }
}

// ---------------------------------------------------------------------------
// Fused residual + LayerNorm — unchanged
// ---------------------------------------------------------------------------
__global__ __launch_bounds__(256) void add_ln_kernel(
    const float* __restrict__ x, const float* __restrict__ y,
    const float* __restrict__ g, const float* __restrict__ beta,
    float* __restrict__ out)
{
    __shared__ float red[8];
    __shared__ float sbroadcast;

    const int row = blockIdx.x;
    const int tid = threadIdx.x;
    const int lane = tid & 31, wid = tid >> 5;
    const size_t base = (size_t)row * DMODEL + tid * 4;

    float4 xv = *(const float4*)(x + base);
    float4 yv = *(const float4*)(y + base);
    float4 v;
    v.x = xv.x + yv.x; v.y = xv.y + yv.y; v.z = xv.z + yv.z; v.w = xv.w + yv.w;

    float s = v.x + v.y + v.z + v.w;
#pragma unroll
    for (int o = 16; o > 0; o >>= 1) s += __shfl_xor_sync(0xffffffffu, s, o);
    if (lane == 0) red[wid] = s;
    __syncthreads();
    if (tid == 0) {
        float t = 0.0f;
#pragma unroll
        for (int w = 0; w < 8; ++w) t += red[w];
        sbroadcast = t * (1.0f / DMODEL);
    }
    __syncthreads();
    const float mean = sbroadcast;

    float dx0 = v.x - mean, dx1 = v.y - mean, dx2 = v.z - mean, dx3 = v.w - mean;
    float s2 = dx0 * dx0 + dx1 * dx1 + dx2 * dx2 + dx3 * dx3;
#pragma unroll
    for (int o = 16; o > 0; o >>= 1) s2 += __shfl_xor_sync(0xffffffffu, s2, o);
    __syncthreads();
    if (lane == 0) red[wid] = s2;
    __syncthreads();
    if (tid == 0) {
        float t = 0.0f;
#pragma unroll
        for (int w = 0; w < 8; ++w) t += red[w];
        sbroadcast = t * (1.0f / DMODEL);
    }
    __syncthreads();
    const float rstd = rsqrtf(sbroadcast + 1e-5f);

    float4 gv = *(const float4*)(g + tid * 4);
    float4 bv = *(const float4*)(beta + tid * 4);
    float4 o4;
    o4.x = dx0 * rstd * gv.x + bv.x;
    o4.y = dx1 * rstd * gv.y + bv.y;
    o4.z = dx2 * rstd * gv.z + bv.z;
    o4.w = dx3 * rstd * gv.w + bv.w;
    *(float4*)(out + base) = o4;
}

// ---------------------------------------------------------------------------
// Launch
// ---------------------------------------------------------------------------
extern "C" void kernel_launch(void* const* d_in, const int* in_sizes, int n_in,
                              void* d_out, int out_size)
{
    (void)in_sizes; (void)n_in; (void)out_size;

    const float* x    = (const float*)d_in[0];
    const float* mask = (const float*)d_in[1];
    const float* Wq   = (const float*)d_in[2];
    const float* bq   = (const float*)d_in[3];
    const float* Wk   = (const float*)d_in[4];
    const float* bk   = (const float*)d_in[5];
    const float* Wv   = (const float*)d_in[6];
    const float* bv   = (const float*)d_in[7];
    const float* Wo   = (const float*)d_in[8];
    const float* bo   = (const float*)d_in[9];
    const float* W1   = (const float*)d_in[10];
    const float* b1   = (const float*)d_in[11];
    const float* W2   = (const float*)d_in[12];
    const float* b2   = (const float*)d_in[13];
    const float* lng  = (const float*)d_in[14];
    const float* lnb  = (const float*)d_in[15];
    float* out = (float*)d_out;

    float *gx, *gq, *gk, *gv, *go, *gy, *gh;
    __nv_bfloat16 *ahi, *alo, *whi, *wlo;
    cudaGetSymbolAddress((void**)&gx, g_x);
    cudaGetSymbolAddress((void**)&gq, g_q);
    cudaGetSymbolAddress((void**)&gk, g_k);
    cudaGetSymbolAddress((void**)&gv, g_v);
    cudaGetSymbolAddress((void**)&go, g_o);
    cudaGetSymbolAddress((void**)&gy, g_y);
    cudaGetSymbolAddress((void**)&gh, g_h);
    cudaGetSymbolAddress((void**)&ahi, g_ahi);
    cudaGetSymbolAddress((void**)&alo, g_alo);
    cudaGetSymbolAddress((void**)&whi, g_whi);
    cudaGetSymbolAddress((void**)&wlo, g_wlo);

    static int smem_set = 0;
    if (!smem_set) {
        cudaFuncSetAttribute(mma_gemm_kernel,
                             cudaFuncAttributeMaxDynamicSharedMemorySize, GSMEM);
        smem_set = 1;
    }

    posenc_kernel<<<(SEQ * DMODEL + 255) / 256, 256>>>(x, gx);

    const float qscale = 0.125f;  // DH^-0.5
    dim3 gProj(DMODEL / 128, MROWS / 128);   // (8, 32)
    dim3 gFF1(DFF / 128, MROWS / 128);       // (32, 32)
    dim3 gAttn(SEQ / 64, NHEAD, BATCH);
    dim3 tT(32, 8);

    for (int l = 0; l < NLAYER; ++l) {
        const float* wq = Wq + (size_t)l * DMODEL * DMODEL;
        const float* wk = Wk + (size_t)l * DMODEL * DMODEL;
        const float* wv = Wv + (size_t)l * DMODEL * DMODEL;
        const float* wo = Wo + (size_t)l * DMODEL * DMODEL;

        split_act_kernel<<<(MROWS * DMODEL / 4 + 255) / 256, 256>>>(gx, ahi, alo, MROWS * DMODEL / 4);

        split_wT_kernel<<<dim3(DMODEL/32, DMODEL/32), tT>>>(wq, whi, wlo, DMODEL, DMODEL);
        mma_gemm_kernel<<<gProj, 256, GSMEM>>>(ahi, alo, whi, wlo,
            bq + (size_t)l * DMODEL, gq, MROWS, DMODEL, DMODEL, qscale, 0);

        split_wT_kernel<<<dim3(DMODEL/32, DMODEL/32), tT>>>(wk, whi, wlo, DMODEL, DMODEL);
        mma_gemm_kernel<<<gProj, 256, GSMEM>>>(ahi, alo, whi, wlo,
            bk + (size_t)l * DMODEL, gk, MROWS, DMODEL, DMODEL, 1.0f, 0);

        split_wT_kernel<<<dim3(DMODEL/32, DMODEL/32), tT>>>(wv, whi, wlo, DMODEL, DMODEL);
        mma_gemm_kernel<<<gProj, 256, GSMEM>>>(ahi, alo, whi, wlo,
            bv + (size_t)l * DMODEL, gv, MROWS, DMODEL, DMODEL, 1.0f, 0);

        attn_kernel<<<gAttn, 256>>>(gq, gk, gv, mask, go);

        split_act_kernel<<<(MROWS * DMODEL / 4 + 255) / 256, 256>>>(go, ahi, alo, MROWS * DMODEL / 4);
        split_wT_kernel<<<dim3(DMODEL/32, DMODEL/32), tT>>>(wo, whi, wlo, DMODEL, DMODEL);
        mma_gemm_kernel<<<gProj, 256, GSMEM>>>(ahi, alo, whi, wlo,
            bo + (size_t)l * DMODEL, gy, MROWS, DMODEL, DMODEL, 1.0f, 0);

        add_ln_kernel<<<MROWS, 256>>>(gx, gy,
            lng + (size_t)(2 * l) * DMODEL, lnb + (size_t)(2 * l) * DMODEL, gx);

        split_act_kernel<<<(MROWS * DMODEL / 4 + 255) / 256, 256>>>(gx, ahi, alo, MROWS * DMODEL / 4);
        split_wT_kernel<<<dim3(DFF/32, DMODEL/32), tT>>>(W1 + (size_t)l * DMODEL * DFF,
                                                         whi, wlo, DMODEL, DFF);
        mma_gemm_kernel<<<gFF1, 256, GSMEM>>>(ahi, alo, whi, wlo,
            b1 + (size_t)l * DFF, gh, MROWS, DFF, DMODEL, 1.0f, 1);

        split_act_kernel<<<(MROWS * DFF / 4 + 255) / 256, 256>>>(gh, ahi, alo, MROWS * DFF / 4);
        split_wT_kernel<<<dim3(DMODEL/32, DFF/32), tT>>>(W2 + (size_t)l * DFF * DMODEL,
                                                         whi, wlo, DFF, DMODEL);
        mma_gemm_kernel<<<gProj, 256, GSMEM>>>(ahi, alo, whi, wlo,
            b2 + (size_t)l * DMODEL, gy, MROWS, DMODEL, DFF, 1.0f, 0);

        add_ln_kernel<<<MROWS, 256>>>(gx, gy,
            lng + (size_t)(2 * l + 1) * DMODEL, lnb + (size_t)(2 * l + 1) * DMODEL, gx);
    }

    cudaMemcpyAsync(out, gx, (size_t)MROWS * DMODEL * sizeof(float),
                    cudaMemcpyDeviceToDevice);
}

// round 4
// speedup vs baseline: 2.1849x; 1.0460x over previous
#include <cuda_runtime.h>
#include <cuda_bf16.h>
#include <math.h>
#include <stdint.h>

// Problem constants
#define NLAYER 6
#define NHEAD  16
#define DMODEL 1024
#define DHEAD  64
#define DFF    4096
#define BATCH  4
#define SEQ    1024
#define MROWS  (BATCH*SEQ)
#define NEG_INF_F (-100000000.0f)

// ---------------------------------------------------------------------------
// Scratch (static device globals; no allocation anywhere)
// ---------------------------------------------------------------------------
__device__ float g_x[MROWS*DMODEL];
__device__ float g_q[MROWS*DMODEL];
__device__ float g_k[MROWS*DMODEL];
__device__ float g_v[MROWS*DMODEL];
__device__ float g_o[MROWS*DMODEL];
__device__ float g_y[MROWS*DMODEL];
__device__ float g_h[MROWS*DFF];
__device__ __nv_bfloat16 g_ahi[MROWS*DFF];
__device__ __nv_bfloat16 g_alo[MROWS*DFF];
__device__ __nv_bfloat16 g_whi[DMODEL*DFF];
__device__ __nv_bfloat16 g_wlo[DMODEL*DFF];

// ---------------------------------------------------------------------------
// PTX helpers (non-arch-specific: cp.async sm_80, ldmatrix sm_75, mma sm_80)
// ---------------------------------------------------------------------------
__device__ __forceinline__ uint32_t smem_u32(const void* p) {
    uint32_t a;
    asm("{ .reg .u64 t; cvta.to.shared.u64 t, %1; cvt.u32.u64 %0, t; }" : "=r"(a) : "l"(p));
    return a;
}
__device__ __forceinline__ void cp_async16(uint32_t dst, const void* src) {
    asm volatile("cp.async.cg.shared.global [%0], [%1], 16;" :: "r"(dst), "l"(src) : "memory");
}
#define CP_COMMIT() asm volatile("cp.async.commit_group;" ::: "memory")

__device__ __forceinline__ void ldsm_x4(uint32_t& r0, uint32_t& r1, uint32_t& r2,
                                        uint32_t& r3, uint32_t addr) {
    asm volatile("ldmatrix.sync.aligned.m8n8.x4.shared.b16 {%0,%1,%2,%3}, [%4];"
                 : "=r"(r0), "=r"(r1), "=r"(r2), "=r"(r3) : "r"(addr));
}
__device__ __forceinline__ void mma_bf16(float* c, const uint32_t* a, const uint32_t* b) {
    asm volatile(
        "mma.sync.aligned.m16n8k16.row.col.f32.bf16.bf16.f32 "
        "{%0,%1,%2,%3}, {%4,%5,%6,%7}, {%8,%9}, {%0,%1,%2,%3};"
        : "+f"(c[0]), "+f"(c[1]), "+f"(c[2]), "+f"(c[3])
        : "r"(a[0]), "r"(a[1]), "r"(a[2]), "r"(a[3]), "r"(b[0]), "r"(b[1]));
}

// Swizzled smem offset for an R-row x 32-bf16 (64B/row) tile (R <= 256).
// Two rows per 128B line; 16B chunk index xor'd with low 3 bits of line idx.
__device__ __forceinline__ uint32_t swz(int row, int c) {
    return (uint32_t)(((row >> 1) << 7) |
                      ((((((row & 1) << 2) | c)) ^ ((row >> 1) & 7)) << 4));
}

// GEMM smem geometry: 128x256 tile, BK=32, double buffered
#define A_TILE 8192          // 128x32 bf16
#define B_TILE 16384         // 256x32 bf16
#define STAGEB (2*A_TILE + 2*B_TILE)   // 49152
#define GSMEM  (2*STAGEB)              // 98304

// ---------------------------------------------------------------------------
// Positional encoding (fp64 for accuracy)
// ---------------------------------------------------------------------------
__global__ void posenc_kernel(const float* __restrict__ x, float* __restrict__ out)
{
    int idx = blockIdx.x * blockDim.x + threadIdx.x;
    if (idx >= SEQ * DMODEL) return;
    int d = idx & (DMODEL - 1);
    int s = idx >> 10;
    int t = (d < DMODEL/2) ? d : d - DMODEL/2;
    const double log_inc = log(10000.0) / (double)(DMODEL/2 - 1);
    double arg = (double)s * exp(-(double)t * log_inc);
    float sig = (float)((d < DMODEL/2) ? sin(arg) : cos(arg));
#pragma unroll
    for (int b = 0; b < BATCH; ++b) {
        size_t off = (size_t)b * SEQ * DMODEL + idx;
        out[off] = x[off] + sig;
    }
}

// ---------------------------------------------------------------------------
// fp32 -> bf16 (hi, lo) elementwise split
// ---------------------------------------------------------------------------
__global__ __launch_bounds__(256) void split_act_kernel(
    const float* __restrict__ in, __nv_bfloat16* __restrict__ hi,
    __nv_bfloat16* __restrict__ lo, int n4)
{
    int i = blockIdx.x * blockDim.x + threadIdx.x;
    if (i >= n4) return;
    float4 v = ((const float4*)in)[i];
    __nv_bfloat16 h0 = __float2bfloat16(v.x);
    __nv_bfloat16 h1 = __float2bfloat16(v.y);
    __nv_bfloat16 h2 = __float2bfloat16(v.z);
    __nv_bfloat16 h3 = __float2bfloat16(v.w);
    __nv_bfloat162 H0 = {h0, h1}, H1 = {h2, h3};
    __nv_bfloat162 L0 = {__float2bfloat16(v.x - __bfloat162float(h0)),
                         __float2bfloat16(v.y - __bfloat162float(h1))};
    __nv_bfloat162 L1 = {__float2bfloat16(v.z - __bfloat162float(h2)),
                         __float2bfloat16(v.w - __bfloat162float(h3))};
    ((__nv_bfloat162*)hi)[2*i]   = H0;
    ((__nv_bfloat162*)hi)[2*i+1] = H1;
    ((__nv_bfloat162*)lo)[2*i]   = L0;
    ((__nv_bfloat162*)lo)[2*i+1] = L1;
}

// ---------------------------------------------------------------------------
// W [K,N] fp32 -> transposed bf16 split: hiT, loT [N,K]
// ---------------------------------------------------------------------------
__global__ __launch_bounds__(256) void split_wT_kernel(
    const float* __restrict__ W, __nv_bfloat16* __restrict__ hiT,
    __nv_bfloat16* __restrict__ loT, int K, int N)
{
    __shared__ float t[32][33];
    int nx = blockIdx.x * 32;
    int ky = blockIdx.y * 32;
    int tx = threadIdx.x, ty = threadIdx.y;   // (32, 8)
#pragma unroll
    for (int i = 0; i < 4; ++i)
        t[ty + 8*i][tx] = W[(size_t)(ky + ty + 8*i) * N + nx + tx];
    __syncthreads();
#pragma unroll
    for (int i = 0; i < 4; ++i) {
        float v = t[tx][ty + 8*i];
        __nv_bfloat16 h = __float2bfloat16(v);
        size_t o = (size_t)(nx + ty + 8*i) * K + ky + tx;
        hiT[o] = h;
        loT[o] = __float2bfloat16(v - __bfloat162float(h));
    }
}

// ---------------------------------------------------------------------------
// HMMA bf16-split GEMM: C = act((Ahi+Alo)[M,K] @ (Bhi+Blo)^T[N,K] + bias)*alpha
// 128x256 CTA tile, 512 threads (16 warps, each 32x64), BK=32,
// double-buffered cp.async, 3-pass compensation with pass-major MMA ordering.
// ---------------------------------------------------------------------------
__global__ __launch_bounds__(512, 1) void mma_gemm_kernel(
    const __nv_bfloat16* __restrict__ Ahi, const __nv_bfloat16* __restrict__ Alo,
    const __nv_bfloat16* __restrict__ Bhi, const __nv_bfloat16* __restrict__ Blo,
    const float* __restrict__ bias, float* __restrict__ C,
    int M, int N, int K, float alpha, int relu)
{
    extern __shared__ char smem[];
    const uint32_t sb = smem_u32(smem);
    const int tid = threadIdx.x;
    const int wid = tid >> 5, lane = tid & 31;
    const int m0 = blockIdx.y * 128, n0 = blockIdx.x * 256;
    const int wm = (wid & 3) * 32;      // warp row base (4 m-groups)
    const int wn = (wid >> 2) * 64;     // warp col base (4 n-groups * 64 = 256)

    float acc[2][8][4];
#pragma unroll
    for (int mi = 0; mi < 2; ++mi)
#pragma unroll
        for (int ni = 0; ni < 8; ++ni)
#pragma unroll
            for (int r = 0; r < 4; ++r) acc[mi][ni][r] = 0.0f;

    const int nch = K >> 5;

    // chunk loader: A tiles 1024 + B tiles 2048 = 3072 x 16B; 6 per thread
#define LOAD_CHUNK(k0, buf)                                                     \
    {                                                                           \
        _Pragma("unroll")                                                       \
        for (int i = 0; i < 6; ++i) {                                           \
            int t = tid + i * 512;                                              \
            const __nv_bfloat16* src;                                           \
            int row, c, gr;                                                     \
            uint32_t toff;                                                      \
            if (t < 1024) {                                                     \
                int tile = t >> 9;                                              \
                int w = t & 511;                                                \
                row = w >> 2; c = w & 3;                                        \
                src = tile ? Alo : Ahi;                                         \
                toff = tile ? A_TILE : 0u;                                      \
                gr = m0 + row;                                                  \
            } else {                                                            \
                int u = t - 1024;                                               \
                int tile = u >> 10;                                             \
                int w = u & 1023;                                               \
                row = w >> 2; c = w & 3;                                        \
                src = tile ? Blo : Bhi;                                         \
                toff = tile ? (2u*A_TILE + B_TILE) : (2u*A_TILE);               \
                gr = n0 + row;                                                  \
            }                                                                   \
            cp_async16((buf) + toff + swz(row, c),                              \
                       src + (size_t)gr * K + (k0) + c * 8);                    \
        }                                                                       \
        CP_COMMIT();                                                            \
    }

    LOAD_CHUNK(0, sb);

    const int a_r = wm + (lane & 15);                       // + mi*16
    const int a_h = lane >> 4;
    const int b_r = wn + ((lane >> 4) << 3) + (lane & 7);   // + nt*16
    const int b_h = (lane >> 3) & 1;

    for (int ch = 0; ch < nch; ++ch) {
        const uint32_t buf = sb + (ch & 1) * STAGEB;
        if (ch + 1 < nch) {
            LOAD_CHUNK((ch + 1) << 5, sb + ((ch + 1) & 1) * STAGEB);
            asm volatile("cp.async.wait_group 1;" ::: "memory");
        } else {
            asm volatile("cp.async.wait_group 0;" ::: "memory");
        }
        __syncthreads();

        const uint32_t Ah = buf;
        const uint32_t Al = buf + A_TILE;
        const uint32_t Bh = buf + 2 * A_TILE;
        const uint32_t Bl = buf + 2 * A_TILE + B_TILE;

#pragma unroll
        for (int kk = 0; kk < 2; ++kk) {
            uint32_t ahi_f[2][4], alo_f[2][4];
#pragma unroll
            for (int mi = 0; mi < 2; ++mi) {
                int r = a_r + mi * 16;
                uint32_t off = swz(r, kk * 2 + a_h);
                ldsm_x4(ahi_f[mi][0], ahi_f[mi][1], ahi_f[mi][2], ahi_f[mi][3], Ah + off);
                ldsm_x4(alo_f[mi][0], alo_f[mi][1], alo_f[mi][2], alo_f[mi][3], Al + off);
            }
            uint32_t bf[8][2];
            // --- B-hi fragments: passes Ahi*Bhi and Alo*Bhi ---
#pragma unroll
            for (int nt = 0; nt < 4; ++nt) {
                int r = b_r + nt * 16;
                uint32_t off = swz(r, kk * 2 + b_h);
                uint32_t q0, q1, q2, q3;
                ldsm_x4(q0, q1, q2, q3, Bh + off);
                bf[nt*2][0] = q0; bf[nt*2][1] = q1;
                bf[nt*2+1][0] = q2; bf[nt*2+1][1] = q3;
            }
#pragma unroll
            for (int mi = 0; mi < 2; ++mi)
#pragma unroll
                for (int ni = 0; ni < 8; ++ni)
                    mma_bf16(acc[mi][ni], ahi_f[mi], bf[ni]);
#pragma unroll
            for (int mi = 0; mi < 2; ++mi)
#pragma unroll
                for (int ni = 0; ni < 8; ++ni)
                    mma_bf16(acc[mi][ni], alo_f[mi], bf[ni]);
            // --- B-lo fragments (reuse regs): pass Ahi*Blo ---
#pragma unroll
            for (int nt = 0; nt < 4; ++nt) {
                int r = b_r + nt * 16;
                uint32_t off = swz(r, kk * 2 + b_h);
                uint32_t q0, q1, q2, q3;
                ldsm_x4(q0, q1, q2, q3, Bl + off);
                bf[nt*2][0] = q0; bf[nt*2][1] = q1;
                bf[nt*2+1][0] = q2; bf[nt*2+1][1] = q3;
            }
#pragma unroll
            for (int mi = 0; mi < 2; ++mi)
#pragma unroll
                for (int ni = 0; ni < 8; ++ni)
                    mma_bf16(acc[mi][ni], ahi_f[mi], bf[ni]);
        }
        __syncthreads();
    }

    // Epilogue: c0,c1 -> row grp; c2,c3 -> row grp+8
    const int grp = lane >> 2, qid = lane & 3;
#pragma unroll
    for (int mi = 0; mi < 2; ++mi) {
        const int row0 = m0 + wm + mi * 16 + grp;
#pragma unroll
        for (int ni = 0; ni < 8; ++ni) {
            const int col = n0 + wn + ni * 8 + qid * 2;
            float2 b2 = *(const float2*)(bias + col);
            float2 u, v;
            u.x = (acc[mi][ni][0] + b2.x) * alpha;
            u.y = (acc[mi][ni][1] + b2.y) * alpha;
            v.x = (acc[mi][ni][2] + b2.x) * alpha;
            v.y = (acc[mi][ni][3] + b2.y) * alpha;
            if (relu) {
                u.x = fmaxf(u.x, 0.f); u.y = fmaxf(u.y, 0.f);
                v.x = fmaxf(v.x, 0.f); v.y = fmaxf(v.y, 0.f);
            }
            *(float2*)(C + (size_t)row0 * N + col) = u;
            *(float2*)(C + (size_t)(row0 + 8) * N + col) = v;
        }
    }
#undef LOAD_CHUNK
}

// ---------------------------------------------------------------------------
// Flash attention (fp32, streaming softmax) — unchanged
// ---------------------------------------------------------------------------
__global__ __launch_bounds__(256) void attn_kernel(
    const float* __restrict__ Q, const float* __restrict__ K,
    const float* __restrict__ V, const float* __restrict__ mask,
    float* __restrict__ O)
{
    __shared__ float Qs[64][64];
    __shared__ float KPs[64][64];
    __shared__ float Vs[64][64];

    const int tid = threadIdx.x;
    const int ty = tid >> 4;
    const int tx = tid & 15;
    const int b = blockIdx.z;
    const int h = blockIdx.y;
    const int q0 = blockIdx.x * 64;

    for (int i = tid; i < 64 * 16; i += 256) {
        int r = i >> 4, c = (i & 15) << 2;
        float4 v = *(const float4*)(Q + (size_t)(b * SEQ + q0 + r) * DMODEL + h * DHEAD + c);
        *(float4*)&Qs[r][c] = v;
    }

    float m_i[4], l_i[4], acc[4][4];
#pragma unroll
    for (int i = 0; i < 4; ++i) {
        m_i[i] = -INFINITY; l_i[i] = 0.0f;
#pragma unroll
        for (int j = 0; j < 4; ++j) acc[i][j] = 0.0f;
    }

    for (int kt = 0; kt < SEQ; kt += 64) {
        for (int i = tid; i < 64 * 16; i += 256) {
            int r = i >> 4, c = (i & 15) << 2;
            size_t base = (size_t)(b * SEQ + kt + r) * DMODEL + h * DHEAD + c;
            float4 kv = *(const float4*)(K + base);
            float4 vv = *(const float4*)(V + base);
            KPs[c + 0][r] = kv.x;
            KPs[c + 1][r] = kv.y;
            KPs[c + 2][r] = kv.z;
            KPs[c + 3][r] = kv.w;
            *(float4*)&Vs[r][c] = vv;
        }
        __syncthreads();

        float sv[4][4];
#pragma unroll
        for (int i = 0; i < 4; ++i)
#pragma unroll
            for (int j = 0; j < 4; ++j) sv[i][j] = 0.0f;

#pragma unroll 16
        for (int d = 0; d < 64; ++d) {
            float qr[4], kc[4];
#pragma unroll
            for (int i = 0; i < 4; ++i) qr[i] = Qs[ty * 4 + i][d];
#pragma unroll
            for (int j = 0; j < 4; ++j) kc[j] = KPs[d][tx * 4 + j];
#pragma unroll
            for (int i = 0; i < 4; ++i)
#pragma unroll
                for (int j = 0; j < 4; ++j)
                    sv[i][j] = fmaf(qr[i], kc[j], sv[i][j]);
        }

#pragma unroll
        for (int j = 0; j < 4; ++j) {
            float madd = (1.0f - mask[b * SEQ + kt + tx * 4 + j]) * NEG_INF_F;
#pragma unroll
            for (int i = 0; i < 4; ++i) sv[i][j] += madd;
        }

        float pv[4][4];
#pragma unroll
        for (int i = 0; i < 4; ++i) {
            float mx = fmaxf(fmaxf(sv[i][0], sv[i][1]), fmaxf(sv[i][2], sv[i][3]));
#pragma unroll
            for (int o = 8; o > 0; o >>= 1)
                mx = fmaxf(mx, __shfl_xor_sync(0xffffffffu, mx, o));
            float mnew = fmaxf(m_i[i], mx);
            float rs = 0.0f;
#pragma unroll
            for (int j = 0; j < 4; ++j) {
                pv[i][j] = __expf(sv[i][j] - mnew);
                rs += pv[i][j];
            }
#pragma unroll
            for (int o = 8; o > 0; o >>= 1)
                rs += __shfl_xor_sync(0xffffffffu, rs, o);
            float sc = __expf(m_i[i] - mnew);
            l_i[i] = l_i[i] * sc + rs;
            m_i[i] = mnew;
#pragma unroll
            for (int j = 0; j < 4; ++j) acc[i][j] *= sc;
        }

        __syncthreads();
#pragma unroll
        for (int i = 0; i < 4; ++i)
#pragma unroll
            for (int j = 0; j < 4; ++j)
                KPs[ty * 4 + i][tx * 4 + j] = pv[i][j];
        __syncthreads();

#pragma unroll 16
        for (int k = 0; k < 64; ++k) {
            float pr[4], vc[4];
#pragma unroll
            for (int i = 0; i < 4; ++i) pr[i] = KPs[ty * 4 + i][k];
#pragma unroll
            for (int j = 0; j < 4; ++j) vc[j] = Vs[k][tx * 4 + j];
#pragma unroll
            for (int i = 0; i < 4; ++i)
#pragma unroll
                for (int j = 0; j < 4; ++j)
                    acc[i][j] = fmaf(pr[i], vc[j], acc[i][j]);
        }
        __syncthreads();
    }

#pragma unroll
    for (int i = 0; i < 4; ++i) {
        float inv = 1.0f / l_i[i];
        float4 o4;
        o4.x = acc[i][0] * inv; o4.y = acc[i][1] * inv;
        o4.z = acc[i][2] * inv; o4.w = acc[i][3] * inv;
        *(float4*)(O + (size_t)(b * SEQ + q0 + ty * 4 + i) * DMODEL + h * DHEAD + tx * 4) = o4;
    }
}

// ---------------------------------------------------------------------------
// Fused residual + LayerNorm — unchanged
// ---------------------------------------------------------------------------
__global__ __launch_bounds__(256) void add_ln_kernel(
    const float* __restrict__ x, const float* __restrict__ y,
    const float* __restrict__ g, const float* __restrict__ beta,
    float* __restrict__ out)
{
    __shared__ float red[8];
    __shared__ float sbroadcast;

    const int row = blockIdx.x;
    const int tid = threadIdx.x;
    const int lane = tid & 31, wid = tid >> 5;
    const size_t base = (size_t)row * DMODEL + tid * 4;

    float4 xv = *(const float4*)(x + base);
    float4 yv = *(const float4*)(y + base);
    float4 v;
    v.x = xv.x + yv.x; v.y = xv.y + yv.y; v.z = xv.z + yv.z; v.w = xv.w + yv.w;

    float s = v.x + v.y + v.z + v.w;
#pragma unroll
    for (int o = 16; o > 0; o >>= 1) s += __shfl_xor_sync(0xffffffffu, s, o);
    if (lane == 0) red[wid] = s;
    __syncthreads();
    if (tid == 0) {
        float t = 0.0f;
#pragma unroll
        for (int w = 0; w < 8; ++w) t += red[w];
        sbroadcast = t * (1.0f / DMODEL);
    }
    __syncthreads();
    const float mean = sbroadcast;

    float dx0 = v.x - mean, dx1 = v.y - mean, dx2 = v.z - mean, dx3 = v.w - mean;
    float s2 = dx0 * dx0 + dx1 * dx1 + dx2 * dx2 + dx3 * dx3;
#pragma unroll
    for (int o = 16; o > 0; o >>= 1) s2 += __shfl_xor_sync(0xffffffffu, s2, o);
    __syncthreads();
    if (lane == 0) red[wid] = s2;
    __syncthreads();
    if (tid == 0) {
        float t = 0.0f;
#pragma unroll
        for (int w = 0; w < 8; ++w) t += red[w];
        sbroadcast = t * (1.0f / DMODEL);
    }
    __syncthreads();
    const float rstd = rsqrtf(sbroadcast + 1e-5f);

    float4 gv = *(const float4*)(g + tid * 4);
    float4 bv = *(const float4*)(beta + tid * 4);
    float4 o4;
    o4.x = dx0 * rstd * gv.x + bv.x;
    o4.y = dx1 * rstd * gv.y + bv.y;
    o4.z = dx2 * rstd * gv.z + bv.z;
    o4.w = dx3 * rstd * gv.w + bv.w;
    *(float4*)(out + base) = o4;
}

// ---------------------------------------------------------------------------
// Launch
// ---------------------------------------------------------------------------
extern "C" void kernel_launch(void* const* d_in, const int* in_sizes, int n_in,
                              void* d_out, int out_size)
{
    (void)in_sizes; (void)n_in; (void)out_size;

    const float* x    = (const float*)d_in[0];
    const float* mask = (const float*)d_in[1];
    const float* Wq   = (const float*)d_in[2];
    const float* bq   = (const float*)d_in[3];
    const float* Wk   = (const float*)d_in[4];
    const float* bk   = (const float*)d_in[5];
    const float* Wv   = (const float*)d_in[6];
    const float* bv   = (const float*)d_in[7];
    const float* Wo   = (const float*)d_in[8];
    const float* bo   = (const float*)d_in[9];
    const float* W1   = (const float*)d_in[10];
    const float* b1   = (const float*)d_in[11];
    const float* W2   = (const float*)d_in[12];
    const float* b2   = (const float*)d_in[13];
    const float* lng  = (const float*)d_in[14];
    const float* lnb  = (const float*)d_in[15];
    float* out = (float*)d_out;

    float *gx, *gq, *gk, *gv, *go, *gy, *gh;
    __nv_bfloat16 *ahi, *alo, *whi, *wlo;
    cudaGetSymbolAddress((void**)&gx, g_x);
    cudaGetSymbolAddress((void**)&gq, g_q);
    cudaGetSymbolAddress((void**)&gk, g_k);
    cudaGetSymbolAddress((void**)&gv, g_v);
    cudaGetSymbolAddress((void**)&go, g_o);
    cudaGetSymbolAddress((void**)&gy, g_y);
    cudaGetSymbolAddress((void**)&gh, g_h);
    cudaGetSymbolAddress((void**)&ahi, g_ahi);
    cudaGetSymbolAddress((void**)&alo, g_alo);
    cudaGetSymbolAddress((void**)&whi, g_whi);
    cudaGetSymbolAddress((void**)&wlo, g_wlo);

    static int smem_set = 0;
    if (!smem_set) {
        cudaFuncSetAttribute(mma_gemm_kernel,
                             cudaFuncAttributeMaxDynamicSharedMemorySize, GSMEM);
        smem_set = 1;
    }

    posenc_kernel<<<(SEQ * DMODEL + 255) / 256, 256>>>(x, gx);

    const float qscale = 0.125f;  // DH^-0.5
    dim3 gProj(DMODEL / 256, MROWS / 128);   // (4, 32)
    dim3 gFF1(DFF / 256, MROWS / 128);       // (16, 32)
    dim3 gAttn(SEQ / 64, NHEAD, BATCH);
    dim3 tT(32, 8);

    for (int l = 0; l < NLAYER; ++l) {
        const float* wq = Wq + (size_t)l * DMODEL * DMODEL;
        const float* wk = Wk + (size_t)l * DMODEL * DMODEL;
        const float* wv = Wv + (size_t)l * DMODEL * DMODEL;
        const float* wo = Wo + (size_t)l * DMODEL * DMODEL;

        split_act_kernel<<<(MROWS * DMODEL / 4 + 255) / 256, 256>>>(gx, ahi, alo, MROWS * DMODEL / 4);

        split_wT_kernel<<<dim3(DMODEL/32, DMODEL/32), tT>>>(wq, whi, wlo, DMODEL, DMODEL);
        mma_gemm_kernel<<<gProj, 512, GSMEM>>>(ahi, alo, whi, wlo,
            bq + (size_t)l * DMODEL, gq, MROWS, DMODEL, DMODEL, qscale, 0);

        split_wT_kernel<<<dim3(DMODEL/32, DMODEL/32), tT>>>(wk, whi, wlo, DMODEL, DMODEL);
        mma_gemm_kernel<<<gProj, 512, GSMEM>>>(ahi, alo, whi, wlo,
            bk + (size_t)l * DMODEL, gk, MROWS, DMODEL, DMODEL, 1.0f, 0);

        split_wT_kernel<<<dim3(DMODEL/32, DMODEL/32), tT>>>(wv, whi, wlo, DMODEL, DMODEL);
        mma_gemm_kernel<<<gProj, 512, GSMEM>>>(ahi, alo, whi, wlo,
            bv + (size_t)l * DMODEL, gv, MROWS, DMODEL, DMODEL, 1.0f, 0);

        attn_kernel<<<gAttn, 256>>>(gq, gk, gv, mask, go);

        split_act_kernel<<<(MROWS * DMODEL / 4 + 255) / 256, 256>>>(go, ahi, alo, MROWS * DMODEL / 4);
        split_wT_kernel<<<dim3(DMODEL/32, DMODEL/32), tT>>>(wo, whi, wlo, DMODEL, DMODEL);
        mma_gemm_kernel<<<gProj, 512, GSMEM>>>(ahi, alo, whi, wlo,
            bo + (size_t)l * DMODEL, gy, MROWS, DMODEL, DMODEL, 1.0f, 0);

        add_ln_kernel<<<MROWS, 256>>>(gx, gy,
            lng + (size_t)(2 * l) * DMODEL, lnb + (size_t)(2 * l) * DMODEL, gx);

        split_act_kernel<<<(MROWS * DMODEL / 4 + 255) / 256, 256>>>(gx, ahi, alo, MROWS * DMODEL / 4);
        split_wT_kernel<<<dim3(DFF/32, DMODEL/32), tT>>>(W1 + (size_t)l * DMODEL * DFF,
                                                         whi, wlo, DMODEL, DFF);
        mma_gemm_kernel<<<gFF1, 512, GSMEM>>>(ahi, alo, whi, wlo,
            b1 + (size_t)l * DFF, gh, MROWS, DFF, DMODEL, 1.0f, 1);

        split_act_kernel<<<(MROWS * DFF / 4 + 255) / 256, 256>>>(gh, ahi, alo, MROWS * DFF / 4);
        split_wT_kernel<<<dim3(DMODEL/32, DFF/32), tT>>>(W2 + (size_t)l * DFF * DMODEL,
                                                         whi, wlo, DFF, DMODEL);
        mma_gemm_kernel<<<gProj, 512, GSMEM>>>(ahi, alo, whi, wlo,
            b2 + (size_t)l * DMODEL, gy, MROWS, DMODEL, DFF, 1.0f, 0);

        add_ln_kernel<<<MROWS, 256>>>(gx, gy,
            lng + (size_t)(2 * l + 1) * DMODEL, lnb + (size_t)(2 * l + 1) * DMODEL, gx);
    }

    cudaMemcpyAsync(out, gx, (size_t)MROWS * DMODEL * sizeof(float),
                    cudaMemcpyDeviceToDevice);
}

// round 5
// speedup vs baseline: 2.9241x; 1.3383x over previous
#include <cuda_runtime.h>
#include <cuda_bf16.h>
#include <math.h>
#include <stdint.h>

// Problem constants
#define NLAYER 6
#define NHEAD  16
#define DMODEL 1024
#define DHEAD  64
#define DFF    4096
#define BATCH  4
#define SEQ    1024
#define MROWS  (BATCH*SEQ)
#define NEG_INF_F (-100000000.0f)

// ---------------------------------------------------------------------------
// Scratch (static device globals; no allocation anywhere)
// ---------------------------------------------------------------------------
__device__ float g_x[MROWS*DMODEL];   // running activation (fp32)
__device__ float g_y[MROWS*DMODEL];   // gemm fp32 output (pre-LN)
__device__ __nv_bfloat16 g_xhi[MROWS*DMODEL], g_xlo[MROWS*DMODEL];
__device__ __nv_bfloat16 g_qhi[MROWS*DMODEL], g_qlo[MROWS*DMODEL];
__device__ __nv_bfloat16 g_khi[MROWS*DMODEL], g_klo[MROWS*DMODEL];
__device__ __nv_bfloat16 g_vhi[MROWS*DMODEL], g_vlo[MROWS*DMODEL];
__device__ __nv_bfloat16 g_ohi[MROWS*DMODEL], g_olo[MROWS*DMODEL];
__device__ __nv_bfloat16 g_hhi[MROWS*DFF],    g_hlo[MROWS*DFF];
__device__ __nv_bfloat16 g_whi[DMODEL*DFF],   g_wlo[DMODEL*DFF];

// ---------------------------------------------------------------------------
// PTX helpers (non-arch-specific: cp.async sm_80, ldmatrix sm_75, mma sm_80)
// ---------------------------------------------------------------------------
__device__ __forceinline__ uint32_t smem_u32(const void* p) {
    uint32_t a;
    asm("{ .reg .u64 t; cvta.to.shared.u64 t, %1; cvt.u32.u64 %0, t; }" : "=r"(a) : "l"(p));
    return a;
}
__device__ __forceinline__ void cp_async16(uint32_t dst, const void* src) {
    asm volatile("cp.async.cg.shared.global [%0], [%1], 16;" :: "r"(dst), "l"(src) : "memory");
}
#define CP_COMMIT() asm volatile("cp.async.commit_group;" ::: "memory")

__device__ __forceinline__ void ldsm_x4(uint32_t& r0, uint32_t& r1, uint32_t& r2,
                                        uint32_t& r3, uint32_t addr) {
    asm volatile("ldmatrix.sync.aligned.m8n8.x4.shared.b16 {%0,%1,%2,%3}, [%4];"
                 : "=r"(r0), "=r"(r1), "=r"(r2), "=r"(r3) : "r"(addr));
}
__device__ __forceinline__ void ldsm_x4_t(uint32_t& r0, uint32_t& r1, uint32_t& r2,
                                          uint32_t& r3, uint32_t addr) {
    asm volatile("ldmatrix.sync.aligned.m8n8.x4.trans.shared.b16 {%0,%1,%2,%3}, [%4];"
                 : "=r"(r0), "=r"(r1), "=r"(r2), "=r"(r3) : "r"(addr));
}
__device__ __forceinline__ void mma_bf16(float* c, const uint32_t* a, const uint32_t* b) {
    asm volatile(
        "mma.sync.aligned.m16n8k16.row.col.f32.bf16.bf16.f32 "
        "{%0,%1,%2,%3}, {%4,%5,%6,%7}, {%8,%9}, {%0,%1,%2,%3};"
        : "+f"(c[0]), "+f"(c[1]), "+f"(c[2]), "+f"(c[3])
        : "r"(a[0]), "r"(a[1]), "r"(a[2]), "r"(a[3]), "r"(b[0]), "r"(b[1]));
}
// pack two floats into bf16x2 hi + bf16x2 residual lo
__device__ __forceinline__ void pack_split(float x, float y, uint32_t& hi, uint32_t& lo) {
    __nv_bfloat16 hx = __float2bfloat16(x), hy = __float2bfloat16(y);
    __nv_bfloat162 H; H.x = hx; H.y = hy;
    __nv_bfloat162 L;
    L.x = __float2bfloat16(x - __bfloat162float(hx));
    L.y = __float2bfloat16(y - __bfloat162float(hy));
    hi = *(uint32_t*)&H; lo = *(uint32_t*)&L;
}

// Swizzle for 64B-row tiles (GEMM: 32 bf16/row)
__device__ __forceinline__ uint32_t swz(int row, int c) {
    return (uint32_t)(((row >> 1) << 7) |
                      ((((((row & 1) << 2) | c)) ^ ((row >> 1) & 7)) << 4));
}
// Swizzle for 128B-row tiles (attention: 64 bf16/row, 8 chunks of 16B)
__device__ __forceinline__ uint32_t swz128(int row, int c) {
    return (uint32_t)((row << 7) | (((c ^ (row & 7))) << 4));
}

// GEMM smem geometry: 128x256 tile, BK=32, double buffered
#define A_TILE 8192
#define B_TILE 16384
#define STAGEB (2*A_TILE + 2*B_TILE)
#define GSMEM  (2*STAGEB)

// Attention smem: Qh,Ql,Kh,Kl,Vh,Vl (8KB each) + mask floats
#define ATTN_SMEM (6*8192 + 256)

// ---------------------------------------------------------------------------
// Positional encoding (fp64 for accuracy)
// ---------------------------------------------------------------------------
__global__ void posenc_kernel(const float* __restrict__ x, float* __restrict__ out)
{
    int idx = blockIdx.x * blockDim.x + threadIdx.x;
    if (idx >= SEQ * DMODEL) return;
    int d = idx & (DMODEL - 1);
    int s = idx >> 10;
    int t = (d < DMODEL/2) ? d : d - DMODEL/2;
    const double log_inc = log(10000.0) / (double)(DMODEL/2 - 1);
    double arg = (double)s * exp(-(double)t * log_inc);
    float sig = (float)((d < DMODEL/2) ? sin(arg) : cos(arg));
#pragma unroll
    for (int b = 0; b < BATCH; ++b) {
        size_t off = (size_t)b * SEQ * DMODEL + idx;
        out[off] = x[off] + sig;
    }
}

// ---------------------------------------------------------------------------
// fp32 -> bf16 (hi, lo) elementwise split (only used once, after posenc)
// ---------------------------------------------------------------------------
__global__ __launch_bounds__(256) void split_act_kernel(
    const float* __restrict__ in, __nv_bfloat16* __restrict__ hi,
    __nv_bfloat16* __restrict__ lo, int n4)
{
    int i = blockIdx.x * blockDim.x + threadIdx.x;
    if (i >= n4) return;
    float4 v = ((const float4*)in)[i];
    uint32_t h0, l0, h1, l1;
    pack_split(v.x, v.y, h0, l0);
    pack_split(v.z, v.w, h1, l1);
    ((uint32_t*)hi)[2*i]   = h0;
    ((uint32_t*)hi)[2*i+1] = h1;
    ((uint32_t*)lo)[2*i]   = l0;
    ((uint32_t*)lo)[2*i+1] = l1;
}

// ---------------------------------------------------------------------------
// W [K,N] fp32 -> transposed bf16 split: hiT, loT [N,K]
// ---------------------------------------------------------------------------
__global__ __launch_bounds__(256) void split_wT_kernel(
    const float* __restrict__ W, __nv_bfloat16* __restrict__ hiT,
    __nv_bfloat16* __restrict__ loT, int K, int N)
{
    __shared__ float t[32][33];
    int nx = blockIdx.x * 32;
    int ky = blockIdx.y * 32;
    int tx = threadIdx.x, ty = threadIdx.y;   // (32, 8)
#pragma unroll
    for (int i = 0; i < 4; ++i)
        t[ty + 8*i][tx] = W[(size_t)(ky + ty + 8*i) * N + nx + tx];
    __syncthreads();
#pragma unroll
    for (int i = 0; i < 4; ++i) {
        float v = t[tx][ty + 8*i];
        __nv_bfloat16 h = __float2bfloat16(v);
        size_t o = (size_t)(nx + ty + 8*i) * K + ky + tx;
        hiT[o] = h;
        loT[o] = __float2bfloat16(v - __bfloat162float(h));
    }
}

// ---------------------------------------------------------------------------
// HMMA bf16-split GEMM. outmode 0: fp32 C. outmode 1: bf16 split (Chi, Clo).
// 128x256 CTA tile, 512 threads, BK=32, double-buffered cp.async, 3-pass.
// ---------------------------------------------------------------------------
__global__ __launch_bounds__(512, 1) void mma_gemm_kernel(
    const __nv_bfloat16* __restrict__ Ahi, const __nv_bfloat16* __restrict__ Alo,
    const __nv_bfloat16* __restrict__ Bhi, const __nv_bfloat16* __restrict__ Blo,
    const float* __restrict__ bias, float* __restrict__ C,
    __nv_bfloat16* __restrict__ Chi, __nv_bfloat16* __restrict__ Clo,
    int M, int N, int K, float alpha, int relu, int outmode)
{
    extern __shared__ char smem[];
    const uint32_t sb = smem_u32(smem);
    const int tid = threadIdx.x;
    const int wid = tid >> 5, lane = tid & 31;
    const int m0 = blockIdx.y * 128, n0 = blockIdx.x * 256;
    const int wm = (wid & 3) * 32;
    const int wn = (wid >> 2) * 64;

    float acc[2][8][4];
#pragma unroll
    for (int mi = 0; mi < 2; ++mi)
#pragma unroll
        for (int ni = 0; ni < 8; ++ni)
#pragma unroll
            for (int r = 0; r < 4; ++r) acc[mi][ni][r] = 0.0f;

    const int nch = K >> 5;

#define LOAD_CHUNK(k0, buf)                                                     \
    {                                                                           \
        _Pragma("unroll")                                                       \
        for (int i = 0; i < 6; ++i) {                                           \
            int t = tid + i * 512;                                              \
            const __nv_bfloat16* src;                                           \
            int row, c, gr;                                                     \
            uint32_t toff;                                                      \
            if (t < 1024) {                                                     \
                int tile = t >> 9;                                              \
                int w = t & 511;                                                \
                row = w >> 2; c = w & 3;                                        \
                src = tile ? Alo : Ahi;                                         \
                toff = tile ? A_TILE : 0u;                                      \
                gr = m0 + row;                                                  \
            } else {                                                            \
                int u = t - 1024;                                               \
                int tile = u >> 10;                                             \
                int w = u & 1023;                                               \
                row = w >> 2; c = w & 3;                                        \
                src = tile ? Blo : Bhi;                                         \
                toff = tile ? (2u*A_TILE + B_TILE) : (2u*A_TILE);               \
                gr = n0 + row;                                                  \
            }                                                                   \
            cp_async16((buf) + toff + swz(row, c),                              \
                       src + (size_t)gr * K + (k0) + c * 8);                    \
        }                                                                       \
        CP_COMMIT();                                                            \
    }

    LOAD_CHUNK(0, sb);

    const int a_r = wm + (lane & 15);
    const int a_h = lane >> 4;
    const int b_r = wn + ((lane >> 4) << 3) + (lane & 7);
    const int b_h = (lane >> 3) & 1;

    for (int ch = 0; ch < nch; ++ch) {
        const uint32_t buf = sb + (ch & 1) * STAGEB;
        if (ch + 1 < nch) {
            LOAD_CHUNK((ch + 1) << 5, sb + ((ch + 1) & 1) * STAGEB);
            asm volatile("cp.async.wait_group 1;" ::: "memory");
        } else {
            asm volatile("cp.async.wait_group 0;" ::: "memory");
        }
        __syncthreads();

        const uint32_t Ah = buf;
        const uint32_t Al = buf + A_TILE;
        const uint32_t Bh = buf + 2 * A_TILE;
        const uint32_t Bl = buf + 2 * A_TILE + B_TILE;

#pragma unroll
        for (int kk = 0; kk < 2; ++kk) {
            uint32_t ahi_f[2][4], alo_f[2][4];
#pragma unroll
            for (int mi = 0; mi < 2; ++mi) {
                int r = a_r + mi * 16;
                uint32_t off = swz(r, kk * 2 + a_h);
                ldsm_x4(ahi_f[mi][0], ahi_f[mi][1], ahi_f[mi][2], ahi_f[mi][3], Ah + off);
                ldsm_x4(alo_f[mi][0], alo_f[mi][1], alo_f[mi][2], alo_f[mi][3], Al + off);
            }
            uint32_t bf[8][2];
#pragma unroll
            for (int nt = 0; nt < 4; ++nt) {
                int r = b_r + nt * 16;
                uint32_t off = swz(r, kk * 2 + b_h);
                uint32_t q0, q1, q2, q3;
                ldsm_x4(q0, q1, q2, q3, Bh + off);
                bf[nt*2][0] = q0; bf[nt*2][1] = q1;
                bf[nt*2+1][0] = q2; bf[nt*2+1][1] = q3;
            }
#pragma unroll
            for (int mi = 0; mi < 2; ++mi)
#pragma unroll
                for (int ni = 0; ni < 8; ++ni)
                    mma_bf16(acc[mi][ni], ahi_f[mi], bf[ni]);
#pragma unroll
            for (int mi = 0; mi < 2; ++mi)
#pragma unroll
                for (int ni = 0; ni < 8; ++ni)
                    mma_bf16(acc[mi][ni], alo_f[mi], bf[ni]);
#pragma unroll
            for (int nt = 0; nt < 4; ++nt) {
                int r = b_r + nt * 16;
                uint32_t off = swz(r, kk * 2 + b_h);
                uint32_t q0, q1, q2, q3;
                ldsm_x4(q0, q1, q2, q3, Bl + off);
                bf[nt*2][0] = q0; bf[nt*2][1] = q1;
                bf[nt*2+1][0] = q2; bf[nt*2+1][1] = q3;
            }
#pragma unroll
            for (int mi = 0; mi < 2; ++mi)
#pragma unroll
                for (int ni = 0; ni < 8; ++ni)
                    mma_bf16(acc[mi][ni], ahi_f[mi], bf[ni]);
        }
        __syncthreads();
    }

    const int grp = lane >> 2, qid = lane & 3;
#pragma unroll
    for (int mi = 0; mi < 2; ++mi) {
        const int row0 = m0 + wm + mi * 16 + grp;
#pragma unroll
        for (int ni = 0; ni < 8; ++ni) {
            const int col = n0 + wn + ni * 8 + qid * 2;
            float2 b2 = *(const float2*)(bias + col);
            float2 u, v;
            u.x = (acc[mi][ni][0] + b2.x) * alpha;
            u.y = (acc[mi][ni][1] + b2.y) * alpha;
            v.x = (acc[mi][ni][2] + b2.x) * alpha;
            v.y = (acc[mi][ni][3] + b2.y) * alpha;
            if (relu) {
                u.x = fmaxf(u.x, 0.f); u.y = fmaxf(u.y, 0.f);
                v.x = fmaxf(v.x, 0.f); v.y = fmaxf(v.y, 0.f);
            }
            if (outmode == 0) {
                *(float2*)(C + (size_t)row0 * N + col) = u;
                *(float2*)(C + (size_t)(row0 + 8) * N + col) = v;
            } else {
                uint32_t hi, lo;
                pack_split(u.x, u.y, hi, lo);
                *(uint32_t*)(Chi + (size_t)row0 * N + col) = hi;
                *(uint32_t*)(Clo + (size_t)row0 * N + col) = lo;
                pack_split(v.x, v.y, hi, lo);
                *(uint32_t*)(Chi + (size_t)(row0 + 8) * N + col) = hi;
                *(uint32_t*)(Clo + (size_t)(row0 + 8) * N + col) = lo;
            }
        }
    }
#undef LOAD_CHUNK
}

// ---------------------------------------------------------------------------
// MMA flash attention: 4 warps, 64 q-rows per block, one (b,h) per block.
// S = (Qhi+Qlo)(Khi+Klo)^T  and  O = (Phi+Plo)(Vhi+Vlo), 3-pass each.
// Q pre-scaled by DH^-0.5 (folded into Q projection). Writes O as bf16 hi/lo.
// ---------------------------------------------------------------------------
__global__ __launch_bounds__(128) void attn_mma_kernel(
    const __nv_bfloat16* __restrict__ Qhi, const __nv_bfloat16* __restrict__ Qlo,
    const __nv_bfloat16* __restrict__ Khi, const __nv_bfloat16* __restrict__ Klo,
    const __nv_bfloat16* __restrict__ Vhi, const __nv_bfloat16* __restrict__ Vlo,
    const float* __restrict__ mask,
    __nv_bfloat16* __restrict__ Ohi, __nv_bfloat16* __restrict__ Olo)
{
    extern __shared__ char sm[];
    const uint32_t sb = smem_u32(sm);
    const uint32_t Qh = sb,          Ql = sb + 8192;
    const uint32_t Kh = sb + 16384,  Kl = sb + 24576;
    const uint32_t Vh = sb + 32768,  Vl = sb + 40960;
    float* msk = (float*)(sm + 49152);

    const int tid = threadIdx.x, wid = tid >> 5, lane = tid & 31;
    const int b = blockIdx.z, h = blockIdx.y, q0 = blockIdx.x * 64;
    const int g = lane >> 2, qd = lane & 3;

    // Load Q hi/lo tiles: 2 tiles x 512 chunks / 128 threads = 8 each
    for (int i = tid; i < 1024; i += 128) {
        int t = i >> 9;
        int w = i & 511;
        int r = w >> 3, c = w & 7;
        const __nv_bfloat16* src = (t ? Qlo : Qhi)
            + (size_t)(b * SEQ + q0 + r) * DMODEL + h * DHEAD + c * 8;
        cp_async16((t ? Ql : Qh) + swz128(r, c), src);
    }
    CP_COMMIT();

    float m_i[2] = {-INFINITY, -INFINITY}, l_i[2] = {0.f, 0.f};
    float oacc[8][4];
#pragma unroll
    for (int ni = 0; ni < 8; ++ni)
#pragma unroll
        for (int r = 0; r < 4; ++r) oacc[ni][r] = 0.f;

    const int a_r = wid * 16 + (lane & 15);
    const int a_c = lane >> 4;
    const int b_r = (lane & 7) + ((lane >> 4) << 3);
    const int b_c = (lane >> 3) & 1;
    const int v_ro = ((lane >> 3) & 1) * 8 + (lane & 7);
    const int v_co = lane >> 4;

    for (int kt = 0; kt < SEQ; kt += 64) {
        // load K,V hi/lo tiles: 4 x 512 chunks / 128 = 16 each
        for (int i = tid; i < 2048; i += 128) {
            int t = i >> 9;
            int w = i & 511;
            int r = w >> 3, c = w & 7;
            const __nv_bfloat16* src =
                ((t == 0) ? Khi : (t == 1) ? Klo : (t == 2) ? Vhi : Vlo)
                + (size_t)(b * SEQ + kt + r) * DMODEL + h * DHEAD + c * 8;
            uint32_t dstb = (t == 0) ? Kh : (t == 1) ? Kl : (t == 2) ? Vh : Vl;
            cp_async16(dstb + swz128(r, c), src);
        }
        CP_COMMIT();
        if (tid < 64) msk[tid] = (1.0f - mask[b * SEQ + kt + tid]) * NEG_INF_F;
        asm volatile("cp.async.wait_group 0;" ::: "memory");
        __syncthreads();

        // ---- S = Q K^T (3-pass) ----
        float sacc[8][4];
#pragma unroll
        for (int ni = 0; ni < 8; ++ni)
#pragma unroll
            for (int r = 0; r < 4; ++r) sacc[ni][r] = 0.f;

#pragma unroll
        for (int kk = 0; kk < 4; ++kk) {
            uint32_t qh[4], ql[4];
            uint32_t offA = swz128(a_r, kk * 2 + a_c);
            ldsm_x4(qh[0], qh[1], qh[2], qh[3], Qh + offA);
            ldsm_x4(ql[0], ql[1], ql[2], ql[3], Ql + offA);
            uint32_t bh[8][2], bl[8][2];
#pragma unroll
            for (int nt = 0; nt < 4; ++nt) {
                uint32_t off = swz128(b_r + nt * 16, kk * 2 + b_c);
                uint32_t r0, r1, r2, r3;
                ldsm_x4(r0, r1, r2, r3, Kh + off);
                bh[nt*2][0] = r0; bh[nt*2][1] = r1;
                bh[nt*2+1][0] = r2; bh[nt*2+1][1] = r3;
                ldsm_x4(r0, r1, r2, r3, Kl + off);
                bl[nt*2][0] = r0; bl[nt*2][1] = r1;
                bl[nt*2+1][0] = r2; bl[nt*2+1][1] = r3;
            }
#pragma unroll
            for (int ni = 0; ni < 8; ++ni) mma_bf16(sacc[ni], qh, bh[ni]);
#pragma unroll
            for (int ni = 0; ni < 8; ++ni) mma_bf16(sacc[ni], qh, bl[ni]);
#pragma unroll
            for (int ni = 0; ni < 8; ++ni) mma_bf16(sacc[ni], ql, bh[ni]);
        }

        // additive mask
#pragma unroll
        for (int ni = 0; ni < 8; ++ni) {
            float ma = msk[ni * 8 + qd * 2], mb = msk[ni * 8 + qd * 2 + 1];
            sacc[ni][0] += ma; sacc[ni][1] += mb;
            sacc[ni][2] += ma; sacc[ni][3] += mb;
        }

        // ---- streaming softmax: rows g (c0,c1) and g+8 (c2,c3) ----
#pragma unroll
        for (int hf = 0; hf < 2; ++hf) {
            float mx = -INFINITY;
#pragma unroll
            for (int ni = 0; ni < 8; ++ni)
                mx = fmaxf(mx, fmaxf(sacc[ni][hf*2], sacc[ni][hf*2+1]));
            mx = fmaxf(mx, __shfl_xor_sync(0xffffffffu, mx, 1));
            mx = fmaxf(mx, __shfl_xor_sync(0xffffffffu, mx, 2));
            float mnew = fmaxf(m_i[hf], mx);
            float rs = 0.f;
#pragma unroll
            for (int ni = 0; ni < 8; ++ni) {
                float e0 = __expf(sacc[ni][hf*2]   - mnew);
                float e1 = __expf(sacc[ni][hf*2+1] - mnew);
                sacc[ni][hf*2] = e0; sacc[ni][hf*2+1] = e1;
                rs += e0 + e1;
            }
            rs += __shfl_xor_sync(0xffffffffu, rs, 1);
            rs += __shfl_xor_sync(0xffffffffu, rs, 2);
            float sc = __expf(m_i[hf] - mnew);   // 0 on first tile
            l_i[hf] = l_i[hf] * sc + rs;
            m_i[hf] = mnew;
#pragma unroll
            for (int ni = 0; ni < 8; ++ni) {
                oacc[ni][hf*2]   *= sc;
                oacc[ni][hf*2+1] *= sc;
            }
        }

        // ---- O += P V (3-pass); P fragments straight from sacc regs ----
#pragma unroll
        for (int kk = 0; kk < 4; ++kk) {
            uint32_t ph[4], pl[4];
            pack_split(sacc[2*kk][0],   sacc[2*kk][1],   ph[0], pl[0]);
            pack_split(sacc[2*kk][2],   sacc[2*kk][3],   ph[1], pl[1]);
            pack_split(sacc[2*kk+1][0], sacc[2*kk+1][1], ph[2], pl[2]);
            pack_split(sacc[2*kk+1][2], sacc[2*kk+1][3], ph[3], pl[3]);
            uint32_t vh[8][2], vl[8][2];
#pragma unroll
            for (int nt = 0; nt < 4; ++nt) {
                uint32_t off = swz128(kk * 16 + v_ro, nt * 2 + v_co);
                uint32_t r0, r1, r2, r3;
                ldsm_x4_t(r0, r1, r2, r3, Vh + off);
                vh[nt*2][0] = r0; vh[nt*2][1] = r1;
                vh[nt*2+1][0] = r2; vh[nt*2+1][1] = r3;
                ldsm_x4_t(r0, r1, r2, r3, Vl + off);
                vl[nt*2][0] = r0; vl[nt*2][1] = r1;
                vl[nt*2+1][0] = r2; vl[nt*2+1][1] = r3;
            }
#pragma unroll
            for (int ni = 0; ni < 8; ++ni) mma_bf16(oacc[ni], ph, vh[ni]);
#pragma unroll
            for (int ni = 0; ni < 8; ++ni) mma_bf16(oacc[ni], ph, vl[ni]);
#pragma unroll
            for (int ni = 0; ni < 8; ++ni) mma_bf16(oacc[ni], pl, vh[ni]);
        }
        __syncthreads();   // protect smem before next tile's cp.async
    }

    // ---- O /= l; write bf16 hi/lo ----
#pragma unroll
    for (int hf = 0; hf < 2; ++hf) {
        float inv = 1.0f / l_i[hf];
        int row = q0 + wid * 16 + g + hf * 8;
#pragma unroll
        for (int ni = 0; ni < 8; ++ni) {
            float x0 = oacc[ni][hf*2] * inv, x1 = oacc[ni][hf*2+1] * inv;
            uint32_t hi, lo;
            pack_split(x0, x1, hi, lo);
            size_t off = (size_t)(b * SEQ + row) * DMODEL + h * DHEAD + ni * 8 + qd * 2;
            *(uint32_t*)(Ohi + off) = hi;
            *(uint32_t*)(Olo + off) = lo;
        }
    }
}

// ---------------------------------------------------------------------------
// Fused residual + LayerNorm; writes fp32 x and bf16 hi/lo split of x.
// ---------------------------------------------------------------------------
__global__ __launch_bounds__(256) void add_ln_kernel(
    const float* __restrict__ x, const float* __restrict__ y,
    const float* __restrict__ g, const float* __restrict__ beta,
    float* __restrict__ out,
    __nv_bfloat16* __restrict__ ohi, __nv_bfloat16* __restrict__ olo)
{
    __shared__ float red[8];
    __shared__ float sbroadcast;

    const int row = blockIdx.x;
    const int tid = threadIdx.x;
    const int lane = tid & 31, wid = tid >> 5;
    const size_t base = (size_t)row * DMODEL + tid * 4;

    float4 xv = *(const float4*)(x + base);
    float4 yv = *(const float4*)(y + base);
    float4 v;
    v.x = xv.x + yv.x; v.y = xv.y + yv.y; v.z = xv.z + yv.z; v.w = xv.w + yv.w;

    float s = v.x + v.y + v.z + v.w;
#pragma unroll
    for (int o = 16; o > 0; o >>= 1) s += __shfl_xor_sync(0xffffffffu, s, o);
    if (lane == 0) red[wid] = s;
    __syncthreads();
    if (tid == 0) {
        float t = 0.0f;
#pragma unroll
        for (int w = 0; w < 8; ++w) t += red[w];
        sbroadcast = t * (1.0f / DMODEL);
    }
    __syncthreads();
    const float mean = sbroadcast;

    float dx0 = v.x - mean, dx1 = v.y - mean, dx2 = v.z - mean, dx3 = v.w - mean;
    float s2 = dx0 * dx0 + dx1 * dx1 + dx2 * dx2 + dx3 * dx3;
#pragma unroll
    for (int o = 16; o > 0; o >>= 1) s2 += __shfl_xor_sync(0xffffffffu, s2, o);
    __syncthreads();
    if (lane == 0) red[wid] = s2;
    __syncthreads();
    if (tid == 0) {
        float t = 0.0f;
#pragma unroll
        for (int w = 0; w < 8; ++w) t += red[w];
        sbroadcast = t * (1.0f / DMODEL);
    }
    __syncthreads();
    const float rstd = rsqrtf(sbroadcast + 1e-5f);

    float4 gv = *(const float4*)(g + tid * 4);
    float4 bv = *(const float4*)(beta + tid * 4);
    float4 o4;
    o4.x = dx0 * rstd * gv.x + bv.x;
    o4.y = dx1 * rstd * gv.y + bv.y;
    o4.z = dx2 * rstd * gv.z + bv.z;
    o4.w = dx3 * rstd * gv.w + bv.w;
    *(float4*)(out + base) = o4;

    uint32_t h0, l0, h1, l1;
    pack_split(o4.x, o4.y, h0, l0);
    pack_split(o4.z, o4.w, h1, l1);
    *(uint32_t*)(ohi + base)     = h0;
    *(uint32_t*)(ohi + base + 2) = h1;
    *(uint32_t*)(olo + base)     = l0;
    *(uint32_t*)(olo + base + 2) = l1;
}

// ---------------------------------------------------------------------------
// Launch
// ---------------------------------------------------------------------------
extern "C" void kernel_launch(void* const* d_in, const int* in_sizes, int n_in,
                              void* d_out, int out_size)
{
    (void)in_sizes; (void)n_in; (void)out_size;

    const float* x    = (const float*)d_in[0];
    const float* mask = (const float*)d_in[1];
    const float* Wq   = (const float*)d_in[2];
    const float* bq   = (const float*)d_in[3];
    const float* Wk   = (const float*)d_in[4];
    const float* bk   = (const float*)d_in[5];
    const float* Wv   = (const float*)d_in[6];
    const float* bv   = (const float*)d_in[7];
    const float* Wo   = (const float*)d_in[8];
    const float* bo   = (const float*)d_in[9];
    const float* W1   = (const float*)d_in[10];
    const float* b1   = (const float*)d_in[11];
    const float* W2   = (const float*)d_in[12];
    const float* b2   = (const float*)d_in[13];
    const float* lng  = (const float*)d_in[14];
    const float* lnb  = (const float*)d_in[15];
    float* out = (float*)d_out;

    float *gx, *gy;
    __nv_bfloat16 *xhi, *xlo, *qhi, *qlo, *khi, *klo, *vhi, *vlo,
                  *ohi, *olo, *hhi, *hlo, *whi, *wlo;
    cudaGetSymbolAddress((void**)&gx,  g_x);
    cudaGetSymbolAddress((void**)&gy,  g_y);
    cudaGetSymbolAddress((void**)&xhi, g_xhi);
    cudaGetSymbolAddress((void**)&xlo, g_xlo);
    cudaGetSymbolAddress((void**)&qhi, g_qhi);
    cudaGetSymbolAddress((void**)&qlo, g_qlo);
    cudaGetSymbolAddress((void**)&khi, g_khi);
    cudaGetSymbolAddress((void**)&klo, g_klo);
    cudaGetSymbolAddress((void**)&vhi, g_vhi);
    cudaGetSymbolAddress((void**)&vlo, g_vlo);
    cudaGetSymbolAddress((void**)&ohi, g_ohi);
    cudaGetSymbolAddress((void**)&olo, g_olo);
    cudaGetSymbolAddress((void**)&hhi, g_hhi);
    cudaGetSymbolAddress((void**)&hlo, g_hlo);
    cudaGetSymbolAddress((void**)&whi, g_whi);
    cudaGetSymbolAddress((void**)&wlo, g_wlo);

    static int attr_set = 0;
    if (!attr_set) {
        cudaFuncSetAttribute(mma_gemm_kernel,
                             cudaFuncAttributeMaxDynamicSharedMemorySize, GSMEM);
        cudaFuncSetAttribute(attn_mma_kernel,
                             cudaFuncAttributeMaxDynamicSharedMemorySize, ATTN_SMEM);
        attr_set = 1;
    }

    posenc_kernel<<<(SEQ * DMODEL + 255) / 256, 256>>>(x, gx);
    split_act_kernel<<<(MROWS * DMODEL / 4 + 255) / 256, 256>>>(gx, xhi, xlo, MROWS * DMODEL / 4);

    const float qscale = 0.125f;  // DH^-0.5
    dim3 gProj(DMODEL / 256, MROWS / 128);   // (4, 32)
    dim3 gFF1(DFF / 256, MROWS / 128);       // (16, 32)
    dim3 gAttn(SEQ / 64, NHEAD, BATCH);
    dim3 tT(32, 8);

    for (int l = 0; l < NLAYER; ++l) {
        const float* wq = Wq + (size_t)l * DMODEL * DMODEL;
        const float* wk = Wk + (size_t)l * DMODEL * DMODEL;
        const float* wv = Wv + (size_t)l * DMODEL * DMODEL;
        const float* wo = Wo + (size_t)l * DMODEL * DMODEL;

        split_wT_kernel<<<dim3(DMODEL/32, DMODEL/32), tT>>>(wq, whi, wlo, DMODEL, DMODEL);
        mma_gemm_kernel<<<gProj, 512, GSMEM>>>(xhi, xlo, whi, wlo,
            bq + (size_t)l * DMODEL, nullptr, qhi, qlo,
            MROWS, DMODEL, DMODEL, qscale, 0, 1);

        split_wT_kernel<<<dim3(DMODEL/32, DMODEL/32), tT>>>(wk, whi, wlo, DMODEL, DMODEL);
        mma_gemm_kernel<<<gProj, 512, GSMEM>>>(xhi, xlo, whi, wlo,
            bk + (size_t)l * DMODEL, nullptr, khi, klo,
            MROWS, DMODEL, DMODEL, 1.0f, 0, 1);

        split_wT_kernel<<<dim3(DMODEL/32, DMODEL/32), tT>>>(wv, whi, wlo, DMODEL, DMODEL);
        mma_gemm_kernel<<<gProj, 512, GSMEM>>>(xhi, xlo, whi, wlo,
            bv + (size_t)l * DMODEL, nullptr, vhi, vlo,
            MROWS, DMODEL, DMODEL, 1.0f, 0, 1);

        attn_mma_kernel<<<gAttn, 128, ATTN_SMEM>>>(qhi, qlo, khi, klo, vhi, vlo,
                                                   mask, ohi, olo);

        split_wT_kernel<<<dim3(DMODEL/32, DMODEL/32), tT>>>(wo, whi, wlo, DMODEL, DMODEL);
        mma_gemm_kernel<<<gProj, 512, GSMEM>>>(ohi, olo, whi, wlo,
            bo + (size_t)l * DMODEL, gy, nullptr, nullptr,
            MROWS, DMODEL, DMODEL, 1.0f, 0, 0);

        add_ln_kernel<<<MROWS, 256>>>(gx, gy,
            lng + (size_t)(2 * l) * DMODEL, lnb + (size_t)(2 * l) * DMODEL,
            gx, xhi, xlo);

        split_wT_kernel<<<dim3(DFF/32, DMODEL/32), tT>>>(W1 + (size_t)l * DMODEL * DFF,
                                                         whi, wlo, DMODEL, DFF);
        mma_gemm_kernel<<<gFF1, 512, GSMEM>>>(xhi, xlo, whi, wlo,
            b1 + (size_t)l * DFF, nullptr, hhi, hlo,
            MROWS, DFF, DMODEL, 1.0f, 1, 1);

        split_wT_kernel<<<dim3(DMODEL/32, DFF/32), tT>>>(W2 + (size_t)l * DFF * DMODEL,
                                                         whi, wlo, DFF, DMODEL);
        mma_gemm_kernel<<<gProj, 512, GSMEM>>>(hhi, hlo, whi, wlo,
            b2 + (size_t)l * DMODEL, gy, nullptr, nullptr,
            MROWS, DMODEL, DFF, 1.0f, 0, 0);

        add_ln_kernel<<<MROWS, 256>>>(gx, gy,
            lng + (size_t)(2 * l + 1) * DMODEL, lnb + (size_t)(2 * l + 1) * DMODEL,
            gx, xhi, xlo);
    }

    cudaMemcpyAsync(out, gx, (size_t)MROWS * DMODEL * sizeof(float),
                    cudaMemcpyDeviceToDevice);
}

// round 6
// speedup vs baseline: 2.9732x; 1.0168x over previous
#include <cuda_runtime.h>
#include <cuda_bf16.h>
#include <math.h>
#include <stdint.h>

// Problem constants
#define NLAYER 6
#define NHEAD  16
#define DMODEL 1024
#define DHEAD  64
#define DFF    4096
#define BATCH  4
#define SEQ    1024
#define MROWS  (BATCH*SEQ)
#define NEG_INF_F (-100000000.0f)

// ---------------------------------------------------------------------------
// Scratch (static device globals; no allocation anywhere)
// ---------------------------------------------------------------------------
__device__ float g_x[MROWS*DMODEL];
__device__ float g_y[MROWS*DMODEL];
__device__ __nv_bfloat16 g_xhi[MROWS*DMODEL], g_xlo[MROWS*DMODEL];
__device__ __nv_bfloat16 g_qhi[MROWS*DMODEL], g_qlo[MROWS*DMODEL];
__device__ __nv_bfloat16 g_khi[MROWS*DMODEL], g_klo[MROWS*DMODEL];
__device__ __nv_bfloat16 g_vhi[MROWS*DMODEL], g_vlo[MROWS*DMODEL];
__device__ __nv_bfloat16 g_ohi[MROWS*DMODEL], g_olo[MROWS*DMODEL];
__device__ __nv_bfloat16 g_hhi[MROWS*DFF],    g_hlo[MROWS*DFF];
// per-role weight split buffers (so stream-2 splits never alias an in-flight read)
__device__ __nv_bfloat16 g_wqkv_hi[3*DMODEL*DMODEL], g_wqkv_lo[3*DMODEL*DMODEL];
__device__ __nv_bfloat16 g_wo_hi[DMODEL*DMODEL],     g_wo_lo[DMODEL*DMODEL];
__device__ __nv_bfloat16 g_w1_hi[DMODEL*DFF],        g_w1_lo[DMODEL*DFF];
__device__ __nv_bfloat16 g_w2_hi[DFF*DMODEL],        g_w2_lo[DFF*DMODEL];

// ---------------------------------------------------------------------------
// PTX helpers (non-arch-specific: cp.async sm_80, ldmatrix sm_75, mma sm_80)
// ---------------------------------------------------------------------------
__device__ __forceinline__ uint32_t smem_u32(const void* p) {
    uint32_t a;
    asm("{ .reg .u64 t; cvta.to.shared.u64 t, %1; cvt.u32.u64 %0, t; }" : "=r"(a) : "l"(p));
    return a;
}
__device__ __forceinline__ void cp_async16(uint32_t dst, const void* src) {
    asm volatile("cp.async.cg.shared.global [%0], [%1], 16;" :: "r"(dst), "l"(src) : "memory");
}
#define CP_COMMIT() asm volatile("cp.async.commit_group;" ::: "memory")

__device__ __forceinline__ void ldsm_x4(uint32_t& r0, uint32_t& r1, uint32_t& r2,
                                        uint32_t& r3, uint32_t addr) {
    asm volatile("ldmatrix.sync.aligned.m8n8.x4.shared.b16 {%0,%1,%2,%3}, [%4];"
                 : "=r"(r0), "=r"(r1), "=r"(r2), "=r"(r3) : "r"(addr));
}
__device__ __forceinline__ void ldsm_x4_t(uint32_t& r0, uint32_t& r1, uint32_t& r2,
                                          uint32_t& r3, uint32_t addr) {
    asm volatile("ldmatrix.sync.aligned.m8n8.x4.trans.shared.b16 {%0,%1,%2,%3}, [%4];"
                 : "=r"(r0), "=r"(r1), "=r"(r2), "=r"(r3) : "r"(addr));
}
__device__ __forceinline__ void mma_bf16(float* c, const uint32_t* a, const uint32_t* b) {
    asm volatile(
        "mma.sync.aligned.m16n8k16.row.col.f32.bf16.bf16.f32 "
        "{%0,%1,%2,%3}, {%4,%5,%6,%7}, {%8,%9}, {%0,%1,%2,%3};"
        : "+f"(c[0]), "+f"(c[1]), "+f"(c[2]), "+f"(c[3])
        : "r"(a[0]), "r"(a[1]), "r"(a[2]), "r"(a[3]), "r"(b[0]), "r"(b[1]));
}
__device__ __forceinline__ void pack_split(float x, float y, uint32_t& hi, uint32_t& lo) {
    __nv_bfloat16 hx = __float2bfloat16(x), hy = __float2bfloat16(y);
    __nv_bfloat162 H; H.x = hx; H.y = hy;
    __nv_bfloat162 L;
    L.x = __float2bfloat16(x - __bfloat162float(hx));
    L.y = __float2bfloat16(y - __bfloat162float(hy));
    hi = *(uint32_t*)&H; lo = *(uint32_t*)&L;
}

// Swizzle for 64B-row tiles (GEMM: 32 bf16/row)
__device__ __forceinline__ uint32_t swz(int row, int c) {
    return (uint32_t)(((row >> 1) << 7) |
                      ((((((row & 1) << 2) | c)) ^ ((row >> 1) & 7)) << 4));
}
// Swizzle for 128B-row tiles (attention: 64 bf16/row)
__device__ __forceinline__ uint32_t swz128(int row, int c) {
    return (uint32_t)((row << 7) | (((c ^ (row & 7))) << 4));
}

// GEMM smem geometry: 128x256 tile, BK=32, TRIPLE buffered
#define A_TILE 8192
#define B_TILE 16384
#define STAGEB (2*A_TILE + 2*B_TILE)   // 49152
#define GSMEM  (3*STAGEB)              // 147456

#define ATTN_SMEM (6*8192 + 256)

// ---------------------------------------------------------------------------
// Positional encoding (fp64) + fused bf16 split of the result
// ---------------------------------------------------------------------------
__global__ void posenc_kernel(const float* __restrict__ x, float* __restrict__ out,
                              __nv_bfloat16* __restrict__ ohi,
                              __nv_bfloat16* __restrict__ olo)
{
    int idx = blockIdx.x * blockDim.x + threadIdx.x;
    if (idx >= SEQ * DMODEL) return;
    int d = idx & (DMODEL - 1);
    int s = idx >> 10;
    int t = (d < DMODEL/2) ? d : d - DMODEL/2;
    const double log_inc = log(10000.0) / (double)(DMODEL/2 - 1);
    double arg = (double)s * exp(-(double)t * log_inc);
    float sig = (float)((d < DMODEL/2) ? sin(arg) : cos(arg));
#pragma unroll
    for (int b = 0; b < BATCH; ++b) {
        size_t off = (size_t)b * SEQ * DMODEL + idx;
        float v = x[off] + sig;
        out[off] = v;
        __nv_bfloat16 h = __float2bfloat16(v);
        ohi[off] = h;
        olo[off] = __float2bfloat16(v - __bfloat162float(h));
    }
}

// ---------------------------------------------------------------------------
// W [K,N] fp32 -> transposed bf16 split: hiT, loT [N,K]
// ---------------------------------------------------------------------------
__global__ __launch_bounds__(256) void split_wT_kernel(
    const float* __restrict__ W, __nv_bfloat16* __restrict__ hiT,
    __nv_bfloat16* __restrict__ loT, int K, int N)
{
    __shared__ float t[32][33];
    int nx = blockIdx.x * 32;
    int ky = blockIdx.y * 32;
    int tx = threadIdx.x, ty = threadIdx.y;   // (32, 8)
#pragma unroll
    for (int i = 0; i < 4; ++i)
        t[ty + 8*i][tx] = W[(size_t)(ky + ty + 8*i) * N + nx + tx];
    __syncthreads();
#pragma unroll
    for (int i = 0; i < 4; ++i) {
        float v = t[tx][ty + 8*i];
        __nv_bfloat16 h = __float2bfloat16(v);
        size_t o = (size_t)(nx + ty + 8*i) * K + ky + tx;
        hiT[o] = h;
        loT[o] = __float2bfloat16(v - __bfloat162float(h));
    }
}

// --- shared chunk loader (A 128 rows, B 256 rows, both [*,K] bf16, BK=32) ---
#define LOAD_CHUNK(k0, buf)                                                     \
    {                                                                           \
        _Pragma("unroll")                                                       \
        for (int i = 0; i < 6; ++i) {                                           \
            int t = tid + i * 512;                                              \
            const __nv_bfloat16* src;                                           \
            int row, c, gr;                                                     \
            uint32_t toff;                                                      \
            if (t < 1024) {                                                     \
                int tile = t >> 9;                                              \
                int w = t & 511;                                                \
                row = w >> 2; c = w & 3;                                        \
                src = tile ? Alo : Ahi;                                         \
                toff = tile ? A_TILE : 0u;                                      \
                gr = m0 + row;                                                  \
            } else {                                                            \
                int u = t - 1024;                                               \
                int tile = u >> 10;                                             \
                int w = u & 1023;                                               \
                row = w >> 2; c = w & 3;                                        \
                src = tile ? Blo : Bhi;                                         \
                toff = tile ? (2u*A_TILE + B_TILE) : (2u*A_TILE);               \
                gr = n0 + row;                                                  \
            }                                                                   \
            cp_async16((buf) + toff + swz(row, c),                              \
                       src + (size_t)gr * K + (k0) + c * 8);                    \
        }                                                                       \
        CP_COMMIT();                                                            \
    }

// --- shared MMA body (3-pass, pass-major) ---
#define MMA_BODY(buf)                                                            \
    {                                                                            \
        const uint32_t Ah = buf;                                                 \
        const uint32_t Al = buf + A_TILE;                                        \
        const uint32_t Bh = buf + 2 * A_TILE;                                    \
        const uint32_t Bl = buf + 2 * A_TILE + B_TILE;                           \
        _Pragma("unroll")                                                        \
        for (int kk = 0; kk < 2; ++kk) {                                         \
            uint32_t ahi_f[2][4], alo_f[2][4];                                   \
            _Pragma("unroll")                                                    \
            for (int mi = 0; mi < 2; ++mi) {                                     \
                int r = a_r + mi * 16;                                           \
                uint32_t off = swz(r, kk * 2 + a_h);                             \
                ldsm_x4(ahi_f[mi][0], ahi_f[mi][1], ahi_f[mi][2], ahi_f[mi][3], Ah + off); \
                ldsm_x4(alo_f[mi][0], alo_f[mi][1], alo_f[mi][2], alo_f[mi][3], Al + off); \
            }                                                                    \
            uint32_t bf[8][2];                                                   \
            _Pragma("unroll")                                                    \
            for (int nt = 0; nt < 4; ++nt) {                                     \
                int r = b_r + nt * 16;                                           \
                uint32_t off = swz(r, kk * 2 + b_h);                             \
                uint32_t q0, q1, q2, q3;                                         \
                ldsm_x4(q0, q1, q2, q3, Bh + off);                               \
                bf[nt*2][0] = q0; bf[nt*2][1] = q1;                              \
                bf[nt*2+1][0] = q2; bf[nt*2+1][1] = q3;                          \
            }                                                                    \
            _Pragma("unroll")                                                    \
            for (int mi = 0; mi < 2; ++mi)                                       \
                _Pragma("unroll")                                                \
                for (int ni = 0; ni < 8; ++ni)                                   \
                    mma_bf16(acc[mi][ni], ahi_f[mi], bf[ni]);                    \
            _Pragma("unroll")                                                    \
            for (int mi = 0; mi < 2; ++mi)                                       \
                _Pragma("unroll")                                                \
                for (int ni = 0; ni < 8; ++ni)                                   \
                    mma_bf16(acc[mi][ni], alo_f[mi], bf[ni]);                    \
            _Pragma("unroll")                                                    \
            for (int nt = 0; nt < 4; ++nt) {                                     \
                int r = b_r + nt * 16;                                           \
                uint32_t off = swz(r, kk * 2 + b_h);                             \
                uint32_t q0, q1, q2, q3;                                         \
                ldsm_x4(q0, q1, q2, q3, Bl + off);                               \
                bf[nt*2][0] = q0; bf[nt*2][1] = q1;                              \
                bf[nt*2+1][0] = q2; bf[nt*2+1][1] = q3;                          \
            }                                                                    \
            _Pragma("unroll")                                                    \
            for (int mi = 0; mi < 2; ++mi)                                       \
                _Pragma("unroll")                                                \
                for (int ni = 0; ni < 8; ++ni)                                   \
                    mma_bf16(acc[mi][ni], ahi_f[mi], bf[ni]);                    \
        }                                                                        \
    }

// --- shared 3-stage K-loop ---
#define K_LOOP()                                                                 \
    LOAD_CHUNK(0, sb);                                                           \
    LOAD_CHUNK(32, sb + STAGEB);                                                 \
    for (int ch = 0; ch < nch; ++ch) {                                           \
        const uint32_t buf = sb + (uint32_t)(ch % 3) * STAGEB;                   \
        if (ch + 2 < nch) {                                                      \
            LOAD_CHUNK((ch + 2) * 32, sb + (uint32_t)((ch + 2) % 3) * STAGEB);   \
            asm volatile("cp.async.wait_group 2;" ::: "memory");                 \
        } else if (ch + 1 < nch) {                                               \
            asm volatile("cp.async.wait_group 1;" ::: "memory");                 \
        } else {                                                                 \
            asm volatile("cp.async.wait_group 0;" ::: "memory");                 \
        }                                                                        \
        __syncthreads();                                                         \
        MMA_BODY(buf)                                                            \
        __syncthreads();                                                         \
    }

// ---------------------------------------------------------------------------
// General HMMA bf16-split GEMM (Wo / FF1 / FF2).
// outmode 0: fp32 C. outmode 1: bf16 split (Chi, Clo).
// ---------------------------------------------------------------------------
__global__ __launch_bounds__(512, 1) void mma_gemm_kernel(
    const __nv_bfloat16* __restrict__ Ahi, const __nv_bfloat16* __restrict__ Alo,
    const __nv_bfloat16* __restrict__ Bhi, const __nv_bfloat16* __restrict__ Blo,
    const float* __restrict__ bias, float* __restrict__ C,
    __nv_bfloat16* __restrict__ Chi, __nv_bfloat16* __restrict__ Clo,
    int M, int N, int K, float alpha, int relu, int outmode)
{
    extern __shared__ char smem[];
    const uint32_t sb = smem_u32(smem);
    const int tid = threadIdx.x;
    const int wid = tid >> 5, lane = tid & 31;
    const int m0 = blockIdx.y * 128, n0 = blockIdx.x * 256;
    const int wm = (wid & 3) * 32;
    const int wn = (wid >> 2) * 64;

    float acc[2][8][4];
#pragma unroll
    for (int mi = 0; mi < 2; ++mi)
#pragma unroll
        for (int ni = 0; ni < 8; ++ni)
#pragma unroll
            for (int r = 0; r < 4; ++r) acc[mi][ni][r] = 0.0f;

    const int nch = K >> 5;
    const int a_r = wm + (lane & 15);
    const int a_h = lane >> 4;
    const int b_r = wn + ((lane >> 4) << 3) + (lane & 7);
    const int b_h = (lane >> 3) & 1;

    K_LOOP()

    const int grp = lane >> 2, qid = lane & 3;
#pragma unroll
    for (int mi = 0; mi < 2; ++mi) {
        const int row0 = m0 + wm + mi * 16 + grp;
#pragma unroll
        for (int ni = 0; ni < 8; ++ni) {
            const int col = n0 + wn + ni * 8 + qid * 2;
            float2 b2 = *(const float2*)(bias + col);
            float2 u, v;
            u.x = (acc[mi][ni][0] + b2.x) * alpha;
            u.y = (acc[mi][ni][1] + b2.y) * alpha;
            v.x = (acc[mi][ni][2] + b2.x) * alpha;
            v.y = (acc[mi][ni][3] + b2.y) * alpha;
            if (relu) {
                u.x = fmaxf(u.x, 0.f); u.y = fmaxf(u.y, 0.f);
                v.x = fmaxf(v.x, 0.f); v.y = fmaxf(v.y, 0.f);
            }
            if (outmode == 0) {
                *(float2*)(C + (size_t)row0 * N + col) = u;
                *(float2*)(C + (size_t)(row0 + 8) * N + col) = v;
            } else {
                uint32_t hi, lo;
                pack_split(u.x, u.y, hi, lo);
                *(uint32_t*)(Chi + (size_t)row0 * N + col) = hi;
                *(uint32_t*)(Clo + (size_t)row0 * N + col) = lo;
                pack_split(v.x, v.y, hi, lo);
                *(uint32_t*)(Chi + (size_t)(row0 + 8) * N + col) = hi;
                *(uint32_t*)(Clo + (size_t)(row0 + 8) * N + col) = lo;
            }
        }
    }
}

// ---------------------------------------------------------------------------
// Batched QKV GEMM: B packed [3072, 1024] (wq|wk|wv). grid (12, 32).
// Per-CTA matrix id selects bias / alpha / output buffers.
// ---------------------------------------------------------------------------
__global__ __launch_bounds__(512, 1) void mma_gemm_qkv_kernel(
    const __nv_bfloat16* __restrict__ Ahi, const __nv_bfloat16* __restrict__ Alo,
    const __nv_bfloat16* __restrict__ Bhi, const __nv_bfloat16* __restrict__ Blo,
    const float* __restrict__ bq, const float* __restrict__ bk,
    const float* __restrict__ bv,
    __nv_bfloat16* __restrict__ Qhi, __nv_bfloat16* __restrict__ Qlo,
    __nv_bfloat16* __restrict__ Khi, __nv_bfloat16* __restrict__ Klo,
    __nv_bfloat16* __restrict__ Vhi, __nv_bfloat16* __restrict__ Vlo,
    float qscale)
{
    extern __shared__ char smem[];
    const uint32_t sb = smem_u32(smem);
    const int tid = threadIdx.x;
    const int wid = tid >> 5, lane = tid & 31;
    const int m0 = blockIdx.y * 128, n0 = blockIdx.x * 256;
    const int K = DMODEL;
    const int wm = (wid & 3) * 32;
    const int wn = (wid >> 2) * 64;

    float acc[2][8][4];
#pragma unroll
    for (int mi = 0; mi < 2; ++mi)
#pragma unroll
        for (int ni = 0; ni < 8; ++ni)
#pragma unroll
            for (int r = 0; r < 4; ++r) acc[mi][ni][r] = 0.0f;

    const int nch = K >> 5;
    const int a_r = wm + (lane & 15);
    const int a_h = lane >> 4;
    const int b_r = wn + ((lane >> 4) << 3) + (lane & 7);
    const int b_h = (lane >> 3) & 1;

    K_LOOP()

    const int mid = n0 >> 10;
    const float* bsel = (mid == 0) ? bq : (mid == 1) ? bk : bv;
    __nv_bfloat16* hisel = (mid == 0) ? Qhi : (mid == 1) ? Khi : Vhi;
    __nv_bfloat16* losel = (mid == 0) ? Qlo : (mid == 1) ? Klo : Vlo;
    const float asel = (mid == 0) ? qscale : 1.0f;
    const int cb = mid << 10;

    const int grp = lane >> 2, qid = lane & 3;
#pragma unroll
    for (int mi = 0; mi < 2; ++mi) {
        const int row0 = m0 + wm + mi * 16 + grp;
#pragma unroll
        for (int ni = 0; ni < 8; ++ni) {
            const int col = n0 + wn + ni * 8 + qid * 2 - cb;
            float2 b2 = *(const float2*)(bsel + col);
            float2 u, v;
            u.x = (acc[mi][ni][0] + b2.x) * asel;
            u.y = (acc[mi][ni][1] + b2.y) * asel;
            v.x = (acc[mi][ni][2] + b2.x) * asel;
            v.y = (acc[mi][ni][3] + b2.y) * asel;
            uint32_t hi, lo;
            pack_split(u.x, u.y, hi, lo);
            *(uint32_t*)(hisel + (size_t)row0 * DMODEL + col) = hi;
            *(uint32_t*)(losel + (size_t)row0 * DMODEL + col) = lo;
            pack_split(v.x, v.y, hi, lo);
            *(uint32_t*)(hisel + (size_t)(row0 + 8) * DMODEL + col) = hi;
            *(uint32_t*)(losel + (size_t)(row0 + 8) * DMODEL + col) = lo;
        }
    }
}

// ---------------------------------------------------------------------------
// MMA flash attention (unchanged from R5)
// ---------------------------------------------------------------------------
__global__ __launch_bounds__(128) void attn_mma_kernel(
    const __nv_bfloat16* __restrict__ Qhi, const __nv_bfloat16* __restrict__ Qlo,
    const __nv_bfloat16* __restrict__ Khi, const __nv_bfloat16* __restrict__ Klo,
    const __nv_bfloat16* __restrict__ Vhi, const __nv_bfloat16* __restrict__ Vlo,
    const float* __restrict__ mask,
    __nv_bfloat16* __restrict__ Ohi, __nv_bfloat16* __restrict__ Olo)
{
    extern __shared__ char sm[];
    const uint32_t sb = smem_u32(sm);
    const uint32_t Qh = sb,          Ql = sb + 8192;
    const uint32_t Kh = sb + 16384,  Kl = sb + 24576;
    const uint32_t Vh = sb + 32768,  Vl = sb + 40960;
    float* msk = (float*)(sm + 49152);

    const int tid = threadIdx.x, wid = tid >> 5, lane = tid & 31;
    const int b = blockIdx.z, h = blockIdx.y, q0 = blockIdx.x * 64;
    const int g = lane >> 2, qd = lane & 3;

    for (int i = tid; i < 1024; i += 128) {
        int t = i >> 9;
        int w = i & 511;
        int r = w >> 3, c = w & 7;
        const __nv_bfloat16* src = (t ? Qlo : Qhi)
            + (size_t)(b * SEQ + q0 + r) * DMODEL + h * DHEAD + c * 8;
        cp_async16((t ? Ql : Qh) + swz128(r, c), src);
    }
    CP_COMMIT();

    float m_i[2] = {-INFINITY, -INFINITY}, l_i[2] = {0.f, 0.f};
    float oacc[8][4];
#pragma unroll
    for (int ni = 0; ni < 8; ++ni)
#pragma unroll
        for (int r = 0; r < 4; ++r) oacc[ni][r] = 0.f;

    const int a_r = wid * 16 + (lane & 15);
    const int a_c = lane >> 4;
    const int b_r = (lane & 7) + ((lane >> 4) << 3);
    const int b_c = (lane >> 3) & 1;
    const int v_ro = ((lane >> 3) & 1) * 8 + (lane & 7);
    const int v_co = lane >> 4;

    for (int kt = 0; kt < SEQ; kt += 64) {
        for (int i = tid; i < 2048; i += 128) {
            int t = i >> 9;
            int w = i & 511;
            int r = w >> 3, c = w & 7;
            const __nv_bfloat16* src =
                ((t == 0) ? Khi : (t == 1) ? Klo : (t == 2) ? Vhi : Vlo)
                + (size_t)(b * SEQ + kt + r) * DMODEL + h * DHEAD + c * 8;
            uint32_t dstb = (t == 0) ? Kh : (t == 1) ? Kl : (t == 2) ? Vh : Vl;
            cp_async16(dstb + swz128(r, c), src);
        }
        CP_COMMIT();
        if (tid < 64) msk[tid] = (1.0f - mask[b * SEQ + kt + tid]) * NEG_INF_F;
        asm volatile("cp.async.wait_group 0;" ::: "memory");
        __syncthreads();

        float sacc[8][4];
#pragma unroll
        for (int ni = 0; ni < 8; ++ni)
#pragma unroll
            for (int r = 0; r < 4; ++r) sacc[ni][r] = 0.f;

#pragma unroll
        for (int kk = 0; kk < 4; ++kk) {
            uint32_t qh[4], ql[4];
            uint32_t offA = swz128(a_r, kk * 2 + a_c);
            ldsm_x4(qh[0], qh[1], qh[2], qh[3], Qh + offA);
            ldsm_x4(ql[0], ql[1], ql[2], ql[3], Ql + offA);
            uint32_t bh[8][2], bl[8][2];
#pragma unroll
            for (int nt = 0; nt < 4; ++nt) {
                uint32_t off = swz128(b_r + nt * 16, kk * 2 + b_c);
                uint32_t r0, r1, r2, r3;
                ldsm_x4(r0, r1, r2, r3, Kh + off);
                bh[nt*2][0] = r0; bh[nt*2][1] = r1;
                bh[nt*2+1][0] = r2; bh[nt*2+1][1] = r3;
                ldsm_x4(r0, r1, r2, r3, Kl + off);
                bl[nt*2][0] = r0; bl[nt*2][1] = r1;
                bl[nt*2+1][0] = r2; bl[nt*2+1][1] = r3;
            }
#pragma unroll
            for (int ni = 0; ni < 8; ++ni) mma_bf16(sacc[ni], qh, bh[ni]);
#pragma unroll
            for (int ni = 0; ni < 8; ++ni) mma_bf16(sacc[ni], qh, bl[ni]);
#pragma unroll
            for (int ni = 0; ni < 8; ++ni) mma_bf16(sacc[ni], ql, bh[ni]);
        }

#pragma unroll
        for (int ni = 0; ni < 8; ++ni) {
            float ma = msk[ni * 8 + qd * 2], mb = msk[ni * 8 + qd * 2 + 1];
            sacc[ni][0] += ma; sacc[ni][1] += mb;
            sacc[ni][2] += ma; sacc[ni][3] += mb;
        }

#pragma unroll
        for (int hf = 0; hf < 2; ++hf) {
            float mx = -INFINITY;
#pragma unroll
            for (int ni = 0; ni < 8; ++ni)
                mx = fmaxf(mx, fmaxf(sacc[ni][hf*2], sacc[ni][hf*2+1]));
            mx = fmaxf(mx, __shfl_xor_sync(0xffffffffu, mx, 1));
            mx = fmaxf(mx, __shfl_xor_sync(0xffffffffu, mx, 2));
            float mnew = fmaxf(m_i[hf], mx);
            float rs = 0.f;
#pragma unroll
            for (int ni = 0; ni < 8; ++ni) {
                float e0 = __expf(sacc[ni][hf*2]   - mnew);
                float e1 = __expf(sacc[ni][hf*2+1] - mnew);
                sacc[ni][hf*2] = e0; sacc[ni][hf*2+1] = e1;
                rs += e0 + e1;
            }
            rs += __shfl_xor_sync(0xffffffffu, rs, 1);
            rs += __shfl_xor_sync(0xffffffffu, rs, 2);
            float sc = __expf(m_i[hf] - mnew);
            l_i[hf] = l_i[hf] * sc + rs;
            m_i[hf] = mnew;
#pragma unroll
            for (int ni = 0; ni < 8; ++ni) {
                oacc[ni][hf*2]   *= sc;
                oacc[ni][hf*2+1] *= sc;
            }
        }

#pragma unroll
        for (int kk = 0; kk < 4; ++kk) {
            uint32_t ph[4], pl[4];
            pack_split(sacc[2*kk][0],   sacc[2*kk][1],   ph[0], pl[0]);
            pack_split(sacc[2*kk][2],   sacc[2*kk][3],   ph[1], pl[1]);
            pack_split(sacc[2*kk+1][0], sacc[2*kk+1][1], ph[2], pl[2]);
            pack_split(sacc[2*kk+1][2], sacc[2*kk+1][3], ph[3], pl[3]);
            uint32_t vh[8][2], vl[8][2];
#pragma unroll
            for (int nt = 0; nt < 4; ++nt) {
                uint32_t off = swz128(kk * 16 + v_ro, nt * 2 + v_co);
                uint32_t r0, r1, r2, r3;
                ldsm_x4_t(r0, r1, r2, r3, Vh + off);
                vh[nt*2][0] = r0; vh[nt*2][1] = r1;
                vh[nt*2+1][0] = r2; vh[nt*2+1][1] = r3;
                ldsm_x4_t(r0, r1, r2, r3, Vl + off);
                vl[nt*2][0] = r0; vl[nt*2][1] = r1;
                vl[nt*2+1][0] = r2; vl[nt*2+1][1] = r3;
            }
#pragma unroll
            for (int ni = 0; ni < 8; ++ni) mma_bf16(oacc[ni], ph, vh[ni]);
#pragma unroll
            for (int ni = 0; ni < 8; ++ni) mma_bf16(oacc[ni], ph, vl[ni]);
#pragma unroll
            for (int ni = 0; ni < 8; ++ni) mma_bf16(oacc[ni], pl, vh[ni]);
        }
        __syncthreads();
    }

#pragma unroll
    for (int hf = 0; hf < 2; ++hf) {
        float inv = 1.0f / l_i[hf];
        int row = q0 + wid * 16 + g + hf * 8;
#pragma unroll
        for (int ni = 0; ni < 8; ++ni) {
            float x0 = oacc[ni][hf*2] * inv, x1 = oacc[ni][hf*2+1] * inv;
            uint32_t hi, lo;
            pack_split(x0, x1, hi, lo);
            size_t off = (size_t)(b * SEQ + row) * DMODEL + h * DHEAD + ni * 8 + qd * 2;
            *(uint32_t*)(Ohi + off) = hi;
            *(uint32_t*)(Olo + off) = lo;
        }
    }
}

// ---------------------------------------------------------------------------
// Fused residual + LayerNorm; writes fp32 x and bf16 hi/lo split of x.
// ---------------------------------------------------------------------------
__global__ __launch_bounds__(256) void add_ln_kernel(
    const float* __restrict__ x, const float* __restrict__ y,
    const float* __restrict__ g, const float* __restrict__ beta,
    float* __restrict__ out,
    __nv_bfloat16* __restrict__ ohi, __nv_bfloat16* __restrict__ olo)
{
    __shared__ float red[8];
    __shared__ float sbroadcast;

    const int row = blockIdx.x;
    const int tid = threadIdx.x;
    const int lane = tid & 31, wid = tid >> 5;
    const size_t base = (size_t)row * DMODEL + tid * 4;

    float4 xv = *(const float4*)(x + base);
    float4 yv = *(const float4*)(y + base);
    float4 v;
    v.x = xv.x + yv.x; v.y = xv.y + yv.y; v.z = xv.z + yv.z; v.w = xv.w + yv.w;

    float s = v.x + v.y + v.z + v.w;
#pragma unroll
    for (int o = 16; o > 0; o >>= 1) s += __shfl_xor_sync(0xffffffffu, s, o);
    if (lane == 0) red[wid] = s;
    __syncthreads();
    if (tid == 0) {
        float t = 0.0f;
#pragma unroll
        for (int w = 0; w < 8; ++w) t += red[w];
        sbroadcast = t * (1.0f / DMODEL);
    }
    __syncthreads();
    const float mean = sbroadcast;

    float dx0 = v.x - mean, dx1 = v.y - mean, dx2 = v.z - mean, dx3 = v.w - mean;
    float s2 = dx0 * dx0 + dx1 * dx1 + dx2 * dx2 + dx3 * dx3;
#pragma unroll
    for (int o = 16; o > 0; o >>= 1) s2 += __shfl_xor_sync(0xffffffffu, s2, o);
    __syncthreads();
    if (lane == 0) red[wid] = s2;
    __syncthreads();
    if (tid == 0) {
        float t = 0.0f;
#pragma unroll
        for (int w = 0; w < 8; ++w) t += red[w];
        sbroadcast = t * (1.0f / DMODEL);
    }
    __syncthreads();
    const float rstd = rsqrtf(sbroadcast + 1e-5f);

    float4 gv = *(const float4*)(g + tid * 4);
    float4 bv = *(const float4*)(beta + tid * 4);
    float4 o4;
    o4.x = dx0 * rstd * gv.x + bv.x;
    o4.y = dx1 * rstd * gv.y + bv.y;
    o4.z = dx2 * rstd * gv.z + bv.z;
    o4.w = dx3 * rstd * gv.w + bv.w;
    *(float4*)(out + base) = o4;

    uint32_t h0, l0, h1, l1;
    pack_split(o4.x, o4.y, h0, l0);
    pack_split(o4.z, o4.w, h1, l1);
    *(uint32_t*)(ohi + base)     = h0;
    *(uint32_t*)(ohi + base + 2) = h1;
    *(uint32_t*)(olo + base)     = l0;
    *(uint32_t*)(olo + base + 2) = l1;
}

// ---------------------------------------------------------------------------
// Launch (dual-stream: main = stream 0, s2 = weight splits)
// ---------------------------------------------------------------------------
extern "C" void kernel_launch(void* const* d_in, const int* in_sizes, int n_in,
                              void* d_out, int out_size)
{
    (void)in_sizes; (void)n_in; (void)out_size;

    const float* x    = (const float*)d_in[0];
    const float* mask = (const float*)d_in[1];
    const float* Wq   = (const float*)d_in[2];
    const float* bq   = (const float*)d_in[3];
    const float* Wk   = (const float*)d_in[4];
    const float* bk   = (const float*)d_in[5];
    const float* Wv   = (const float*)d_in[6];
    const float* bv   = (const float*)d_in[7];
    const float* Wo   = (const float*)d_in[8];
    const float* bo   = (const float*)d_in[9];
    const float* W1   = (const float*)d_in[10];
    const float* b1   = (const float*)d_in[11];
    const float* W2   = (const float*)d_in[12];
    const float* b2   = (const float*)d_in[13];
    const float* lng  = (const float*)d_in[14];
    const float* lnb  = (const float*)d_in[15];
    float* out = (float*)d_out;

    float *gx, *gy;
    __nv_bfloat16 *xhi, *xlo, *qhi, *qlo, *khi, *klo, *vhi, *vlo,
                  *ohi, *olo, *hhi, *hlo;
    __nv_bfloat16 *wqkvh, *wqkvl, *woh, *wol, *w1h, *w1l, *w2h, *w2l;
    cudaGetSymbolAddress((void**)&gx,  g_x);
    cudaGetSymbolAddress((void**)&gy,  g_y);
    cudaGetSymbolAddress((void**)&xhi, g_xhi);
    cudaGetSymbolAddress((void**)&xlo, g_xlo);
    cudaGetSymbolAddress((void**)&qhi, g_qhi);
    cudaGetSymbolAddress((void**)&qlo, g_qlo);
    cudaGetSymbolAddress((void**)&khi, g_khi);
    cudaGetSymbolAddress((void**)&klo, g_klo);
    cudaGetSymbolAddress((void**)&vhi, g_vhi);
    cudaGetSymbolAddress((void**)&vlo, g_vlo);
    cudaGetSymbolAddress((void**)&ohi, g_ohi);
    cudaGetSymbolAddress((void**)&olo, g_olo);
    cudaGetSymbolAddress((void**)&hhi, g_hhi);
    cudaGetSymbolAddress((void**)&hlo, g_hlo);
    cudaGetSymbolAddress((void**)&wqkvh, g_wqkv_hi);
    cudaGetSymbolAddress((void**)&wqkvl, g_wqkv_lo);
    cudaGetSymbolAddress((void**)&woh, g_wo_hi);
    cudaGetSymbolAddress((void**)&wol, g_wo_lo);
    cudaGetSymbolAddress((void**)&w1h, g_w1_hi);
    cudaGetSymbolAddress((void**)&w1l, g_w1_lo);
    cudaGetSymbolAddress((void**)&w2h, g_w2_hi);
    cudaGetSymbolAddress((void**)&w2l, g_w2_lo);

    static cudaStream_t s2 = nullptr;
    static cudaEvent_t evpool[64];
    static int attr_set = 0;
    if (!attr_set) {
        cudaFuncSetAttribute(mma_gemm_kernel,
                             cudaFuncAttributeMaxDynamicSharedMemorySize, GSMEM);
        cudaFuncSetAttribute(mma_gemm_qkv_kernel,
                             cudaFuncAttributeMaxDynamicSharedMemorySize, GSMEM);
        cudaFuncSetAttribute(attn_mma_kernel,
                             cudaFuncAttributeMaxDynamicSharedMemorySize, ATTN_SMEM);
        cudaStreamCreateWithFlags(&s2, cudaStreamNonBlocking);
        for (int i = 0; i < 64; ++i)
            cudaEventCreateWithFlags(&evpool[i], cudaEventDisableTiming);
        attr_set = 1;
    }
    int evn = 0;
#define EV() (evpool[evn++])

    const float qscale = 0.125f;
    dim3 gQKV(3 * DMODEL / 256, MROWS / 128);  // (12, 32)
    dim3 gProj(DMODEL / 256, MROWS / 128);     // (4, 32)
    dim3 gFF1(DFF / 256, MROWS / 128);         // (16, 32)
    dim3 gAttn(SEQ / 64, NHEAD, BATCH);
    dim3 tT(32, 8);

    // fork s2 from main
    cudaEvent_t eFork = EV();
    cudaEventRecord(eFork, 0);
    cudaStreamWaitEvent(s2, eFork, 0);

    posenc_kernel<<<(SEQ * DMODEL + 255) / 256, 256>>>(x, gx, xhi, xlo);

    cudaEvent_t e_qkv_done = nullptr, e_wo_done = nullptr,
                e_ff1_done = nullptr, e_ff2_done = nullptr;

    for (int l = 0; l < NLAYER; ++l) {
        const float* wq = Wq + (size_t)l * DMODEL * DMODEL;
        const float* wk = Wk + (size_t)l * DMODEL * DMODEL;
        const float* wv = Wv + (size_t)l * DMODEL * DMODEL;
        const float* wo = Wo + (size_t)l * DMODEL * DMODEL;

        // --- stream 2: weight splits for layer l (wait for prior readers) ---
        if (e_qkv_done) cudaStreamWaitEvent(s2, e_qkv_done, 0);
        split_wT_kernel<<<dim3(32,32), tT, 0, s2>>>(wq, wqkvh,               wqkvl,               DMODEL, DMODEL);
        split_wT_kernel<<<dim3(32,32), tT, 0, s2>>>(wk, wqkvh + 1024*1024,   wqkvl + 1024*1024,   DMODEL, DMODEL);
        split_wT_kernel<<<dim3(32,32), tT, 0, s2>>>(wv, wqkvh + 2*1024*1024, wqkvl + 2*1024*1024, DMODEL, DMODEL);
        cudaEvent_t e_sqkv = EV(); cudaEventRecord(e_sqkv, s2);

        if (e_wo_done) cudaStreamWaitEvent(s2, e_wo_done, 0);
        split_wT_kernel<<<dim3(32,32), tT, 0, s2>>>(wo, woh, wol, DMODEL, DMODEL);
        cudaEvent_t e_so = EV(); cudaEventRecord(e_so, s2);

        if (e_ff1_done) cudaStreamWaitEvent(s2, e_ff1_done, 0);
        split_wT_kernel<<<dim3(DFF/32, DMODEL/32), tT, 0, s2>>>(
            W1 + (size_t)l * DMODEL * DFF, w1h, w1l, DMODEL, DFF);
        cudaEvent_t e_s1 = EV(); cudaEventRecord(e_s1, s2);

        if (e_ff2_done) cudaStreamWaitEvent(s2, e_ff2_done, 0);
        split_wT_kernel<<<dim3(DMODEL/32, DFF/32), tT, 0, s2>>>(
            W2 + (size_t)l * DFF * DMODEL, w2h, w2l, DFF, DMODEL);
        cudaEvent_t e_s2e = EV(); cudaEventRecord(e_s2e, s2);

        // --- main: layer l compute ---
        cudaStreamWaitEvent(0, e_sqkv, 0);
        mma_gemm_qkv_kernel<<<gQKV, 512, GSMEM>>>(xhi, xlo, wqkvh, wqkvl,
            bq + (size_t)l * DMODEL, bk + (size_t)l * DMODEL, bv + (size_t)l * DMODEL,
            qhi, qlo, khi, klo, vhi, vlo, qscale);
        e_qkv_done = EV(); cudaEventRecord(e_qkv_done, 0);

        attn_mma_kernel<<<gAttn, 128, ATTN_SMEM>>>(qhi, qlo, khi, klo, vhi, vlo,
                                                   mask, ohi, olo);

        cudaStreamWaitEvent(0, e_so, 0);
        mma_gemm_kernel<<<gProj, 512, GSMEM>>>(ohi, olo, woh, wol,
            bo + (size_t)l * DMODEL, gy, nullptr, nullptr,
            MROWS, DMODEL, DMODEL, 1.0f, 0, 0);
        e_wo_done = EV(); cudaEventRecord(e_wo_done, 0);

        add_ln_kernel<<<MROWS, 256>>>(gx, gy,
            lng + (size_t)(2 * l) * DMODEL, lnb + (size_t)(2 * l) * DMODEL,
            gx, xhi, xlo);

        cudaStreamWaitEvent(0, e_s1, 0);
        mma_gemm_kernel<<<gFF1, 512, GSMEM>>>(xhi, xlo, w1h, w1l,
            b1 + (size_t)l * DFF, nullptr, hhi, hlo,
            MROWS, DFF, DMODEL, 1.0f, 1, 1);
        e_ff1_done = EV(); cudaEventRecord(e_ff1_done, 0);

        cudaStreamWaitEvent(0, e_s2e, 0);
        mma_gemm_kernel<<<gProj, 512, GSMEM>>>(hhi, hlo, w2h, w2l,
            b2 + (size_t)l * DMODEL, gy, nullptr, nullptr,
            MROWS, DMODEL, DFF, 1.0f, 0, 0);
        e_ff2_done = EV(); cudaEventRecord(e_ff2_done, 0);

        add_ln_kernel<<<MROWS, 256>>>(gx, gy,
            lng + (size_t)(2 * l + 1) * DMODEL, lnb + (size_t)(2 * l + 1) * DMODEL,
            gx, xhi, xlo);
    }

    // final join of s2 into main (all s2 records are already consumed, belt+braces)
    cudaEvent_t eJoin = EV();
    cudaEventRecord(eJoin, s2);
    cudaStreamWaitEvent(0, eJoin, 0);

    cudaMemcpyAsync(out, gx, (size_t)MROWS * DMODEL * sizeof(float),
                    cudaMemcpyDeviceToDevice);
#undef EV
}

// round 7
// speedup vs baseline: 3.2607x; 1.0967x over previous
#include <cuda_runtime.h>
#include <cuda_bf16.h>
#include <math.h>
#include <stdint.h>

// Problem constants
#define NLAYER 6
#define NHEAD  16
#define DMODEL 1024
#define DHEAD  64
#define DFF    4096
#define BATCH  4
#define SEQ    1024
#define MROWS  (BATCH*SEQ)
#define NEG_INF_F (-100000000.0f)

// ---------------------------------------------------------------------------
// Scratch (static device globals; no allocation anywhere)
// ---------------------------------------------------------------------------
__device__ float g_x[MROWS*DMODEL];
__device__ float g_y[MROWS*DMODEL];
__device__ __nv_bfloat16 g_xhi[MROWS*DMODEL], g_xlo[MROWS*DMODEL];
__device__ __nv_bfloat16 g_qhi[MROWS*DMODEL], g_qlo[MROWS*DMODEL];
__device__ __nv_bfloat16 g_khi[MROWS*DMODEL], g_klo[MROWS*DMODEL];
__device__ __nv_bfloat16 g_vhi[MROWS*DMODEL], g_vlo[MROWS*DMODEL];
__device__ __nv_bfloat16 g_ohi[MROWS*DMODEL], g_olo[MROWS*DMODEL];
__device__ __nv_bfloat16 g_hhi[MROWS*DFF],    g_hlo[MROWS*DFF];
__device__ __nv_bfloat16 g_wqkv_hi[3*DMODEL*DMODEL], g_wqkv_lo[3*DMODEL*DMODEL];
__device__ __nv_bfloat16 g_wo_hi[DMODEL*DMODEL],     g_wo_lo[DMODEL*DMODEL];
__device__ __nv_bfloat16 g_w1_hi[DMODEL*DFF],        g_w1_lo[DMODEL*DFF];
__device__ __nv_bfloat16 g_w2_hi[DFF*DMODEL],        g_w2_lo[DFF*DMODEL];

// ---------------------------------------------------------------------------
// PTX helpers
// ---------------------------------------------------------------------------
__device__ __forceinline__ uint32_t smem_u32(const void* p) {
    uint32_t a;
    asm("{ .reg .u64 t; cvta.to.shared.u64 t, %1; cvt.u32.u64 %0, t; }" : "=r"(a) : "l"(p));
    return a;
}
__device__ __forceinline__ void cp_async16(uint32_t dst, const void* src) {
    asm volatile("cp.async.cg.shared.global [%0], [%1], 16;" :: "r"(dst), "l"(src) : "memory");
}
#define CP_COMMIT() asm volatile("cp.async.commit_group;" ::: "memory")

__device__ __forceinline__ void ldsm_x4(uint32_t& r0, uint32_t& r1, uint32_t& r2,
                                        uint32_t& r3, uint32_t addr) {
    asm volatile("ldmatrix.sync.aligned.m8n8.x4.shared.b16 {%0,%1,%2,%3}, [%4];"
                 : "=r"(r0), "=r"(r1), "=r"(r2), "=r"(r3) : "r"(addr));
}
__device__ __forceinline__ void ldsm_x4_t(uint32_t& r0, uint32_t& r1, uint32_t& r2,
                                          uint32_t& r3, uint32_t addr) {
    asm volatile("ldmatrix.sync.aligned.m8n8.x4.trans.shared.b16 {%0,%1,%2,%3}, [%4];"
                 : "=r"(r0), "=r"(r1), "=r"(r2), "=r"(r3) : "r"(addr));
}
__device__ __forceinline__ void mma_bf16(float* c, const uint32_t* a, const uint32_t* b) {
    asm volatile(
        "mma.sync.aligned.m16n8k16.row.col.f32.bf16.bf16.f32 "
        "{%0,%1,%2,%3}, {%4,%5,%6,%7}, {%8,%9}, {%0,%1,%2,%3};"
        : "+f"(c[0]), "+f"(c[1]), "+f"(c[2]), "+f"(c[3])
        : "r"(a[0]), "r"(a[1]), "r"(a[2]), "r"(a[3]), "r"(b[0]), "r"(b[1]));
}
__device__ __forceinline__ void pack_split(float x, float y, uint32_t& hi, uint32_t& lo) {
    __nv_bfloat16 hx = __float2bfloat16(x), hy = __float2bfloat16(y);
    __nv_bfloat162 H; H.x = hx; H.y = hy;
    __nv_bfloat162 L;
    L.x = __float2bfloat16(x - __bfloat162float(hx));
    L.y = __float2bfloat16(y - __bfloat162float(hy));
    hi = *(uint32_t*)&H; lo = *(uint32_t*)&L;
}

// Swizzle for 64B-row tiles (GEMM: 32 bf16/row)
__device__ __forceinline__ uint32_t swz(int row, int c) {
    return (uint32_t)(((row >> 1) << 7) |
                      ((((((row & 1) << 2) | c)) ^ ((row >> 1) & 7)) << 4));
}
// Swizzle for 128B-row tiles (attention: 64 bf16/row)
__device__ __forceinline__ uint32_t swz128(int row, int c) {
    return (uint32_t)((row << 7) | (((c ^ (row & 7))) << 4));
}

// GEMM smem geometry: 128x128 tile, BK=32, TRIPLE buffered, 2 CTAs/SM
#define T_TILE 8192                  // one 128x32 bf16 tile
#define STAGEB (4*T_TILE)            // Ahi, Alo, Bhi, Blo = 32768
#define GSMEM  (3*STAGEB)            // 98304 (x2 CTAs = 192KB/SM)

#define ATTN_SMEM (6*8192 + 256)

// ---------------------------------------------------------------------------
// Positional encoding (fp64) + fused bf16 split of the result
// ---------------------------------------------------------------------------
__global__ void posenc_kernel(const float* __restrict__ x, float* __restrict__ out,
                              __nv_bfloat16* __restrict__ ohi,
                              __nv_bfloat16* __restrict__ olo)
{
    int idx = blockIdx.x * blockDim.x + threadIdx.x;
    if (idx >= SEQ * DMODEL) return;
    int d = idx & (DMODEL - 1);
    int s = idx >> 10;
    int t = (d < DMODEL/2) ? d : d - DMODEL/2;
    const double log_inc = log(10000.0) / (double)(DMODEL/2 - 1);
    double arg = (double)s * exp(-(double)t * log_inc);
    float sig = (float)((d < DMODEL/2) ? sin(arg) : cos(arg));
#pragma unroll
    for (int b = 0; b < BATCH; ++b) {
        size_t off = (size_t)b * SEQ * DMODEL + idx;
        float v = x[off] + sig;
        out[off] = v;
        __nv_bfloat16 h = __float2bfloat16(v);
        ohi[off] = h;
        olo[off] = __float2bfloat16(v - __bfloat162float(h));
    }
}

// ---------------------------------------------------------------------------
// W [K,N] fp32 -> transposed bf16 split: hiT, loT [N,K]
// ---------------------------------------------------------------------------
__global__ __launch_bounds__(256) void split_wT_kernel(
    const float* __restrict__ W, __nv_bfloat16* __restrict__ hiT,
    __nv_bfloat16* __restrict__ loT, int K, int N)
{
    __shared__ float t[32][33];
    int nx = blockIdx.x * 32;
    int ky = blockIdx.y * 32;
    int tx = threadIdx.x, ty = threadIdx.y;   // (32, 8)
#pragma unroll
    for (int i = 0; i < 4; ++i)
        t[ty + 8*i][tx] = W[(size_t)(ky + ty + 8*i) * N + nx + tx];
    __syncthreads();
#pragma unroll
    for (int i = 0; i < 4; ++i) {
        float v = t[tx][ty + 8*i];
        __nv_bfloat16 h = __float2bfloat16(v);
        size_t o = (size_t)(nx + ty + 8*i) * K + ky + tx;
        hiT[o] = h;
        loT[o] = __float2bfloat16(v - __bfloat162float(h));
    }
}

// --- chunk loader: 4 tiles (Ahi,Alo,Bhi,Blo) x 512 16B chunks / 256 thr = 8 ---
#define LOAD_CHUNK(k0, buf)                                                     \
    {                                                                           \
        _Pragma("unroll")                                                       \
        for (int i = 0; i < 8; ++i) {                                           \
            int t = tid + i * 256;                                              \
            int tile = t >> 9;                                                  \
            int w = t & 511;                                                    \
            int row = w >> 2;                                                   \
            int c = w & 3;                                                      \
            const __nv_bfloat16* src =                                          \
                (tile == 0) ? Ahi : (tile == 1) ? Alo : (tile == 2) ? Bhi : Blo;\
            int gr = ((tile < 2) ? m0 : n0) + row;                              \
            cp_async16((buf) + (uint32_t)tile * T_TILE + swz(row, c),           \
                       src + (size_t)gr * K + (k0) + c * 8);                    \
        }                                                                       \
        CP_COMMIT();                                                            \
    }

// --- MMA body (3-pass, pass-major), 8 warps each 32x64 ---
#define MMA_BODY(buf)                                                            \
    {                                                                            \
        const uint32_t Ah = buf;                                                 \
        const uint32_t Al = buf + T_TILE;                                        \
        const uint32_t Bh = buf + 2 * T_TILE;                                    \
        const uint32_t Bl = buf + 3 * T_TILE;                                    \
        _Pragma("unroll")                                                        \
        for (int kk = 0; kk < 2; ++kk) {                                         \
            uint32_t ahi_f[2][4], alo_f[2][4];                                   \
            _Pragma("unroll")                                                    \
            for (int mi = 0; mi < 2; ++mi) {                                     \
                int r = a_r + mi * 16;                                           \
                uint32_t off = swz(r, kk * 2 + a_h);                             \
                ldsm_x4(ahi_f[mi][0], ahi_f[mi][1], ahi_f[mi][2], ahi_f[mi][3], Ah + off); \
                ldsm_x4(alo_f[mi][0], alo_f[mi][1], alo_f[mi][2], alo_f[mi][3], Al + off); \
            }                                                                    \
            uint32_t bf[8][2];                                                   \
            _Pragma("unroll")                                                    \
            for (int nt = 0; nt < 4; ++nt) {                                     \
                int r = b_r + nt * 16;                                           \
                uint32_t off = swz(r, kk * 2 + b_h);                             \
                uint32_t q0, q1, q2, q3;                                         \
                ldsm_x4(q0, q1, q2, q3, Bh + off);                               \
                bf[nt*2][0] = q0; bf[nt*2][1] = q1;                              \
                bf[nt*2+1][0] = q2; bf[nt*2+1][1] = q3;                          \
            }                                                                    \
            _Pragma("unroll")                                                    \
            for (int mi = 0; mi < 2; ++mi)                                       \
                _Pragma("unroll")                                                \
                for (int ni = 0; ni < 8; ++ni)                                   \
                    mma_bf16(acc[mi][ni], ahi_f[mi], bf[ni]);                    \
            _Pragma("unroll")                                                    \
            for (int mi = 0; mi < 2; ++mi)                                       \
                _Pragma("unroll")                                                \
                for (int ni = 0; ni < 8; ++ni)                                   \
                    mma_bf16(acc[mi][ni], alo_f[mi], bf[ni]);                    \
            _Pragma("unroll")                                                    \
            for (int nt = 0; nt < 4; ++nt) {                                     \
                int r = b_r + nt * 16;                                           \
                uint32_t off = swz(r, kk * 2 + b_h);                             \
                uint32_t q0, q1, q2, q3;                                         \
                ldsm_x4(q0, q1, q2, q3, Bl + off);                               \
                bf[nt*2][0] = q0; bf[nt*2][1] = q1;                              \
                bf[nt*2+1][0] = q2; bf[nt*2+1][1] = q3;                          \
            }                                                                    \
            _Pragma("unroll")                                                    \
            for (int mi = 0; mi < 2; ++mi)                                       \
                _Pragma("unroll")                                                \
                for (int ni = 0; ni < 8; ++ni)                                   \
                    mma_bf16(acc[mi][ni], ahi_f[mi], bf[ni]);                    \
        }                                                                        \
    }

// --- 3-stage K-loop ---
#define K_LOOP()                                                                 \
    LOAD_CHUNK(0, sb);                                                           \
    LOAD_CHUNK(32, sb + STAGEB);                                                 \
    for (int ch = 0; ch < nch; ++ch) {                                           \
        const uint32_t buf = sb + (uint32_t)(ch % 3) * STAGEB;                   \
        if (ch + 2 < nch) {                                                      \
            LOAD_CHUNK((ch + 2) * 32, sb + (uint32_t)((ch + 2) % 3) * STAGEB);   \
            asm volatile("cp.async.wait_group 2;" ::: "memory");                 \
        } else if (ch + 1 < nch) {                                               \
            asm volatile("cp.async.wait_group 1;" ::: "memory");                 \
        } else {                                                                 \
            asm volatile("cp.async.wait_group 0;" ::: "memory");                 \
        }                                                                        \
        __syncthreads();                                                         \
        MMA_BODY(buf)                                                            \
        __syncthreads();                                                         \
    }

// ---------------------------------------------------------------------------
// General HMMA bf16-split GEMM (Wo / FF1 / FF2): 128x128 tile, 256 thr, 2 CTA/SM
// ---------------------------------------------------------------------------
__global__ __launch_bounds__(256, 2) void mma_gemm_kernel(
    const __nv_bfloat16* __restrict__ Ahi, const __nv_bfloat16* __restrict__ Alo,
    const __nv_bfloat16* __restrict__ Bhi, const __nv_bfloat16* __restrict__ Blo,
    const float* __restrict__ bias, float* __restrict__ C,
    __nv_bfloat16* __restrict__ Chi, __nv_bfloat16* __restrict__ Clo,
    int M, int N, int K, float alpha, int relu, int outmode)
{
    extern __shared__ char smem[];
    const uint32_t sb = smem_u32(smem);
    const int tid = threadIdx.x;
    const int wid = tid >> 5, lane = tid & 31;
    const int m0 = blockIdx.y * 128, n0 = blockIdx.x * 128;
    const int wm = (wid & 3) * 32;
    const int wn = (wid >> 2) * 64;

    float acc[2][8][4];
#pragma unroll
    for (int mi = 0; mi < 2; ++mi)
#pragma unroll
        for (int ni = 0; ni < 8; ++ni)
#pragma unroll
            for (int r = 0; r < 4; ++r) acc[mi][ni][r] = 0.0f;

    const int nch = K >> 5;
    const int a_r = wm + (lane & 15);
    const int a_h = lane >> 4;
    const int b_r = wn + ((lane >> 4) << 3) + (lane & 7);
    const int b_h = (lane >> 3) & 1;

    K_LOOP()

    const int grp = lane >> 2, qid = lane & 3;
#pragma unroll
    for (int mi = 0; mi < 2; ++mi) {
        const int row0 = m0 + wm + mi * 16 + grp;
#pragma unroll
        for (int ni = 0; ni < 8; ++ni) {
            const int col = n0 + wn + ni * 8 + qid * 2;
            float2 b2 = *(const float2*)(bias + col);
            float2 u, v;
            u.x = (acc[mi][ni][0] + b2.x) * alpha;
            u.y = (acc[mi][ni][1] + b2.y) * alpha;
            v.x = (acc[mi][ni][2] + b2.x) * alpha;
            v.y = (acc[mi][ni][3] + b2.y) * alpha;
            if (relu) {
                u.x = fmaxf(u.x, 0.f); u.y = fmaxf(u.y, 0.f);
                v.x = fmaxf(v.x, 0.f); v.y = fmaxf(v.y, 0.f);
            }
            if (outmode == 0) {
                *(float2*)(C + (size_t)row0 * N + col) = u;
                *(float2*)(C + (size_t)(row0 + 8) * N + col) = v;
            } else {
                uint32_t hi, lo;
                pack_split(u.x, u.y, hi, lo);
                *(uint32_t*)(Chi + (size_t)row0 * N + col) = hi;
                *(uint32_t*)(Clo + (size_t)row0 * N + col) = lo;
                pack_split(v.x, v.y, hi, lo);
                *(uint32_t*)(Chi + (size_t)(row0 + 8) * N + col) = hi;
                *(uint32_t*)(Clo + (size_t)(row0 + 8) * N + col) = lo;
            }
        }
    }
}

// ---------------------------------------------------------------------------
// Batched QKV GEMM: B packed [3072, 1024]. grid (24, 32). mid = n0>>10.
// ---------------------------------------------------------------------------
__global__ __launch_bounds__(256, 2) void mma_gemm_qkv_kernel(
    const __nv_bfloat16* __restrict__ Ahi, const __nv_bfloat16* __restrict__ Alo,
    const __nv_bfloat16* __restrict__ Bhi, const __nv_bfloat16* __restrict__ Blo,
    const float* __restrict__ bq, const float* __restrict__ bk,
    const float* __restrict__ bv,
    __nv_bfloat16* __restrict__ Qhi, __nv_bfloat16* __restrict__ Qlo,
    __nv_bfloat16* __restrict__ Khi, __nv_bfloat16* __restrict__ Klo,
    __nv_bfloat16* __restrict__ Vhi, __nv_bfloat16* __restrict__ Vlo,
    float qscale)
{
    extern __shared__ char smem[];
    const uint32_t sb = smem_u32(smem);
    const int tid = threadIdx.x;
    const int wid = tid >> 5, lane = tid & 31;
    const int m0 = blockIdx.y * 128, n0 = blockIdx.x * 128;
    const int K = DMODEL;
    const int wm = (wid & 3) * 32;
    const int wn = (wid >> 2) * 64;

    float acc[2][8][4];
#pragma unroll
    for (int mi = 0; mi < 2; ++mi)
#pragma unroll
        for (int ni = 0; ni < 8; ++ni)
#pragma unroll
            for (int r = 0; r < 4; ++r) acc[mi][ni][r] = 0.0f;

    const int nch = K >> 5;
    const int a_r = wm + (lane & 15);
    const int a_h = lane >> 4;
    const int b_r = wn + ((lane >> 4) << 3) + (lane & 7);
    const int b_h = (lane >> 3) & 1;

    K_LOOP()

    const int mid = n0 >> 10;
    const float* bsel = (mid == 0) ? bq : (mid == 1) ? bk : bv;
    __nv_bfloat16* hisel = (mid == 0) ? Qhi : (mid == 1) ? Khi : Vhi;
    __nv_bfloat16* losel = (mid == 0) ? Qlo : (mid == 1) ? Klo : Vlo;
    const float asel = (mid == 0) ? qscale : 1.0f;
    const int cb = mid << 10;

    const int grp = lane >> 2, qid = lane & 3;
#pragma unroll
    for (int mi = 0; mi < 2; ++mi) {
        const int row0 = m0 + wm + mi * 16 + grp;
#pragma unroll
        for (int ni = 0; ni < 8; ++ni) {
            const int col = n0 + wn + ni * 8 + qid * 2 - cb;
            float2 b2 = *(const float2*)(bsel + col);
            float2 u, v;
            u.x = (acc[mi][ni][0] + b2.x) * asel;
            u.y = (acc[mi][ni][1] + b2.y) * asel;
            v.x = (acc[mi][ni][2] + b2.x) * asel;
            v.y = (acc[mi][ni][3] + b2.y) * asel;
            uint32_t hi, lo;
            pack_split(u.x, u.y, hi, lo);
            *(uint32_t*)(hisel + (size_t)row0 * DMODEL + col) = hi;
            *(uint32_t*)(losel + (size_t)row0 * DMODEL + col) = lo;
            pack_split(v.x, v.y, hi, lo);
            *(uint32_t*)(hisel + (size_t)(row0 + 8) * DMODEL + col) = hi;
            *(uint32_t*)(losel + (size_t)(row0 + 8) * DMODEL + col) = lo;
        }
    }
}

// ---------------------------------------------------------------------------
// MMA flash attention (unchanged)
// ---------------------------------------------------------------------------
__global__ __launch_bounds__(128) void attn_mma_kernel(
    const __nv_bfloat16* __restrict__ Qhi, const __nv_bfloat16* __restrict__ Qlo,
    const __nv_bfloat16* __restrict__ Khi, const __nv_bfloat16* __restrict__ Klo,
    const __nv_bfloat16* __restrict__ Vhi, const __nv_bfloat16* __restrict__ Vlo,
    const float* __restrict__ mask,
    __nv_bfloat16* __restrict__ Ohi, __nv_bfloat16* __restrict__ Olo)
{
    extern __shared__ char sm[];
    const uint32_t sb = smem_u32(sm);
    const uint32_t Qh = sb,          Ql = sb + 8192;
    const uint32_t Kh = sb + 16384,  Kl = sb + 24576;
    const uint32_t Vh = sb + 32768,  Vl = sb + 40960;
    float* msk = (float*)(sm + 49152);

    const int tid = threadIdx.x, wid = tid >> 5, lane = tid & 31;
    const int b = blockIdx.z, h = blockIdx.y, q0 = blockIdx.x * 64;
    const int g = lane >> 2, qd = lane & 3;

    for (int i = tid; i < 1024; i += 128) {
        int t = i >> 9;
        int w = i & 511;
        int r = w >> 3, c = w & 7;
        const __nv_bfloat16* src = (t ? Qlo : Qhi)
            + (size_t)(b * SEQ + q0 + r) * DMODEL + h * DHEAD + c * 8;
        cp_async16((t ? Ql : Qh) + swz128(r, c), src);
    }
    CP_COMMIT();

    float m_i[2] = {-INFINITY, -INFINITY}, l_i[2] = {0.f, 0.f};
    float oacc[8][4];
#pragma unroll
    for (int ni = 0; ni < 8; ++ni)
#pragma unroll
        for (int r = 0; r < 4; ++r) oacc[ni][r] = 0.f;

    const int a_r = wid * 16 + (lane & 15);
    const int a_c = lane >> 4;
    const int b_r = (lane & 7) + ((lane >> 4) << 3);
    const int b_c = (lane >> 3) & 1;
    const int v_ro = ((lane >> 3) & 1) * 8 + (lane & 7);
    const int v_co = lane >> 4;

    for (int kt = 0; kt < SEQ; kt += 64) {
        for (int i = tid; i < 2048; i += 128) {
            int t = i >> 9;
            int w = i & 511;
            int r = w >> 3, c = w & 7;
            const __nv_bfloat16* src =
                ((t == 0) ? Khi : (t == 1) ? Klo : (t == 2) ? Vhi : Vlo)
                + (size_t)(b * SEQ + kt + r) * DMODEL + h * DHEAD + c * 8;
            uint32_t dstb = (t == 0) ? Kh : (t == 1) ? Kl : (t == 2) ? Vh : Vl;
            cp_async16(dstb + swz128(r, c), src);
        }
        CP_COMMIT();
        if (tid < 64) msk[tid] = (1.0f - mask[b * SEQ + kt + tid]) * NEG_INF_F;
        asm volatile("cp.async.wait_group 0;" ::: "memory");
        __syncthreads();

        float sacc[8][4];
#pragma unroll
        for (int ni = 0; ni < 8; ++ni)
#pragma unroll
            for (int r = 0; r < 4; ++r) sacc[ni][r] = 0.f;

#pragma unroll
        for (int kk = 0; kk < 4; ++kk) {
            uint32_t qh[4], ql[4];
            uint32_t offA = swz128(a_r, kk * 2 + a_c);
            ldsm_x4(qh[0], qh[1], qh[2], qh[3], Qh + offA);
            ldsm_x4(ql[0], ql[1], ql[2], ql[3], Ql + offA);
            uint32_t bh[8][2], bl[8][2];
#pragma unroll
            for (int nt = 0; nt < 4; ++nt) {
                uint32_t off = swz128(b_r + nt * 16, kk * 2 + b_c);
                uint32_t r0, r1, r2, r3;
                ldsm_x4(r0, r1, r2, r3, Kh + off);
                bh[nt*2][0] = r0; bh[nt*2][1] = r1;
                bh[nt*2+1][0] = r2; bh[nt*2+1][1] = r3;
                ldsm_x4(r0, r1, r2, r3, Kl + off);
                bl[nt*2][0] = r0; bl[nt*2][1] = r1;
                bl[nt*2+1][0] = r2; bl[nt*2+1][1] = r3;
            }
#pragma unroll
            for (int ni = 0; ni < 8; ++ni) mma_bf16(sacc[ni], qh, bh[ni]);
#pragma unroll
            for (int ni = 0; ni < 8; ++ni) mma_bf16(sacc[ni], qh, bl[ni]);
#pragma unroll
            for (int ni = 0; ni < 8; ++ni) mma_bf16(sacc[ni], ql, bh[ni]);
        }

#pragma unroll
        for (int ni = 0; ni < 8; ++ni) {
            float ma = msk[ni * 8 + qd * 2], mb = msk[ni * 8 + qd * 2 + 1];
            sacc[ni][0] += ma; sacc[ni][1] += mb;
            sacc[ni][2] += ma; sacc[ni][3] += mb;
        }

#pragma unroll
        for (int hf = 0; hf < 2; ++hf) {
            float mx = -INFINITY;
#pragma unroll
            for (int ni = 0; ni < 8; ++ni)
                mx = fmaxf(mx, fmaxf(sacc[ni][hf*2], sacc[ni][hf*2+1]));
            mx = fmaxf(mx, __shfl_xor_sync(0xffffffffu, mx, 1));
            mx = fmaxf(mx, __shfl_xor_sync(0xffffffffu, mx, 2));
            float mnew = fmaxf(m_i[hf], mx);
            float rs = 0.f;
#pragma unroll
            for (int ni = 0; ni < 8; ++ni) {
                float e0 = __expf(sacc[ni][hf*2]   - mnew);
                float e1 = __expf(sacc[ni][hf*2+1] - mnew);
                sacc[ni][hf*2] = e0; sacc[ni][hf*2+1] = e1;
                rs += e0 + e1;
            }
            rs += __shfl_xor_sync(0xffffffffu, rs, 1);
            rs += __shfl_xor_sync(0xffffffffu, rs, 2);
            float sc = __expf(m_i[hf] - mnew);
            l_i[hf] = l_i[hf] * sc + rs;
            m_i[hf] = mnew;
#pragma unroll
            for (int ni = 0; ni < 8; ++ni) {
                oacc[ni][hf*2]   *= sc;
                oacc[ni][hf*2+1] *= sc;
            }
        }

#pragma unroll
        for (int kk = 0; kk < 4; ++kk) {
            uint32_t ph[4], pl[4];
            pack_split(sacc[2*kk][0],   sacc[2*kk][1],   ph[0], pl[0]);
            pack_split(sacc[2*kk][2],   sacc[2*kk][3],   ph[1], pl[1]);
            pack_split(sacc[2*kk+1][0], sacc[2*kk+1][1], ph[2], pl[2]);
            pack_split(sacc[2*kk+1][2], sacc[2*kk+1][3], ph[3], pl[3]);
            uint32_t vh[8][2], vl[8][2];
#pragma unroll
            for (int nt = 0; nt < 4; ++nt) {
                uint32_t off = swz128(kk * 16 + v_ro, nt * 2 + v_co);
                uint32_t r0, r1, r2, r3;
                ldsm_x4_t(r0, r1, r2, r3, Vh + off);
                vh[nt*2][0] = r0; vh[nt*2][1] = r1;
                vh[nt*2+1][0] = r2; vh[nt*2+1][1] = r3;
                ldsm_x4_t(r0, r1, r2, r3, Vl + off);
                vl[nt*2][0] = r0; vl[nt*2][1] = r1;
                vl[nt*2+1][0] = r2; vl[nt*2+1][1] = r3;
            }
#pragma unroll
            for (int ni = 0; ni < 8; ++ni) mma_bf16(oacc[ni], ph, vh[ni]);
#pragma unroll
            for (int ni = 0; ni < 8; ++ni) mma_bf16(oacc[ni], ph, vl[ni]);
#pragma unroll
            for (int ni = 0; ni < 8; ++ni) mma_bf16(oacc[ni], pl, vh[ni]);
        }
        __syncthreads();
    }

#pragma unroll
    for (int hf = 0; hf < 2; ++hf) {
        float inv = 1.0f / l_i[hf];
        int row = q0 + wid * 16 + g + hf * 8;
#pragma unroll
        for (int ni = 0; ni < 8; ++ni) {
            float x0 = oacc[ni][hf*2] * inv, x1 = oacc[ni][hf*2+1] * inv;
            uint32_t hi, lo;
            pack_split(x0, x1, hi, lo);
            size_t off = (size_t)(b * SEQ + row) * DMODEL + h * DHEAD + ni * 8 + qd * 2;
            *(uint32_t*)(Ohi + off) = hi;
            *(uint32_t*)(Olo + off) = lo;
        }
    }
}

// ---------------------------------------------------------------------------
// Fused residual + LayerNorm; writes fp32 x and bf16 hi/lo split of x.
// ---------------------------------------------------------------------------
__global__ __launch_bounds__(256) void add_ln_kernel(
    const float* __restrict__ x, const float* __restrict__ y,
    const float* __restrict__ g, const float* __restrict__ beta,
    float* __restrict__ out,
    __nv_bfloat16* __restrict__ ohi, __nv_bfloat16* __restrict__ olo)
{
    __shared__ float red[8];
    __shared__ float sbroadcast;

    const int row = blockIdx.x;
    const int tid = threadIdx.x;
    const int lane = tid & 31, wid = tid >> 5;
    const size_t base = (size_t)row * DMODEL + tid * 4;

    float4 xv = *(const float4*)(x + base);
    float4 yv = *(const float4*)(y + base);
    float4 v;
    v.x = xv.x + yv.x; v.y = xv.y + yv.y; v.z = xv.z + yv.z; v.w = xv.w + yv.w;

    float s = v.x + v.y + v.z + v.w;
#pragma unroll
    for (int o = 16; o > 0; o >>= 1) s += __shfl_xor_sync(0xffffffffu, s, o);
    if (lane == 0) red[wid] = s;
    __syncthreads();
    if (tid == 0) {
        float t = 0.0f;
#pragma unroll
        for (int w = 0; w < 8; ++w) t += red[w];
        sbroadcast = t * (1.0f / DMODEL);
    }
    __syncthreads();
    const float mean = sbroadcast;

    float dx0 = v.x - mean, dx1 = v.y - mean, dx2 = v.z - mean, dx3 = v.w - mean;
    float s2 = dx0 * dx0 + dx1 * dx1 + dx2 * dx2 + dx3 * dx3;
#pragma unroll
    for (int o = 16; o > 0; o >>= 1) s2 += __shfl_xor_sync(0xffffffffu, s2, o);
    __syncthreads();
    if (lane == 0) red[wid] = s2;
    __syncthreads();
    if (tid == 0) {
        float t = 0.0f;
#pragma unroll
        for (int w = 0; w < 8; ++w) t += red[w];
        sbroadcast = t * (1.0f / DMODEL);
    }
    __syncthreads();
    const float rstd = rsqrtf(sbroadcast + 1e-5f);

    float4 gv = *(const float4*)(g + tid * 4);
    float4 bv = *(const float4*)(beta + tid * 4);
    float4 o4;
    o4.x = dx0 * rstd * gv.x + bv.x;
    o4.y = dx1 * rstd * gv.y + bv.y;
    o4.z = dx2 * rstd * gv.z + bv.z;
    o4.w = dx3 * rstd * gv.w + bv.w;
    *(float4*)(out + base) = o4;

    uint32_t h0, l0, h1, l1;
    pack_split(o4.x, o4.y, h0, l0);
    pack_split(o4.z, o4.w, h1, l1);
    *(uint32_t*)(ohi + base)     = h0;
    *(uint32_t*)(ohi + base + 2) = h1;
    *(uint32_t*)(olo + base)     = l0;
    *(uint32_t*)(olo + base + 2) = l1;
}

// ---------------------------------------------------------------------------
// Launch (dual-stream: main = stream 0, s2 = weight splits)
// ---------------------------------------------------------------------------
extern "C" void kernel_launch(void* const* d_in, const int* in_sizes, int n_in,
                              void* d_out, int out_size)
{
    (void)in_sizes; (void)n_in; (void)out_size;

    const float* x    = (const float*)d_in[0];
    const float* mask = (const float*)d_in[1];
    const float* Wq   = (const float*)d_in[2];
    const float* bq   = (const float*)d_in[3];
    const float* Wk   = (const float*)d_in[4];
    const float* bk   = (const float*)d_in[5];
    const float* Wv   = (const float*)d_in[6];
    const float* bv   = (const float*)d_in[7];
    const float* Wo   = (const float*)d_in[8];
    const float* bo   = (const float*)d_in[9];
    const float* W1   = (const float*)d_in[10];
    const float* b1   = (const float*)d_in[11];
    const float* W2   = (const float*)d_in[12];
    const float* b2   = (const float*)d_in[13];
    const float* lng  = (const float*)d_in[14];
    const float* lnb  = (const float*)d_in[15];
    float* out = (float*)d_out;

    float *gx, *gy;
    __nv_bfloat16 *xhi, *xlo, *qhi, *qlo, *khi, *klo, *vhi, *vlo,
                  *ohi, *olo, *hhi, *hlo;
    __nv_bfloat16 *wqkvh, *wqkvl, *woh, *wol, *w1h, *w1l, *w2h, *w2l;
    cudaGetSymbolAddress((void**)&gx,  g_x);
    cudaGetSymbolAddress((void**)&gy,  g_y);
    cudaGetSymbolAddress((void**)&xhi, g_xhi);
    cudaGetSymbolAddress((void**)&xlo, g_xlo);
    cudaGetSymbolAddress((void**)&qhi, g_qhi);
    cudaGetSymbolAddress((void**)&qlo, g_qlo);
    cudaGetSymbolAddress((void**)&khi, g_khi);
    cudaGetSymbolAddress((void**)&klo, g_klo);
    cudaGetSymbolAddress((void**)&vhi, g_vhi);
    cudaGetSymbolAddress((void**)&vlo, g_vlo);
    cudaGetSymbolAddress((void**)&ohi, g_ohi);
    cudaGetSymbolAddress((void**)&olo, g_olo);
    cudaGetSymbolAddress((void**)&hhi, g_hhi);
    cudaGetSymbolAddress((void**)&hlo, g_hlo);
    cudaGetSymbolAddress((void**)&wqkvh, g_wqkv_hi);
    cudaGetSymbolAddress((void**)&wqkvl, g_wqkv_lo);
    cudaGetSymbolAddress((void**)&woh, g_wo_hi);
    cudaGetSymbolAddress((void**)&wol, g_wo_lo);
    cudaGetSymbolAddress((void**)&w1h, g_w1_hi);
    cudaGetSymbolAddress((void**)&w1l, g_w1_lo);
    cudaGetSymbolAddress((void**)&w2h, g_w2_hi);
    cudaGetSymbolAddress((void**)&w2l, g_w2_lo);

    static cudaStream_t s2 = nullptr;
    static cudaEvent_t evpool[64];
    static int attr_set = 0;
    if (!attr_set) {
        cudaFuncSetAttribute(mma_gemm_kernel,
                             cudaFuncAttributeMaxDynamicSharedMemorySize, GSMEM);
        cudaFuncSetAttribute(mma_gemm_qkv_kernel,
                             cudaFuncAttributeMaxDynamicSharedMemorySize, GSMEM);
        cudaFuncSetAttribute(attn_mma_kernel,
                             cudaFuncAttributeMaxDynamicSharedMemorySize, ATTN_SMEM);
        cudaStreamCreateWithFlags(&s2, cudaStreamNonBlocking);
        for (int i = 0; i < 64; ++i)
            cudaEventCreateWithFlags(&evpool[i], cudaEventDisableTiming);
        attr_set = 1;
    }
    int evn = 0;
#define EV() (evpool[evn++])

    const float qscale = 0.125f;
    dim3 gQKV(3 * DMODEL / 128, MROWS / 128);  // (24, 32)
    dim3 gProj(DMODEL / 128, MROWS / 128);     // (8, 32)
    dim3 gFF1(DFF / 128, MROWS / 128);         // (32, 32)
    dim3 gAttn(SEQ / 64, NHEAD, BATCH);
    dim3 tT(32, 8);

    cudaEvent_t eFork = EV();
    cudaEventRecord(eFork, 0);
    cudaStreamWaitEvent(s2, eFork, 0);

    posenc_kernel<<<(SEQ * DMODEL + 255) / 256, 256>>>(x, gx, xhi, xlo);

    cudaEvent_t e_qkv_done = nullptr, e_wo_done = nullptr,
                e_ff1_done = nullptr, e_ff2_done = nullptr;

    for (int l = 0; l < NLAYER; ++l) {
        const float* wq = Wq + (size_t)l * DMODEL * DMODEL;
        const float* wk = Wk + (size_t)l * DMODEL * DMODEL;
        const float* wv = Wv + (size_t)l * DMODEL * DMODEL;
        const float* wo = Wo + (size_t)l * DMODEL * DMODEL;

        if (e_qkv_done) cudaStreamWaitEvent(s2, e_qkv_done, 0);
        split_wT_kernel<<<dim3(32,32), tT, 0, s2>>>(wq, wqkvh,               wqkvl,               DMODEL, DMODEL);
        split_wT_kernel<<<dim3(32,32), tT, 0, s2>>>(wk, wqkvh + 1024*1024,   wqkvl + 1024*1024,   DMODEL, DMODEL);
        split_wT_kernel<<<dim3(32,32), tT, 0, s2>>>(wv, wqkvh + 2*1024*1024, wqkvl + 2*1024*1024, DMODEL, DMODEL);
        cudaEvent_t e_sqkv = EV(); cudaEventRecord(e_sqkv, s2);

        if (e_wo_done) cudaStreamWaitEvent(s2, e_wo_done, 0);
        split_wT_kernel<<<dim3(32,32), tT, 0, s2>>>(wo, woh, wol, DMODEL, DMODEL);
        cudaEvent_t e_so = EV(); cudaEventRecord(e_so, s2);

        if (e_ff1_done) cudaStreamWaitEvent(s2, e_ff1_done, 0);
        split_wT_kernel<<<dim3(DFF/32, DMODEL/32), tT, 0, s2>>>(
            W1 + (size_t)l * DMODEL * DFF, w1h, w1l, DMODEL, DFF);
        cudaEvent_t e_s1 = EV(); cudaEventRecord(e_s1, s2);

        if (e_ff2_done) cudaStreamWaitEvent(s2, e_ff2_done, 0);
        split_wT_kernel<<<dim3(DMODEL/32, DFF/32), tT, 0, s2>>>(
            W2 + (size_t)l * DFF * DMODEL, w2h, w2l, DFF, DMODEL);
        cudaEvent_t e_s2e = EV(); cudaEventRecord(e_s2e, s2);

        cudaStreamWaitEvent(0, e_sqkv, 0);
        mma_gemm_qkv_kernel<<<gQKV, 256, GSMEM>>>(xhi, xlo, wqkvh, wqkvl,
            bq + (size_t)l * DMODEL, bk + (size_t)l * DMODEL, bv + (size_t)l * DMODEL,
            qhi, qlo, khi, klo, vhi, vlo, qscale);
        e_qkv_done = EV(); cudaEventRecord(e_qkv_done, 0);

        attn_mma_kernel<<<gAttn, 128, ATTN_SMEM>>>(qhi, qlo, khi, klo, vhi, vlo,
                                                   mask, ohi, olo);

        cudaStreamWaitEvent(0, e_so, 0);
        mma_gemm_kernel<<<gProj, 256, GSMEM>>>(ohi, olo, woh, wol,
            bo + (size_t)l * DMODEL, gy, nullptr, nullptr,
            MROWS, DMODEL, DMODEL, 1.0f, 0, 0);
        e_wo_done = EV(); cudaEventRecord(e_wo_done, 0);

        add_ln_kernel<<<MROWS, 256>>>(gx, gy,
            lng + (size_t)(2 * l) * DMODEL, lnb + (size_t)(2 * l) * DMODEL,
            gx, xhi, xlo);

        cudaStreamWaitEvent(0, e_s1, 0);
        mma_gemm_kernel<<<gFF1, 256, GSMEM>>>(xhi, xlo, w1h, w1l,
            b1 + (size_t)l * DFF, nullptr, hhi, hlo,
            MROWS, DFF, DMODEL, 1.0f, 1, 1);
        e_ff1_done = EV(); cudaEventRecord(e_ff1_done, 0);

        cudaStreamWaitEvent(0, e_s2e, 0);
        mma_gemm_kernel<<<gProj, 256, GSMEM>>>(hhi, hlo, w2h, w2l,
            b2 + (size_t)l * DMODEL, gy, nullptr, nullptr,
            MROWS, DMODEL, DFF, 1.0f, 0, 0);
        e_ff2_done = EV(); cudaEventRecord(e_ff2_done, 0);

        add_ln_kernel<<<MROWS, 256>>>(gx, gy,
            lng + (size_t)(2 * l + 1) * DMODEL, lnb + (size_t)(2 * l + 1) * DMODEL,
            gx, xhi, xlo);
    }

    cudaEvent_t eJoin = EV();
    cudaEventRecord(eJoin, s2);
    cudaStreamWaitEvent(0, eJoin, 0);

    cudaMemcpyAsync(out, gx, (size_t)MROWS * DMODEL * sizeof(float),
                    cudaMemcpyDeviceToDevice);
#undef EV
}

// round 8
// speedup vs baseline: 3.3063x; 1.0140x over previous
#include <cuda_runtime.h>
#include <cuda_bf16.h>
#include <math.h>
#include <stdint.h>

// Problem constants
#define NLAYER 6
#define NHEAD  16
#define DMODEL 1024
#define DHEAD  64
#define DFF    4096
#define BATCH  4
#define SEQ    1024
#define MROWS  (BATCH*SEQ)
#define NEG_INF_F (-100000000.0f)

// ---------------------------------------------------------------------------
// Scratch (static device globals; no allocation anywhere)
// ---------------------------------------------------------------------------
__device__ float g_x[MROWS*DMODEL];
__device__ float g_y[MROWS*DMODEL];
__device__ __nv_bfloat16 g_xhi[MROWS*DMODEL], g_xlo[MROWS*DMODEL];
__device__ __nv_bfloat16 g_qhi[MROWS*DMODEL], g_qlo[MROWS*DMODEL];
__device__ __nv_bfloat16 g_khi[MROWS*DMODEL], g_klo[MROWS*DMODEL];
__device__ __nv_bfloat16 g_vhi[MROWS*DMODEL], g_vlo[MROWS*DMODEL];
__device__ __nv_bfloat16 g_ohi[MROWS*DMODEL], g_olo[MROWS*DMODEL];
__device__ __nv_bfloat16 g_hhi[MROWS*DFF],    g_hlo[MROWS*DFF];
__device__ __nv_bfloat16 g_wqkv_hi[3*DMODEL*DMODEL], g_wqkv_lo[3*DMODEL*DMODEL];
__device__ __nv_bfloat16 g_wo_hi[DMODEL*DMODEL],     g_wo_lo[DMODEL*DMODEL];
__device__ __nv_bfloat16 g_w1_hi[DMODEL*DFF],        g_w1_lo[DMODEL*DFF];
__device__ __nv_bfloat16 g_w2_hi[DFF*DMODEL],        g_w2_lo[DFF*DMODEL];

// ---------------------------------------------------------------------------
// PTX helpers
// ---------------------------------------------------------------------------
__device__ __forceinline__ uint32_t smem_u32(const void* p) {
    uint32_t a;
    asm("{ .reg .u64 t; cvta.to.shared.u64 t, %1; cvt.u32.u64 %0, t; }" : "=r"(a) : "l"(p));
    return a;
}
__device__ __forceinline__ void cp_async16(uint32_t dst, const void* src) {
    asm volatile("cp.async.cg.shared.global [%0], [%1], 16;" :: "r"(dst), "l"(src) : "memory");
}
#define CP_COMMIT() asm volatile("cp.async.commit_group;" ::: "memory")

__device__ __forceinline__ void ldsm_x4(uint32_t& r0, uint32_t& r1, uint32_t& r2,
                                        uint32_t& r3, uint32_t addr) {
    asm volatile("ldmatrix.sync.aligned.m8n8.x4.shared.b16 {%0,%1,%2,%3}, [%4];"
                 : "=r"(r0), "=r"(r1), "=r"(r2), "=r"(r3) : "r"(addr));
}
__device__ __forceinline__ void ldsm_x4_t(uint32_t& r0, uint32_t& r1, uint32_t& r2,
                                          uint32_t& r3, uint32_t addr) {
    asm volatile("ldmatrix.sync.aligned.m8n8.x4.trans.shared.b16 {%0,%1,%2,%3}, [%4];"
                 : "=r"(r0), "=r"(r1), "=r"(r2), "=r"(r3) : "r"(addr));
}
__device__ __forceinline__ void mma_bf16(float* c, const uint32_t* a, const uint32_t* b) {
    asm volatile(
        "mma.sync.aligned.m16n8k16.row.col.f32.bf16.bf16.f32 "
        "{%0,%1,%2,%3}, {%4,%5,%6,%7}, {%8,%9}, {%0,%1,%2,%3};"
        : "+f"(c[0]), "+f"(c[1]), "+f"(c[2]), "+f"(c[3])
        : "r"(a[0]), "r"(a[1]), "r"(a[2]), "r"(a[3]), "r"(b[0]), "r"(b[1]));
}
__device__ __forceinline__ void pack_split(float x, float y, uint32_t& hi, uint32_t& lo) {
    __nv_bfloat16 hx = __float2bfloat16(x), hy = __float2bfloat16(y);
    __nv_bfloat162 H; H.x = hx; H.y = hy;
    __nv_bfloat162 L;
    L.x = __float2bfloat16(x - __bfloat162float(hx));
    L.y = __float2bfloat16(y - __bfloat162float(hy));
    hi = *(uint32_t*)&H; lo = *(uint32_t*)&L;
}

// Swizzle for 64B-row tiles (GEMM: 32 bf16/row)
__device__ __forceinline__ uint32_t swz(int row, int c) {
    return (uint32_t)(((row >> 1) << 7) |
                      ((((((row & 1) << 2) | c)) ^ ((row >> 1) & 7)) << 4));
}
// Swizzle for 128B-row tiles (attention: 64 bf16/row)
__device__ __forceinline__ uint32_t swz128(int row, int c) {
    return (uint32_t)((row << 7) | (((c ^ (row & 7))) << 4));
}

// GEMM smem geometry: 128x128 tile, BK=32, TRIPLE buffered, 2 CTAs/SM
#define T_TILE 8192
#define STAGEB (4*T_TILE)
#define GSMEM  (3*STAGEB)            // 98304 (x2 CTAs = 192KB/SM)

// Attention smem: Q hi/lo (2x16KB) + K/V hi/lo double-buffered (2x32KB) + mask x2
#define AQ_TILE 16384                // 128 rows x 64 bf16
#define AKV_STAGE 32768              // Kh,Kl,Vh,Vl (8KB each)
#define ATTN_SMEM (2*AQ_TILE + 2*AKV_STAGE + 512)   // 98816 (x2 CTAs = ~193KB)

// ---------------------------------------------------------------------------
// Positional encoding (fp64) + fused bf16 split of the result
// ---------------------------------------------------------------------------
__global__ void posenc_kernel(const float* __restrict__ x, float* __restrict__ out,
                              __nv_bfloat16* __restrict__ ohi,
                              __nv_bfloat16* __restrict__ olo)
{
    int idx = blockIdx.x * blockDim.x + threadIdx.x;
    if (idx >= SEQ * DMODEL) return;
    int d = idx & (DMODEL - 1);
    int s = idx >> 10;
    int t = (d < DMODEL/2) ? d : d - DMODEL/2;
    const double log_inc = log(10000.0) / (double)(DMODEL/2 - 1);
    double arg = (double)s * exp(-(double)t * log_inc);
    float sig = (float)((d < DMODEL/2) ? sin(arg) : cos(arg));
#pragma unroll
    for (int b = 0; b < BATCH; ++b) {
        size_t off = (size_t)b * SEQ * DMODEL + idx;
        float v = x[off] + sig;
        out[off] = v;
        __nv_bfloat16 h = __float2bfloat16(v);
        ohi[off] = h;
        olo[off] = __float2bfloat16(v - __bfloat162float(h));
    }
}

// ---------------------------------------------------------------------------
// W [K,N] fp32 -> transposed bf16 split: hiT, loT [N,K]
// ---------------------------------------------------------------------------
__global__ __launch_bounds__(256) void split_wT_kernel(
    const float* __restrict__ W, __nv_bfloat16* __restrict__ hiT,
    __nv_bfloat16* __restrict__ loT, int K, int N)
{
    __shared__ float t[32][33];
    int nx = blockIdx.x * 32;
    int ky = blockIdx.y * 32;
    int tx = threadIdx.x, ty = threadIdx.y;   // (32, 8)
#pragma unroll
    for (int i = 0; i < 4; ++i)
        t[ty + 8*i][tx] = W[(size_t)(ky + ty + 8*i) * N + nx + tx];
    __syncthreads();
#pragma unroll
    for (int i = 0; i < 4; ++i) {
        float v = t[tx][ty + 8*i];
        __nv_bfloat16 h = __float2bfloat16(v);
        size_t o = (size_t)(nx + ty + 8*i) * K + ky + tx;
        hiT[o] = h;
        loT[o] = __float2bfloat16(v - __bfloat162float(h));
    }
}

// --- chunk loader: 4 tiles (Ahi,Alo,Bhi,Blo) x 512 16B chunks / 256 thr = 8 ---
#define LOAD_CHUNK(k0, buf)                                                     \
    {                                                                           \
        _Pragma("unroll")                                                       \
        for (int i = 0; i < 8; ++i) {                                           \
            int t = tid + i * 256;                                              \
            int tile = t >> 9;                                                  \
            int w = t & 511;                                                    \
            int row = w >> 2;                                                   \
            int c = w & 3;                                                      \
            const __nv_bfloat16* src =                                          \
                (tile == 0) ? Ahi : (tile == 1) ? Alo : (tile == 2) ? Bhi : Blo;\
            int gr = ((tile < 2) ? m0 : n0) + row;                              \
            cp_async16((buf) + (uint32_t)tile * T_TILE + swz(row, c),           \
                       src + (size_t)gr * K + (k0) + c * 8);                    \
        }                                                                       \
        CP_COMMIT();                                                            \
    }

// --- MMA body (3-pass, pass-major), 8 warps each 32x64 ---
#define MMA_BODY(buf)                                                            \
    {                                                                            \
        const uint32_t Ah = buf;                                                 \
        const uint32_t Al = buf + T_TILE;                                        \
        const uint32_t Bh = buf + 2 * T_TILE;                                    \
        const uint32_t Bl = buf + 3 * T_TILE;                                    \
        _Pragma("unroll")                                                        \
        for (int kk = 0; kk < 2; ++kk) {                                         \
            uint32_t ahi_f[2][4], alo_f[2][4];                                   \
            _Pragma("unroll")                                                    \
            for (int mi = 0; mi < 2; ++mi) {                                     \
                int r = a_r + mi * 16;                                           \
                uint32_t off = swz(r, kk * 2 + a_h);                             \
                ldsm_x4(ahi_f[mi][0], ahi_f[mi][1], ahi_f[mi][2], ahi_f[mi][3], Ah + off); \
                ldsm_x4(alo_f[mi][0], alo_f[mi][1], alo_f[mi][2], alo_f[mi][3], Al + off); \
            }                                                                    \
            uint32_t bf[8][2];                                                   \
            _Pragma("unroll")                                                    \
            for (int nt = 0; nt < 4; ++nt) {                                     \
                int r = b_r + nt * 16;                                           \
                uint32_t off = swz(r, kk * 2 + b_h);                             \
                uint32_t q0, q1, q2, q3;                                         \
                ldsm_x4(q0, q1, q2, q3, Bh + off);                               \
                bf[nt*2][0] = q0; bf[nt*2][1] = q1;                              \
                bf[nt*2+1][0] = q2; bf[nt*2+1][1] = q3;                          \
            }                                                                    \
            _Pragma("unroll")                                                    \
            for (int mi = 0; mi < 2; ++mi)                                       \
                _Pragma("unroll")                                                \
                for (int ni = 0; ni < 8; ++ni)                                   \
                    mma_bf16(acc[mi][ni], ahi_f[mi], bf[ni]);                    \
            _Pragma("unroll")                                                    \
            for (int mi = 0; mi < 2; ++mi)                                       \
                _Pragma("unroll")                                                \
                for (int ni = 0; ni < 8; ++ni)                                   \
                    mma_bf16(acc[mi][ni], alo_f[mi], bf[ni]);                    \
            _Pragma("unroll")                                                    \
            for (int nt = 0; nt < 4; ++nt) {                                     \
                int r = b_r + nt * 16;                                           \
                uint32_t off = swz(r, kk * 2 + b_h);                             \
                uint32_t q0, q1, q2, q3;                                         \
                ldsm_x4(q0, q1, q2, q3, Bl + off);                               \
                bf[nt*2][0] = q0; bf[nt*2][1] = q1;                              \
                bf[nt*2+1][0] = q2; bf[nt*2+1][1] = q3;                          \
            }                                                                    \
            _Pragma("unroll")                                                    \
            for (int mi = 0; mi < 2; ++mi)                                       \
                _Pragma("unroll")                                                \
                for (int ni = 0; ni < 8; ++ni)                                   \
                    mma_bf16(acc[mi][ni], ahi_f[mi], bf[ni]);                    \
        }                                                                        \
    }

// --- 3-stage K-loop ---
#define K_LOOP()                                                                 \
    LOAD_CHUNK(0, sb);                                                           \
    LOAD_CHUNK(32, sb + STAGEB);                                                 \
    for (int ch = 0; ch < nch; ++ch) {                                           \
        const uint32_t buf = sb + (uint32_t)(ch % 3) * STAGEB;                   \
        if (ch + 2 < nch) {                                                      \
            LOAD_CHUNK((ch + 2) * 32, sb + (uint32_t)((ch + 2) % 3) * STAGEB);   \
            asm volatile("cp.async.wait_group 2;" ::: "memory");                 \
        } else if (ch + 1 < nch) {                                               \
            asm volatile("cp.async.wait_group 1;" ::: "memory");                 \
        } else {                                                                 \
            asm volatile("cp.async.wait_group 0;" ::: "memory");                 \
        }                                                                        \
        __syncthreads();                                                         \
        MMA_BODY(buf)                                                            \
        __syncthreads();                                                         \
    }

// ---------------------------------------------------------------------------
// General HMMA bf16-split GEMM (Wo / FF1 / FF2): 128x128 tile, 256 thr, 2 CTA/SM
// ---------------------------------------------------------------------------
__global__ __launch_bounds__(256, 2) void mma_gemm_kernel(
    const __nv_bfloat16* __restrict__ Ahi, const __nv_bfloat16* __restrict__ Alo,
    const __nv_bfloat16* __restrict__ Bhi, const __nv_bfloat16* __restrict__ Blo,
    const float* __restrict__ bias, float* __restrict__ C,
    __nv_bfloat16* __restrict__ Chi, __nv_bfloat16* __restrict__ Clo,
    int M, int N, int K, float alpha, int relu, int outmode)
{
    extern __shared__ char smem[];
    const uint32_t sb = smem_u32(smem);
    const int tid = threadIdx.x;
    const int wid = tid >> 5, lane = tid & 31;
    const int m0 = blockIdx.y * 128, n0 = blockIdx.x * 128;
    const int wm = (wid & 3) * 32;
    const int wn = (wid >> 2) * 64;

    float acc[2][8][4];
#pragma unroll
    for (int mi = 0; mi < 2; ++mi)
#pragma unroll
        for (int ni = 0; ni < 8; ++ni)
#pragma unroll
            for (int r = 0; r < 4; ++r) acc[mi][ni][r] = 0.0f;

    const int nch = K >> 5;
    const int a_r = wm + (lane & 15);
    const int a_h = lane >> 4;
    const int b_r = wn + ((lane >> 4) << 3) + (lane & 7);
    const int b_h = (lane >> 3) & 1;

    K_LOOP()

    const int grp = lane >> 2, qid = lane & 3;
#pragma unroll
    for (int mi = 0; mi < 2; ++mi) {
        const int row0 = m0 + wm + mi * 16 + grp;
#pragma unroll
        for (int ni = 0; ni < 8; ++ni) {
            const int col = n0 + wn + ni * 8 + qid * 2;
            float2 b2 = *(const float2*)(bias + col);
            float2 u, v;
            u.x = (acc[mi][ni][0] + b2.x) * alpha;
            u.y = (acc[mi][ni][1] + b2.y) * alpha;
            v.x = (acc[mi][ni][2] + b2.x) * alpha;
            v.y = (acc[mi][ni][3] + b2.y) * alpha;
            if (relu) {
                u.x = fmaxf(u.x, 0.f); u.y = fmaxf(u.y, 0.f);
                v.x = fmaxf(v.x, 0.f); v.y = fmaxf(v.y, 0.f);
            }
            if (outmode == 0) {
                *(float2*)(C + (size_t)row0 * N + col) = u;
                *(float2*)(C + (size_t)(row0 + 8) * N + col) = v;
            } else {
                uint32_t hi, lo;
                pack_split(u.x, u.y, hi, lo);
                *(uint32_t*)(Chi + (size_t)row0 * N + col) = hi;
                *(uint32_t*)(Clo + (size_t)row0 * N + col) = lo;
                pack_split(v.x, v.y, hi, lo);
                *(uint32_t*)(Chi + (size_t)(row0 + 8) * N + col) = hi;
                *(uint32_t*)(Clo + (size_t)(row0 + 8) * N + col) = lo;
            }
        }
    }
}

// ---------------------------------------------------------------------------
// Batched QKV GEMM: B packed [3072, 1024]. grid (24, 32). mid = n0>>10.
// ---------------------------------------------------------------------------
__global__ __launch_bounds__(256, 2) void mma_gemm_qkv_kernel(
    const __nv_bfloat16* __restrict__ Ahi, const __nv_bfloat16* __restrict__ Alo,
    const __nv_bfloat16* __restrict__ Bhi, const __nv_bfloat16* __restrict__ Blo,
    const float* __restrict__ bq, const float* __restrict__ bk,
    const float* __restrict__ bv,
    __nv_bfloat16* __restrict__ Qhi, __nv_bfloat16* __restrict__ Qlo,
    __nv_bfloat16* __restrict__ Khi, __nv_bfloat16* __restrict__ Klo,
    __nv_bfloat16* __restrict__ Vhi, __nv_bfloat16* __restrict__ Vlo,
    float qscale)
{
    extern __shared__ char smem[];
    const uint32_t sb = smem_u32(smem);
    const int tid = threadIdx.x;
    const int wid = tid >> 5, lane = tid & 31;
    const int m0 = blockIdx.y * 128, n0 = blockIdx.x * 128;
    const int K = DMODEL;
    const int wm = (wid & 3) * 32;
    const int wn = (wid >> 2) * 64;

    float acc[2][8][4];
#pragma unroll
    for (int mi = 0; mi < 2; ++mi)
#pragma unroll
        for (int ni = 0; ni < 8; ++ni)
#pragma unroll
            for (int r = 0; r < 4; ++r) acc[mi][ni][r] = 0.0f;

    const int nch = K >> 5;
    const int a_r = wm + (lane & 15);
    const int a_h = lane >> 4;
    const int b_r = wn + ((lane >> 4) << 3) + (lane & 7);
    const int b_h = (lane >> 3) & 1;

    K_LOOP()

    const int mid = n0 >> 10;
    const float* bsel = (mid == 0) ? bq : (mid == 1) ? bk : bv;
    __nv_bfloat16* hisel = (mid == 0) ? Qhi : (mid == 1) ? Khi : Vhi;
    __nv_bfloat16* losel = (mid == 0) ? Qlo : (mid == 1) ? Klo : Vlo;
    const float asel = (mid == 0) ? qscale : 1.0f;
    const int cb = mid << 10;

    const int grp = lane >> 2, qid = lane & 3;
#pragma unroll
    for (int mi = 0; mi < 2; ++mi) {
        const int row0 = m0 + wm + mi * 16 + grp;
#pragma unroll
        for (int ni = 0; ni < 8; ++ni) {
            const int col = n0 + wn + ni * 8 + qid * 2 - cb;
            float2 b2 = *(const float2*)(bsel + col);
            float2 u, v;
            u.x = (acc[mi][ni][0] + b2.x) * asel;
            u.y = (acc[mi][ni][1] + b2.y) * asel;
            v.x = (acc[mi][ni][2] + b2.x) * asel;
            v.y = (acc[mi][ni][3] + b2.y) * asel;
            uint32_t hi, lo;
            pack_split(u.x, u.y, hi, lo);
            *(uint32_t*)(hisel + (size_t)row0 * DMODEL + col) = hi;
            *(uint32_t*)(losel + (size_t)row0 * DMODEL + col) = lo;
            pack_split(v.x, v.y, hi, lo);
            *(uint32_t*)(hisel + (size_t)(row0 + 8) * DMODEL + col) = hi;
            *(uint32_t*)(losel + (size_t)(row0 + 8) * DMODEL + col) = lo;
        }
    }
}

// ---------------------------------------------------------------------------
// MMA flash attention: 8 warps, 128 q-rows per CTA, double-buffered K/V.
// grid (SEQ/128, NHEAD, BATCH) = (8, 16, 4). 2 CTAs/SM.
// ---------------------------------------------------------------------------
__global__ __launch_bounds__(256, 2) void attn_mma_kernel(
    const __nv_bfloat16* __restrict__ Qhi, const __nv_bfloat16* __restrict__ Qlo,
    const __nv_bfloat16* __restrict__ Khi, const __nv_bfloat16* __restrict__ Klo,
    const __nv_bfloat16* __restrict__ Vhi, const __nv_bfloat16* __restrict__ Vlo,
    const float* __restrict__ mask,
    __nv_bfloat16* __restrict__ Ohi, __nv_bfloat16* __restrict__ Olo)
{
    extern __shared__ char sm[];
    const uint32_t sb = smem_u32(sm);
    const uint32_t Qh = sb, Ql = sb + AQ_TILE;
    const uint32_t KV0 = sb + 2 * AQ_TILE;          // stage base; Kh,Kl,Vh,Vl @ +0,8K,16K,24K
    float* msk = (float*)(sm + 2 * AQ_TILE + 2 * AKV_STAGE);  // [2][64]

    const int tid = threadIdx.x, wid = tid >> 5, lane = tid & 31;
    const int b = blockIdx.z, h = blockIdx.y, q0 = blockIdx.x * 128;
    const int g = lane >> 2, qd = lane & 3;

    // Load Q hi/lo tiles: 2 x 1024 chunks / 256 threads = 8 each
#pragma unroll
    for (int i = 0; i < 8; ++i) {
        int t = tid + i * 256;
        int tt = t >> 10;
        int w = t & 1023;
        int r = w >> 3, c = w & 7;
        const __nv_bfloat16* src = (tt ? Qlo : Qhi)
            + (size_t)(b * SEQ + q0 + r) * DMODEL + h * DHEAD + c * 8;
        cp_async16((tt ? Ql : Qh) + swz128(r, c), src);
    }
    CP_COMMIT();   // group: Q

    float m_i[2] = {-INFINITY, -INFINITY}, l_i[2] = {0.f, 0.f};
    float oacc[8][4];
#pragma unroll
    for (int ni = 0; ni < 8; ++ni)
#pragma unroll
        for (int r = 0; r < 4; ++r) oacc[ni][r] = 0.f;

    const int a_r = wid * 16 + (lane & 15);
    const int a_c = lane >> 4;
    const int b_r = (lane & 7) + ((lane >> 4) << 3);
    const int b_c = (lane >> 3) & 1;
    const int v_ro = ((lane >> 3) & 1) * 8 + (lane & 7);
    const int v_co = lane >> 4;

    // K/V stage loader: 4 tiles x 512 chunks / 256 threads = 8 each
#define LOAD_KV(kt, stg)                                                        \
    {                                                                           \
        const uint32_t sbase = KV0 + (uint32_t)(stg) * AKV_STAGE;               \
        _Pragma("unroll")                                                       \
        for (int i = 0; i < 8; ++i) {                                           \
            int t = tid + i * 256;                                              \
            int tt = t >> 9;                                                    \
            int w = t & 511;                                                    \
            int r = w >> 3, c = w & 7;                                          \
            const __nv_bfloat16* src =                                          \
                ((tt == 0) ? Khi : (tt == 1) ? Klo : (tt == 2) ? Vhi : Vlo)     \
                + (size_t)(b * SEQ + (kt) + r) * DMODEL + h * DHEAD + c * 8;    \
            cp_async16(sbase + (uint32_t)tt * 8192 + swz128(r, c), src);        \
        }                                                                       \
        if (tid < 64)                                                           \
            msk[(stg) * 64 + tid] =                                             \
                (1.0f - mask[b * SEQ + (kt) + tid]) * NEG_INF_F;                \
        CP_COMMIT();                                                            \
    }

    LOAD_KV(0, 0);

    for (int kt = 0; kt < SEQ; kt += 64) {
        const int stg = (kt >> 6) & 1;
        const uint32_t Kh = KV0 + (uint32_t)stg * AKV_STAGE;
        const uint32_t Kl = Kh + 8192;
        const uint32_t Vh = Kh + 16384;
        const uint32_t Vl = Kh + 24576;
        const float* mrow = msk + stg * 64;

        if (kt + 64 < SEQ) {
            LOAD_KV(kt + 64, stg ^ 1);
            asm volatile("cp.async.wait_group 1;" ::: "memory");
        } else {
            asm volatile("cp.async.wait_group 0;" ::: "memory");
        }
        __syncthreads();   // current stage (and Q on first iter) ready

        // ---- S = Q K^T (3-pass) ----
        float sacc[8][4];
#pragma unroll
        for (int ni = 0; ni < 8; ++ni)
#pragma unroll
            for (int r = 0; r < 4; ++r) sacc[ni][r] = 0.f;

#pragma unroll
        for (int kk = 0; kk < 4; ++kk) {
            uint32_t qh[4], ql[4];
            uint32_t offA = swz128(a_r, kk * 2 + a_c);
            ldsm_x4(qh[0], qh[1], qh[2], qh[3], Qh + offA);
            ldsm_x4(ql[0], ql[1], ql[2], ql[3], Ql + offA);
            uint32_t bh[8][2], bl[8][2];
#pragma unroll
            for (int nt = 0; nt < 4; ++nt) {
                uint32_t off = swz128(b_r + nt * 16, kk * 2 + b_c);
                uint32_t r0, r1, r2, r3;
                ldsm_x4(r0, r1, r2, r3, Kh + off);
                bh[nt*2][0] = r0; bh[nt*2][1] = r1;
                bh[nt*2+1][0] = r2; bh[nt*2+1][1] = r3;
                ldsm_x4(r0, r1, r2, r3, Kl + off);
                bl[nt*2][0] = r0; bl[nt*2][1] = r1;
                bl[nt*2+1][0] = r2; bl[nt*2+1][1] = r3;
            }
#pragma unroll
            for (int ni = 0; ni < 8; ++ni) mma_bf16(sacc[ni], qh, bh[ni]);
#pragma unroll
            for (int ni = 0; ni < 8; ++ni) mma_bf16(sacc[ni], qh, bl[ni]);
#pragma unroll
            for (int ni = 0; ni < 8; ++ni) mma_bf16(sacc[ni], ql, bh[ni]);
        }

        // additive mask
#pragma unroll
        for (int ni = 0; ni < 8; ++ni) {
            float ma = mrow[ni * 8 + qd * 2], mb = mrow[ni * 8 + qd * 2 + 1];
            sacc[ni][0] += ma; sacc[ni][1] += mb;
            sacc[ni][2] += ma; sacc[ni][3] += mb;
        }

        // ---- streaming softmax ----
#pragma unroll
        for (int hf = 0; hf < 2; ++hf) {
            float mx = -INFINITY;
#pragma unroll
            for (int ni = 0; ni < 8; ++ni)
                mx = fmaxf(mx, fmaxf(sacc[ni][hf*2], sacc[ni][hf*2+1]));
            mx = fmaxf(mx, __shfl_xor_sync(0xffffffffu, mx, 1));
            mx = fmaxf(mx, __shfl_xor_sync(0xffffffffu, mx, 2));
            float mnew = fmaxf(m_i[hf], mx);
            float rs = 0.f;
#pragma unroll
            for (int ni = 0; ni < 8; ++ni) {
                float e0 = __expf(sacc[ni][hf*2]   - mnew);
                float e1 = __expf(sacc[ni][hf*2+1] - mnew);
                sacc[ni][hf*2] = e0; sacc[ni][hf*2+1] = e1;
                rs += e0 + e1;
            }
            rs += __shfl_xor_sync(0xffffffffu, rs, 1);
            rs += __shfl_xor_sync(0xffffffffu, rs, 2);
            float sc = __expf(m_i[hf] - mnew);
            l_i[hf] = l_i[hf] * sc + rs;
            m_i[hf] = mnew;
#pragma unroll
            for (int ni = 0; ni < 8; ++ni) {
                oacc[ni][hf*2]   *= sc;
                oacc[ni][hf*2+1] *= sc;
            }
        }

        // ---- O += P V (3-pass) ----
#pragma unroll
        for (int kk = 0; kk < 4; ++kk) {
            uint32_t ph[4], pl[4];
            pack_split(sacc[2*kk][0],   sacc[2*kk][1],   ph[0], pl[0]);
            pack_split(sacc[2*kk][2],   sacc[2*kk][3],   ph[1], pl[1]);
            pack_split(sacc[2*kk+1][0], sacc[2*kk+1][1], ph[2], pl[2]);
            pack_split(sacc[2*kk+1][2], sacc[2*kk+1][3], ph[3], pl[3]);
            uint32_t vh[8][2], vl[8][2];
#pragma unroll
            for (int nt = 0; nt < 4; ++nt) {
                uint32_t off = swz128(kk * 16 + v_ro, nt * 2 + v_co);
                uint32_t r0, r1, r2, r3;
                ldsm_x4_t(r0, r1, r2, r3, Vh + off);
                vh[nt*2][0] = r0; vh[nt*2][1] = r1;
                vh[nt*2+1][0] = r2; vh[nt*2+1][1] = r3;
                ldsm_x4_t(r0, r1, r2, r3, Vl + off);
                vl[nt*2][0] = r0; vl[nt*2][1] = r1;
                vl[nt*2+1][0] = r2; vl[nt*2+1][1] = r3;
            }
#pragma unroll
            for (int ni = 0; ni < 8; ++ni) mma_bf16(oacc[ni], ph, vh[ni]);
#pragma unroll
            for (int ni = 0; ni < 8; ++ni) mma_bf16(oacc[ni], ph, vl[ni]);
#pragma unroll
            for (int ni = 0; ni < 8; ++ni) mma_bf16(oacc[ni], pl, vh[ni]);
        }
        __syncthreads();   // all warps done with this stage before it is re-filled
    }

    // ---- O /= l; write bf16 hi/lo ----
#pragma unroll
    for (int hf = 0; hf < 2; ++hf) {
        float inv = 1.0f / l_i[hf];
        int row = q0 + wid * 16 + g + hf * 8;
#pragma unroll
        for (int ni = 0; ni < 8; ++ni) {
            float x0 = oacc[ni][hf*2] * inv, x1 = oacc[ni][hf*2+1] * inv;
            uint32_t hi, lo;
            pack_split(x0, x1, hi, lo);
            size_t off = (size_t)(b * SEQ + row) * DMODEL + h * DHEAD + ni * 8 + qd * 2;
            *(uint32_t*)(Ohi + off) = hi;
            *(uint32_t*)(Olo + off) = lo;
        }
    }
#undef LOAD_KV
}

// ---------------------------------------------------------------------------
// Fused residual + LayerNorm; writes fp32 x and bf16 hi/lo split of x.
// ---------------------------------------------------------------------------
__global__ __launch_bounds__(256) void add_ln_kernel(
    const float* __restrict__ x, const float* __restrict__ y,
    const float* __restrict__ g, const float* __restrict__ beta,
    float* __restrict__ out,
    __nv_bfloat16* __restrict__ ohi, __nv_bfloat16* __restrict__ olo)
{
    __shared__ float red[8];
    __shared__ float sbroadcast;

    const int row = blockIdx.x;
    const int tid = threadIdx.x;
    const int lane = tid & 31, wid = tid >> 5;
    const size_t base = (size_t)row * DMODEL + tid * 4;

    float4 xv = *(const float4*)(x + base);
    float4 yv = *(const float4*)(y + base);
    float4 v;
    v.x = xv.x + yv.x; v.y = xv.y + yv.y; v.z = xv.z + yv.z; v.w = xv.w + yv.w;

    float s = v.x + v.y + v.z + v.w;
#pragma unroll
    for (int o = 16; o > 0; o >>= 1) s += __shfl_xor_sync(0xffffffffu, s, o);
    if (lane == 0) red[wid] = s;
    __syncthreads();
    if (tid == 0) {
        float t = 0.0f;
#pragma unroll
        for (int w = 0; w < 8; ++w) t += red[w];
        sbroadcast = t * (1.0f / DMODEL);
    }
    __syncthreads();
    const float mean = sbroadcast;

    float dx0 = v.x - mean, dx1 = v.y - mean, dx2 = v.z - mean, dx3 = v.w - mean;
    float s2 = dx0 * dx0 + dx1 * dx1 + dx2 * dx2 + dx3 * dx3;
#pragma unroll
    for (int o = 16; o > 0; o >>= 1) s2 += __shfl_xor_sync(0xffffffffu, s2, o);
    __syncthreads();
    if (lane == 0) red[wid] = s2;
    __syncthreads();
    if (tid == 0) {
        float t = 0.0f;
#pragma unroll
        for (int w = 0; w < 8; ++w) t += red[w];
        sbroadcast = t * (1.0f / DMODEL);
    }
    __syncthreads();
    const float rstd = rsqrtf(sbroadcast + 1e-5f);

    float4 gv = *(const float4*)(g + tid * 4);
    float4 bv = *(const float4*)(beta + tid * 4);
    float4 o4;
    o4.x = dx0 * rstd * gv.x + bv.x;
    o4.y = dx1 * rstd * gv.y + bv.y;
    o4.z = dx2 * rstd * gv.z + bv.z;
    o4.w = dx3 * rstd * gv.w + bv.w;
    *(float4*)(out + base) = o4;

    uint32_t h0, l0, h1, l1;
    pack_split(o4.x, o4.y, h0, l0);
    pack_split(o4.z, o4.w, h1, l1);
    *(uint32_t*)(ohi + base)     = h0;
    *(uint32_t*)(ohi + base + 2) = h1;
    *(uint32_t*)(olo + base)     = l0;
    *(uint32_t*)(olo + base + 2) = l1;
}

// ---------------------------------------------------------------------------
// Launch (dual-stream: main = stream 0, s2 = weight splits)
// ---------------------------------------------------------------------------
extern "C" void kernel_launch(void* const* d_in, const int* in_sizes, int n_in,
                              void* d_out, int out_size)
{
    (void)in_sizes; (void)n_in; (void)out_size;

    const float* x    = (const float*)d_in[0];
    const float* mask = (const float*)d_in[1];
    const float* Wq   = (const float*)d_in[2];
    const float* bq   = (const float*)d_in[3];
    const float* Wk   = (const float*)d_in[4];
    const float* bk   = (const float*)d_in[5];
    const float* Wv   = (const float*)d_in[6];
    const float* bv   = (const float*)d_in[7];
    const float* Wo   = (const float*)d_in[8];
    const float* bo   = (const float*)d_in[9];
    const float* W1   = (const float*)d_in[10];
    const float* b1   = (const float*)d_in[11];
    const float* W2   = (const float*)d_in[12];
    const float* b2   = (const float*)d_in[13];
    const float* lng  = (const float*)d_in[14];
    const float* lnb  = (const float*)d_in[15];
    float* out = (float*)d_out;

    float *gx, *gy;
    __nv_bfloat16 *xhi, *xlo, *qhi, *qlo, *khi, *klo, *vhi, *vlo,
                  *ohi, *olo, *hhi, *hlo;
    __nv_bfloat16 *wqkvh, *wqkvl, *woh, *wol, *w1h, *w1l, *w2h, *w2l;
    cudaGetSymbolAddress((void**)&gx,  g_x);
    cudaGetSymbolAddress((void**)&gy,  g_y);
    cudaGetSymbolAddress((void**)&xhi, g_xhi);
    cudaGetSymbolAddress((void**)&xlo, g_xlo);
    cudaGetSymbolAddress((void**)&qhi, g_qhi);
    cudaGetSymbolAddress((void**)&qlo, g_qlo);
    cudaGetSymbolAddress((void**)&khi, g_khi);
    cudaGetSymbolAddress((void**)&klo, g_klo);
    cudaGetSymbolAddress((void**)&vhi, g_vhi);
    cudaGetSymbolAddress((void**)&vlo, g_vlo);
    cudaGetSymbolAddress((void**)&ohi, g_ohi);
    cudaGetSymbolAddress((void**)&olo, g_olo);
    cudaGetSymbolAddress((void**)&hhi, g_hhi);
    cudaGetSymbolAddress((void**)&hlo, g_hlo);
    cudaGetSymbolAddress((void**)&wqkvh, g_wqkv_hi);
    cudaGetSymbolAddress((void**)&wqkvl, g_wqkv_lo);
    cudaGetSymbolAddress((void**)&woh, g_wo_hi);
    cudaGetSymbolAddress((void**)&wol, g_wo_lo);
    cudaGetSymbolAddress((void**)&w1h, g_w1_hi);
    cudaGetSymbolAddress((void**)&w1l, g_w1_lo);
    cudaGetSymbolAddress((void**)&w2h, g_w2_hi);
    cudaGetSymbolAddress((void**)&w2l, g_w2_lo);

    static cudaStream_t s2 = nullptr;
    static cudaEvent_t evpool[64];
    static int attr_set = 0;
    if (!attr_set) {
        cudaFuncSetAttribute(mma_gemm_kernel,
                             cudaFuncAttributeMaxDynamicSharedMemorySize, GSMEM);
        cudaFuncSetAttribute(mma_gemm_qkv_kernel,
                             cudaFuncAttributeMaxDynamicSharedMemorySize, GSMEM);
        cudaFuncSetAttribute(attn_mma_kernel,
                             cudaFuncAttributeMaxDynamicSharedMemorySize, ATTN_SMEM);
        cudaStreamCreateWithFlags(&s2, cudaStreamNonBlocking);
        for (int i = 0; i < 64; ++i)
            cudaEventCreateWithFlags(&evpool[i], cudaEventDisableTiming);
        attr_set = 1;
    }
    int evn = 0;
#define EV() (evpool[evn++])

    const float qscale = 0.125f;
    dim3 gQKV(3 * DMODEL / 128, MROWS / 128);  // (24, 32)
    dim3 gProj(DMODEL / 128, MROWS / 128);     // (8, 32)
    dim3 gFF1(DFF / 128, MROWS / 128);         // (32, 32)
    dim3 gAttn(SEQ / 128, NHEAD, BATCH);       // (8, 16, 4)
    dim3 tT(32, 8);

    cudaEvent_t eFork = EV();
    cudaEventRecord(eFork, 0);
    cudaStreamWaitEvent(s2, eFork, 0);

    posenc_kernel<<<(SEQ * DMODEL + 255) / 256, 256>>>(x, gx, xhi, xlo);

    cudaEvent_t e_qkv_done = nullptr, e_wo_done = nullptr,
                e_ff1_done = nullptr, e_ff2_done = nullptr;

    for (int l = 0; l < NLAYER; ++l) {
        const float* wq = Wq + (size_t)l * DMODEL * DMODEL;
        const float* wk = Wk + (size_t)l * DMODEL * DMODEL;
        const float* wv = Wv + (size_t)l * DMODEL * DMODEL;
        const float* wo = Wo + (size_t)l * DMODEL * DMODEL;

        if (e_qkv_done) cudaStreamWaitEvent(s2, e_qkv_done, 0);
        split_wT_kernel<<<dim3(32,32), tT, 0, s2>>>(wq, wqkvh,               wqkvl,               DMODEL, DMODEL);
        split_wT_kernel<<<dim3(32,32), tT, 0, s2>>>(wk, wqkvh + 1024*1024,   wqkvl + 1024*1024,   DMODEL, DMODEL);
        split_wT_kernel<<<dim3(32,32), tT, 0, s2>>>(wv, wqkvh + 2*1024*1024, wqkvl + 2*1024*1024, DMODEL, DMODEL);
        cudaEvent_t e_sqkv = EV(); cudaEventRecord(e_sqkv, s2);

        if (e_wo_done) cudaStreamWaitEvent(s2, e_wo_done, 0);
        split_wT_kernel<<<dim3(32,32), tT, 0, s2>>>(wo, woh, wol, DMODEL, DMODEL);
        cudaEvent_t e_so = EV(); cudaEventRecord(e_so, s2);

        if (e_ff1_done) cudaStreamWaitEvent(s2, e_ff1_done, 0);
        split_wT_kernel<<<dim3(DFF/32, DMODEL/32), tT, 0, s2>>>(
            W1 + (size_t)l * DMODEL * DFF, w1h, w1l, DMODEL, DFF);
        cudaEvent_t e_s1 = EV(); cudaEventRecord(e_s1, s2);

        if (e_ff2_done) cudaStreamWaitEvent(s2, e_ff2_done, 0);
        split_wT_kernel<<<dim3(DMODEL/32, DFF/32), tT, 0, s2>>>(
            W2 + (size_t)l * DFF * DMODEL, w2h, w2l, DFF, DMODEL);
        cudaEvent_t e_s2e = EV(); cudaEventRecord(e_s2e, s2);

        cudaStreamWaitEvent(0, e_sqkv, 0);
        mma_gemm_qkv_kernel<<<gQKV, 256, GSMEM>>>(xhi, xlo, wqkvh, wqkvl,
            bq + (size_t)l * DMODEL, bk + (size_t)l * DMODEL, bv + (size_t)l * DMODEL,
            qhi, qlo, khi, klo, vhi, vlo, qscale);
        e_qkv_done = EV(); cudaEventRecord(e_qkv_done, 0);

        attn_mma_kernel<<<gAttn, 256, ATTN_SMEM>>>(qhi, qlo, khi, klo, vhi, vlo,
                                                   mask, ohi, olo);

        cudaStreamWaitEvent(0, e_so, 0);
        mma_gemm_kernel<<<gProj, 256, GSMEM>>>(ohi, olo, woh, wol,
            bo + (size_t)l * DMODEL, gy, nullptr, nullptr,
            MROWS, DMODEL, DMODEL, 1.0f, 0, 0);
        e_wo_done = EV(); cudaEventRecord(e_wo_done, 0);

        add_ln_kernel<<<MROWS, 256>>>(gx, gy,
            lng + (size_t)(2 * l) * DMODEL, lnb + (size_t)(2 * l) * DMODEL,
            gx, xhi, xlo);

        cudaStreamWaitEvent(0, e_s1, 0);
        mma_gemm_kernel<<<gFF1, 256, GSMEM>>>(xhi, xlo, w1h, w1l,
            b1 + (size_t)l * DFF, nullptr, hhi, hlo,
            MROWS, DFF, DMODEL, 1.0f, 1, 1);
        e_ff1_done = EV(); cudaEventRecord(e_ff1_done, 0);

        cudaStreamWaitEvent(0, e_s2e, 0);
        mma_gemm_kernel<<<gProj, 256, GSMEM>>>(hhi, hlo, w2h, w2l,
            b2 + (size_t)l * DMODEL, gy, nullptr, nullptr,
            MROWS, DMODEL, DFF, 1.0f, 0, 0);
        e_ff2_done = EV(); cudaEventRecord(e_ff2_done, 0);

        add_ln_kernel<<<MROWS, 256>>>(gx, gy,
            lng + (size_t)(2 * l + 1) * DMODEL, lnb + (size_t)(2 * l + 1) * DMODEL,
            gx, xhi, xlo);
    }

    cudaEvent_t eJoin = EV();
    cudaEventRecord(eJoin, s2);
    cudaStreamWaitEvent(0, eJoin, 0);

    cudaMemcpyAsync(out, gx, (size_t)MROWS * DMODEL * sizeof(float),
                    cudaMemcpyDeviceToDevice);
#undef EV
}